// round 6
// baseline (speedup 1.0000x reference)
#include <cuda_runtime.h>
#include <cuda_bf16.h>
#include <math.h>
#include <cstdint>

#define B_   2
#define S_   2048
#define H_   16
#define DK_  64
#define DM_  1024
#define M_   (B_ * S_)   // 4096

// ---------------------------------------------------------------------------
// PTX helpers — sm_80+ portable (harness PTX target is sm_103 WITHOUT 'a';
// tcgen05/TMEM unavailable; mma.sync/ldmatrix/cp.async are the path).
// ---------------------------------------------------------------------------
__device__ __forceinline__ uint32_t smem_u32(const void* p) {
    uint32_t a;
    asm("{ .reg .u64 t; cvta.to.shared.u64 t, %1; cvt.u32.u64 %0, t; }" : "=r"(a) : "l"(p));
    return a;
}
#define CP_ASYNC16(dst, src) \
    asm volatile("cp.async.cg.shared.global [%0], [%1], 16;" :: "r"(dst), "l"(src))
#define CP_COMMIT() asm volatile("cp.async.commit_group;" ::: "memory")
#define CP_WAIT(n)  asm volatile("cp.async.wait_group %0;" :: "n"(n) : "memory")

#define LDSM_X4(r0, r1, r2, r3, addr) \
    asm volatile("ldmatrix.sync.aligned.m8n8.x4.shared.b16 {%0,%1,%2,%3}, [%4];" \
                 : "=r"(r0), "=r"(r1), "=r"(r2), "=r"(r3) : "r"(addr))

#define MMA_BF16(c, a, b) \
    asm volatile("mma.sync.aligned.m16n8k16.row.col.f32.bf16.bf16.f32 " \
                 "{%0,%1,%2,%3}, {%4,%5,%6,%7}, {%8,%9}, {%0,%1,%2,%3};" \
                 : "+f"((c)[0]), "+f"((c)[1]), "+f"((c)[2]), "+f"((c)[3]) \
                 : "r"((a)[0]), "r"((a)[1]), "r"((a)[2]), "r"((a)[3]), \
                   "r"((b)[0]), "r"((b)[1]))

__device__ __forceinline__ uint32_t sw128(uint32_t off) { return off ^ ((off >> 3) & 0x70); }

// split (x, y) fp32 -> packed bf16x2 hi + lo (residual)
__device__ __forceinline__ void split2(float x, float y, uint32_t& hi, uint32_t& lo) {
    __nv_bfloat16 hx = __float2bfloat16(x), hy = __float2bfloat16(y);
    __nv_bfloat162 h2 = __halves2bfloat162(hx, hy);
    __nv_bfloat162 l2 = __halves2bfloat162(__float2bfloat16(x - __bfloat162float(hx)),
                                           __float2bfloat16(y - __bfloat162float(hy)));
    hi = *reinterpret_cast<uint32_t*>(&h2);
    lo = *reinterpret_cast<uint32_t*>(&l2);
}

// ---------------------------------------------------------------------------
// Scratch (device globals)
// ---------------------------------------------------------------------------
__device__ __nv_bfloat16 g_Ahi[3][(size_t)M_ * DM_];
__device__ __nv_bfloat16 g_Alo[3][(size_t)M_ * DM_];
__device__ __nv_bfloat16 g_Whi[4][(size_t)DM_ * DM_];   // W^T [N,K] K-contig
__device__ __nv_bfloat16 g_Wlo[4][(size_t)DM_ * DM_];
__device__ __nv_bfloat16 g_Qhi[B_ * H_ * S_ * DK_];     // [B,H,S,64]
__device__ __nv_bfloat16 g_Qlo[B_ * H_ * S_ * DK_];
__device__ __nv_bfloat16 g_Khi[B_ * H_ * S_ * DK_];
__device__ __nv_bfloat16 g_Klo[B_ * H_ * S_ * DK_];
__device__ __nv_bfloat16 g_Vhi[B_ * H_ * S_ * DK_];
__device__ __nv_bfloat16 g_Vlo[B_ * H_ * S_ * DK_];
__device__ __nv_bfloat16 g_Vthi[B_ * H_ * DK_ * S_];    // [B,H,64,S] (V^T)
__device__ __nv_bfloat16 g_Vtlo[B_ * H_ * DK_ * S_];

// ---------------------------------------------------------------------------
// fp32 -> (hi, lo) bf16 split for all 3 inputs in one launch
// ---------------------------------------------------------------------------
__global__ void __launch_bounds__(256) conv_inputs(const float4* __restrict__ s0,
                                                   const float4* __restrict__ s1,
                                                   const float4* __restrict__ s2)
{
    const int which = blockIdx.y;
    const float4* src = (which == 0) ? s0 : (which == 1) ? s1 : s2;
    uint32_t* hi = reinterpret_cast<uint32_t*>(g_Ahi[which]);
    uint32_t* lo = reinterpret_cast<uint32_t*>(g_Alo[which]);
    int i = blockIdx.x * 256 + threadIdx.x;
    float4 v = src[i];
    uint32_t h0, l0, h1, l1;
    split2(v.x, v.y, h0, l0);
    split2(v.z, v.w, h1, l1);
    hi[2 * i + 0] = h0;
    hi[2 * i + 1] = h1;
    lo[2 * i + 0] = l0;
    lo[2 * i + 1] = l1;
}

// ---------------------------------------------------------------------------
// All 4 weights: W [K,N] fp32 -> transposed split bf16 Wt[N,K]
// ---------------------------------------------------------------------------
__global__ void __launch_bounds__(256) conv_weights(const float* __restrict__ W0,
                                                    const float* __restrict__ W1,
                                                    const float* __restrict__ W2,
                                                    const float* __restrict__ W3)
{
    __shared__ float tile[32][33];
    const int which = blockIdx.z;
    const float* W = (which == 0) ? W0 : (which == 1) ? W1 : (which == 2) ? W2 : W3;
    __nv_bfloat16* hi = g_Whi[which];
    __nv_bfloat16* lo = g_Wlo[which];
    const int bx = blockIdx.x, by = blockIdx.y;
    const int tx = threadIdx.x, ty = threadIdx.y;     // 32 x 8
    #pragma unroll
    for (int j = 0; j < 32; j += 8)
        tile[ty + j][tx] = W[(size_t)(by * 32 + ty + j) * DM_ + bx * 32 + tx];
    __syncthreads();
    #pragma unroll
    for (int j = 0; j < 32; j += 8) {
        float v = tile[tx][ty + j];
        __nv_bfloat16 h = __float2bfloat16(v);
        size_t o = (size_t)(bx * 32 + ty + j) * DM_ + by * 32 + tx;
        hi[o] = h;
        lo[o] = __float2bfloat16(v - __bfloat162float(h));
    }
}

// ---------------------------------------------------------------------------
// V [B,H,S,64] hi/lo -> V^T [B,H,64,S] hi/lo
// ---------------------------------------------------------------------------
__global__ void __launch_bounds__(256) transpV()
{
    __shared__ __nv_bfloat16 th[64][65], tl[64][65];
    const int s0 = blockIdx.x * 64, bh = blockIdx.y;
    const int t = threadIdx.x;
    const __nv_bfloat16* sh_ = g_Vhi + (size_t)bh * S_ * DK_;
    const __nv_bfloat16* sl_ = g_Vlo + (size_t)bh * S_ * DK_;
    #pragma unroll
    for (int it = 0; it < 2; it++) {
        int r = (t >> 3) + it * 32, c = (t & 7) * 8;
        #pragma unroll
        for (int q = 0; q < 8; q++) {
            th[r][c + q] = sh_[(size_t)(s0 + r) * DK_ + c + q];
            tl[r][c + q] = sl_[(size_t)(s0 + r) * DK_ + c + q];
        }
    }
    __syncthreads();
    __nv_bfloat16* dh = g_Vthi + (size_t)bh * DK_ * S_;
    __nv_bfloat16* dl = g_Vtlo + (size_t)bh * DK_ * S_;
    #pragma unroll
    for (int it = 0; it < 2; it++) {
        int d = (t >> 3) + it * 32, sc = (t & 7) * 8;
        #pragma unroll
        for (int q = 0; q < 8; q++) {
            dh[(size_t)d * S_ + s0 + sc + q] = th[sc + q][d];
            dl[(size_t)d * S_ + s0 + sc + q] = tl[sc + q][d];
        }
    }
}

// ---------------------------------------------------------------------------
// HMMA GEMM: C[4096,1024] = A @ W + bias via 3 bf16 passes.
// CTA tile 128x256, 8 warps (4M x 2N), warp tile 32x128, BK=64, 2-stage.
// Stage = A(16KB) + B(32KB) = 48KB; 2 stages = 96KB; 1 CTA/SM; grid = 128.
// modes 0/1/2 -> head-split bf16 hi/lo into Q/K/V buffers; mode 3 -> fp32 Cext.
// ---------------------------------------------------------------------------
#define GM 128
#define GN 256
#define NCH 48
#define STAGE_BYTES 49152
#define GEMM_SMEM (2 * STAGE_BYTES)

__global__ void __launch_bounds__(256, 1) gemm_mma(const __nv_bfloat16* __restrict__ Ahi,
                                                   const __nv_bfloat16* __restrict__ Alo,
                                                   const __nv_bfloat16* __restrict__ Whi,
                                                   const __nv_bfloat16* __restrict__ Wlo,
                                                   const float* __restrict__ bias,
                                                   float* __restrict__ Cext, int mode)
{
    extern __shared__ __align__(1024) char smem[];
    const uint32_t sb = smem_u32(smem);
    const int t = threadIdx.x, lane = t & 31, wid = t >> 5;
    const int warpM = wid >> 1, warpN = wid & 1;
    const int row0 = blockIdx.y * GM, col0 = blockIdx.x * GN;

    float c[2][16][4] = {};

    // A: 128x64 -> 4 x 16B per thread; B: 256x64 -> 8 x 16B per thread
    int lr[4], lc[4];
    #pragma unroll
    for (int j = 0; j < 4; j++) {
        int g = t + j * 256;
        lr[j] = g >> 3;
        lc[j] = (g & 7) * 8;
    }

    auto issue = [&](int i) {
        const int seg = i >> 4, kc = (i & 15) * 64;
        const __nv_bfloat16* aseg = (seg == 1) ? Alo : Ahi;
        const __nv_bfloat16* wseg = (seg == 2) ? Wlo : Whi;
        const uint32_t ab = sb + (uint32_t)(i & 1) * STAGE_BYTES;
        const uint32_t bb = ab + 16384u;
        #pragma unroll
        for (int j = 0; j < 4; j++) {
            uint32_t so = sw128((uint32_t)(lr[j] * 128 + lc[j] * 2));
            CP_ASYNC16(ab + so, aseg + (size_t)(row0 + lr[j]) * DM_ + kc + lc[j]);
        }
        #pragma unroll
        for (int j = 0; j < 8; j++) {
            int g = t + j * 256, r = g >> 3, cidx = (g & 7) * 8;
            uint32_t so = sw128((uint32_t)(r * 128 + cidx * 2));
            CP_ASYNC16(bb + so, wseg + (size_t)(col0 + r) * DM_ + kc + cidx);
        }
    };

    issue(0);
    CP_COMMIT();

    for (int i = 0; i < NCH; i++) {
        if (i + 1 < NCH) { issue(i + 1); CP_COMMIT(); CP_WAIT(1); }
        else             { CP_WAIT(0); }
        __syncthreads();

        const uint32_t ab = sb + (uint32_t)(i & 1) * STAGE_BYTES;
        const uint32_t bb = ab + 16384u;

        #pragma unroll
        for (int kst = 0; kst < 4; kst++) {
            const int kk = kst * 16;
            uint32_t a[2][4], b[16][2];
            #pragma unroll
            for (int mt = 0; mt < 2; mt++) {
                int r = warpM * 32 + mt * 16 + (lane & 7) + ((lane >> 3) & 1) * 8;
                int kcol = kk + (lane >> 4) * 8;
                LDSM_X4(a[mt][0], a[mt][1], a[mt][2], a[mt][3],
                        ab + sw128((uint32_t)(r * 128 + kcol * 2)));
            }
            #pragma unroll
            for (int np = 0; np < 8; np++) {
                int r = warpN * 128 + np * 16 + (lane & 7) + (lane >> 4) * 8;
                int kcol = kk + ((lane >> 3) & 1) * 8;
                LDSM_X4(b[2 * np][0], b[2 * np][1], b[2 * np + 1][0], b[2 * np + 1][1],
                        bb + sw128((uint32_t)(r * 128 + kcol * 2)));
            }
            #pragma unroll
            for (int mt = 0; mt < 2; mt++)
                #pragma unroll
                for (int nt = 0; nt < 16; nt++)
                    MMA_BF16(c[mt][nt], a[mt], b[nt]);
        }
        __syncthreads();
    }

    __nv_bfloat16* Hb = (mode == 0) ? g_Qhi : (mode == 1) ? g_Khi : g_Vhi;
    __nv_bfloat16* Lb = (mode == 0) ? g_Qlo : (mode == 1) ? g_Klo : g_Vlo;
    #pragma unroll
    for (int mt = 0; mt < 2; mt++) {
        #pragma unroll
        for (int half = 0; half < 2; half++) {
            const int rowg = row0 + warpM * 32 + mt * 16 + (lane >> 2) + half * 8;
            const int bb_ = rowg >> 11, ss = rowg & (S_ - 1);
            #pragma unroll
            for (int nt = 0; nt < 16; nt++) {
                const int colg = col0 + warpN * 128 + nt * 8 + (lane & 3) * 2;
                const float v0 = c[mt][nt][half * 2 + 0] + bias[colg];
                const float v1 = c[mt][nt][half * 2 + 1] + bias[colg + 1];
                if (mode < 3) {
                    const int h = colg >> 6;
                    size_t off = ((size_t)((bb_ * H_ + h) * S_ + ss)) * DK_ + (colg & 63);
                    uint32_t hiw, low;
                    split2(v0, v1, hiw, low);
                    *reinterpret_cast<uint32_t*>(Hb + off) = hiw;
                    *reinterpret_cast<uint32_t*>(Lb + off) = low;
                } else {
                    *reinterpret_cast<float2*>(Cext + (size_t)rowg * DM_ + colg) =
                        make_float2(v0, v1);
                }
            }
        }
    }
}

// ---------------------------------------------------------------------------
// HMMA flash attention, causal, hi/lo split on QK^T and PV (unchanged R5).
// ---------------------------------------------------------------------------
#define ATT_SMEM 98304

__global__ void __launch_bounds__(256, 1) attn_mma()
{
    extern __shared__ __align__(1024) char smem[];
    const uint32_t sb = smem_u32(smem);
    const int t = threadIdx.x, lane = t & 31, w = t >> 5;
    const int qb = (int)gridDim.x - 1 - (int)blockIdx.x;   // heavy-first (LPT)
    const int bh = blockIdx.y;
    const int qs = qb * 128;
    const int ntiles = qb * 2 + 2;

    const size_t bo = (size_t)bh * S_ * DK_;
    const __nv_bfloat16* Qh = g_Qhi + bo;
    const __nv_bfloat16* Ql = g_Qlo + bo;
    const __nv_bfloat16* Kh = g_Khi + bo;
    const __nv_bfloat16* Kl = g_Klo + bo;
    const __nv_bfloat16* Vh = g_Vthi + (size_t)bh * DK_ * S_;
    const __nv_bfloat16* Vl = g_Vtlo + (size_t)bh * DK_ * S_;

    const uint32_t QH = sb, QL = sb + 16384;

    #pragma unroll
    for (int j = 0; j < 4; j++) {
        int g = t + j * 256, r = g >> 3, c = (g & 7) * 8;
        uint32_t so = sw128((uint32_t)(r * 128 + c * 2));
        CP_ASYNC16(QH + so, Qh + (size_t)(qs + r) * DK_ + c);
        CP_ASYNC16(QL + so, Ql + (size_t)(qs + r) * DK_ + c);
    }
    auto issueKV = [&](int i) {
        const int kt = i * 64;
        const uint32_t bB = sb + 32768u + (uint32_t)(i & 1) * 32768u;
        #pragma unroll
        for (int j = 0; j < 2; j++) {
            int g = t + j * 256, r = g >> 3, c = (g & 7) * 8;
            uint32_t so = sw128((uint32_t)(r * 128 + c * 2));
            CP_ASYNC16(bB + so,         Kh + (size_t)(kt + r) * DK_ + c);
            CP_ASYNC16(bB + 8192 + so,  Kl + (size_t)(kt + r) * DK_ + c);
            CP_ASYNC16(bB + 16384 + so, Vh + (size_t)r * S_ + kt + c);
            CP_ASYNC16(bB + 24576 + so, Vl + (size_t)r * S_ + kt + c);
        }
    };
    issueKV(0);
    CP_COMMIT();
    if (ntiles > 1) { issueKV(1); CP_COMMIT(); }

    uint32_t qhf[4][4], qlf[4][4];
    float o[8][4] = {};
    float mrow0 = -INFINITY, mrow1 = -INFINITY, lrow0 = 0.f, lrow1 = 0.f;

    for (int i = 0; i < ntiles; i++) {
        if (i + 1 < ntiles) CP_WAIT(1); else CP_WAIT(0);
        __syncthreads();

        if (i == 0) {
            #pragma unroll
            for (int kc = 0; kc < 4; kc++) {
                int r = w * 16 + (lane & 7) + ((lane >> 3) & 1) * 8;
                int kcol = kc * 16 + (lane >> 4) * 8;
                uint32_t so = sw128((uint32_t)(r * 128 + kcol * 2));
                LDSM_X4(qhf[kc][0], qhf[kc][1], qhf[kc][2], qhf[kc][3], QH + so);
                LDSM_X4(qlf[kc][0], qlf[kc][1], qlf[kc][2], qlf[kc][3], QL + so);
            }
        }

        const int kt = i * 64;
        const uint32_t bB = sb + 32768u + (uint32_t)(i & 1) * 32768u;

        float s[8][4] = {};
        #pragma unroll
        for (int kc = 0; kc < 4; kc++) {
            const int kk = kc * 16;
            uint32_t bf[8][2];
            #pragma unroll
            for (int np = 0; np < 4; np++) {
                int r = np * 16 + (lane & 7) + (lane >> 4) * 8;
                int kcol = kk + ((lane >> 3) & 1) * 8;
                LDSM_X4(bf[2 * np][0], bf[2 * np][1], bf[2 * np + 1][0], bf[2 * np + 1][1],
                        bB + sw128((uint32_t)(r * 128 + kcol * 2)));
            }
            #pragma unroll
            for (int j = 0; j < 8; j++) {
                MMA_BF16(s[j], qhf[kc], bf[j]);
                MMA_BF16(s[j], qlf[kc], bf[j]);
            }
            #pragma unroll
            for (int np = 0; np < 4; np++) {
                int r = np * 16 + (lane & 7) + (lane >> 4) * 8;
                int kcol = kk + ((lane >> 3) & 1) * 8;
                LDSM_X4(bf[2 * np][0], bf[2 * np][1], bf[2 * np + 1][0], bf[2 * np + 1][1],
                        bB + 8192 + sw128((uint32_t)(r * 128 + kcol * 2)));
            }
            #pragma unroll
            for (int j = 0; j < 8; j++)
                MMA_BF16(s[j], qhf[kc], bf[j]);
        }

        const int r0g = qs + w * 16 + (lane >> 2);
        const bool needmask = (kt + 63 > qs + w * 16);
        float mx0 = -INFINITY, mx1 = -INFINITY;
        #pragma unroll
        for (int j = 0; j < 8; j++) {
            const int cg = kt + j * 8 + (lane & 3) * 2;
            float v0 = s[j][0] * 0.125f, v1 = s[j][1] * 0.125f;
            float v2 = s[j][2] * 0.125f, v3 = s[j][3] * 0.125f;
            if (needmask) {
                if (cg     > r0g)     v0 = -INFINITY;
                if (cg + 1 > r0g)     v1 = -INFINITY;
                if (cg     > r0g + 8) v2 = -INFINITY;
                if (cg + 1 > r0g + 8) v3 = -INFINITY;
            }
            s[j][0] = v0; s[j][1] = v1; s[j][2] = v2; s[j][3] = v3;
            mx0 = fmaxf(mx0, fmaxf(v0, v1));
            mx1 = fmaxf(mx1, fmaxf(v2, v3));
        }
        mx0 = fmaxf(mx0, __shfl_xor_sync(0xffffffffu, mx0, 1));
        mx0 = fmaxf(mx0, __shfl_xor_sync(0xffffffffu, mx0, 2));
        mx1 = fmaxf(mx1, __shfl_xor_sync(0xffffffffu, mx1, 1));
        mx1 = fmaxf(mx1, __shfl_xor_sync(0xffffffffu, mx1, 2));
        const float mn0 = fmaxf(mrow0, mx0), mn1 = fmaxf(mrow1, mx1);
        const float al0 = __expf(mrow0 - mn0), al1 = __expf(mrow1 - mn1);
        float sum0 = 0.f, sum1 = 0.f;
        #pragma unroll
        for (int j = 0; j < 8; j++) {
            float p0 = __expf(s[j][0] - mn0); s[j][0] = p0; sum0 += p0;
            float p1 = __expf(s[j][1] - mn0); s[j][1] = p1; sum0 += p1;
            float p2 = __expf(s[j][2] - mn1); s[j][2] = p2; sum1 += p2;
            float p3 = __expf(s[j][3] - mn1); s[j][3] = p3; sum1 += p3;
        }
        sum0 += __shfl_xor_sync(0xffffffffu, sum0, 1);
        sum0 += __shfl_xor_sync(0xffffffffu, sum0, 2);
        sum1 += __shfl_xor_sync(0xffffffffu, sum1, 1);
        sum1 += __shfl_xor_sync(0xffffffffu, sum1, 2);
        lrow0 = lrow0 * al0 + sum0;
        lrow1 = lrow1 * al1 + sum1;
        mrow0 = mn0; mrow1 = mn1;
        #pragma unroll
        for (int j = 0; j < 8; j++) {
            o[j][0] *= al0; o[j][1] *= al0;
            o[j][2] *= al1; o[j][3] *= al1;
        }

        uint32_t phi[4][4], plo[4][4];
        #pragma unroll
        for (int kc = 0; kc < 4; kc++) {
            split2(s[2 * kc][0],     s[2 * kc][1],     phi[kc][0], plo[kc][0]);
            split2(s[2 * kc][2],     s[2 * kc][3],     phi[kc][1], plo[kc][1]);
            split2(s[2 * kc + 1][0], s[2 * kc + 1][1], phi[kc][2], plo[kc][2]);
            split2(s[2 * kc + 1][2], s[2 * kc + 1][3], phi[kc][3], plo[kc][3]);
        }

        #pragma unroll
        for (int kc = 0; kc < 4; kc++) {
            const int kk = kc * 16;
            uint32_t bf[8][2];
            #pragma unroll
            for (int np = 0; np < 4; np++) {
                int r = np * 16 + (lane & 7) + (lane >> 4) * 8;
                int kcol = kk + ((lane >> 3) & 1) * 8;
                LDSM_X4(bf[2 * np][0], bf[2 * np][1], bf[2 * np + 1][0], bf[2 * np + 1][1],
                        bB + 16384 + sw128((uint32_t)(r * 128 + kcol * 2)));
            }
            #pragma unroll
            for (int j = 0; j < 8; j++) {
                MMA_BF16(o[j], phi[kc], bf[j]);
                MMA_BF16(o[j], plo[kc], bf[j]);
            }
            #pragma unroll
            for (int np = 0; np < 4; np++) {
                int r = np * 16 + (lane & 7) + (lane >> 4) * 8;
                int kcol = kk + ((lane >> 3) & 1) * 8;
                LDSM_X4(bf[2 * np][0], bf[2 * np][1], bf[2 * np + 1][0], bf[2 * np + 1][1],
                        bB + 24576 + sw128((uint32_t)(r * 128 + kcol * 2)));
            }
            #pragma unroll
            for (int j = 0; j < 8; j++)
                MMA_BF16(o[j], phi[kc], bf[j]);
        }

        __syncthreads();
        if (i + 2 < ntiles) { issueKV(i + 2); CP_COMMIT(); }
    }

    const float inv0 = 1.0f / lrow0, inv1 = 1.0f / lrow1;
    const int b = bh >> 4, h = bh & 15;
    const int row0g = qs + w * 16 + (lane >> 2);
    #pragma unroll
    for (int j = 0; j < 8; j++) {
        const int d = j * 8 + (lane & 3) * 2;
        size_t off0 = (size_t)(b * S_ + row0g) * DM_ + h * DK_ + d;
        size_t off1 = off0 + (size_t)8 * DM_;
        uint32_t hiw, low;
        split2(o[j][0] * inv0, o[j][1] * inv0, hiw, low);
        *reinterpret_cast<uint32_t*>(g_Ahi[0] + off0) = hiw;
        *reinterpret_cast<uint32_t*>(g_Alo[0] + off0) = low;
        split2(o[j][2] * inv1, o[j][3] * inv1, hiw, low);
        *reinterpret_cast<uint32_t*>(g_Ahi[0] + off1) = hiw;
        *reinterpret_cast<uint32_t*>(g_Alo[0] + off1) = low;
    }
}

// ----------------------------------------------------------------------------
extern "C" void kernel_launch(void* const* d_in, const int* in_sizes, int n_in,
                              void* d_out, int out_size)
{
    const float* query = (const float*)d_in[0];
    const float* key   = (const float*)d_in[1];
    const float* value = (const float*)d_in[2];
    const float* Wq = (const float*)d_in[4];
    const float* bq = (const float*)d_in[5];
    const float* Wk = (const float*)d_in[6];
    const float* bk = (const float*)d_in[7];
    const float* Wv = (const float*)d_in[8];
    const float* bv = (const float*)d_in[9];
    const float* Wo = (const float*)d_in[10];
    const float* bo = (const float*)d_in[11];
    float* out = (float*)d_out;

    cudaFuncSetAttribute(gemm_mma, cudaFuncAttributeMaxDynamicSharedMemorySize, GEMM_SMEM);
    cudaFuncSetAttribute(attn_mma, cudaFuncAttributeMaxDynamicSharedMemorySize, ATT_SMEM);

    const int n4 = M_ * DM_ / 4;
    const dim3 gg(DM_ / GN, M_ / GM);   // (4, 32) = 128 CTAs

    __nv_bfloat16 *Ahi, *Alo, *Whi, *Wlo;
    cudaGetSymbolAddress((void**)&Ahi, g_Ahi);
    cudaGetSymbolAddress((void**)&Alo, g_Alo);
    cudaGetSymbolAddress((void**)&Whi, g_Whi);
    cudaGetSymbolAddress((void**)&Wlo, g_Wlo);
    const size_t AS = (size_t)M_ * DM_;
    const size_t WS = (size_t)DM_ * DM_;

    conv_inputs<<<dim3(n4 / 256, 3), 256>>>((const float4*)query, (const float4*)key,
                                            (const float4*)value);
    conv_weights<<<dim3(32, 32, 4), dim3(32, 8)>>>(Wq, Wk, Wv, Wo);

    gemm_mma<<<gg, 256, GEMM_SMEM>>>(Ahi + 0 * AS, Alo + 0 * AS, Whi + 0 * WS, Wlo + 0 * WS, bq, nullptr, 0);
    gemm_mma<<<gg, 256, GEMM_SMEM>>>(Ahi + 1 * AS, Alo + 1 * AS, Whi + 1 * WS, Wlo + 1 * WS, bk, nullptr, 1);
    gemm_mma<<<gg, 256, GEMM_SMEM>>>(Ahi + 2 * AS, Alo + 2 * AS, Whi + 2 * WS, Wlo + 2 * WS, bv, nullptr, 2);
    transpV<<<dim3(S_ / 64, B_ * H_), 256>>>();
    attn_mma<<<dim3(S_ / 128, B_ * H_), 256, ATT_SMEM>>>();
    gemm_mma<<<gg, 256, GEMM_SMEM>>>(Ahi + 0 * AS, Alo + 0 * AS, Whi + 3 * WS, Wlo + 3 * WS, bo, out, 3);
}

// round 7
// speedup vs baseline: 1.4827x; 1.4827x over previous
#include <cuda_runtime.h>
#include <cuda_fp16.h>
#include <math.h>
#include <cstdint>

#define B_   2
#define S_   2048
#define H_   16
#define DK_  64
#define DM_  1024
#define M_   (B_ * S_)   // 4096

// ---------------------------------------------------------------------------
// PTX helpers — sm_80+ portable (harness PTX target is sm_103 WITHOUT 'a';
// tcgen05/TMEM unavailable; mma.sync/ldmatrix/cp.async are the path).
// ---------------------------------------------------------------------------
__device__ __forceinline__ uint32_t smem_u32(const void* p) {
    uint32_t a;
    asm("{ .reg .u64 t; cvta.to.shared.u64 t, %1; cvt.u32.u64 %0, t; }" : "=r"(a) : "l"(p));
    return a;
}
#define CP_ASYNC16(dst, src) \
    asm volatile("cp.async.cg.shared.global [%0], [%1], 16;" :: "r"(dst), "l"(src))
#define CP_COMMIT() asm volatile("cp.async.commit_group;" ::: "memory")
#define CP_WAIT(n)  asm volatile("cp.async.wait_group %0;" :: "n"(n) : "memory")

#define LDSM_X4(r0, r1, r2, r3, addr) \
    asm volatile("ldmatrix.sync.aligned.m8n8.x4.shared.b16 {%0,%1,%2,%3}, [%4];" \
                 : "=r"(r0), "=r"(r1), "=r"(r2), "=r"(r3) : "r"(addr))

#define MMA_F16(c, a, b) \
    asm volatile("mma.sync.aligned.m16n8k16.row.col.f32.f16.f16.f32 " \
                 "{%0,%1,%2,%3}, {%4,%5,%6,%7}, {%8,%9}, {%0,%1,%2,%3};" \
                 : "+f"((c)[0]), "+f"((c)[1]), "+f"((c)[2]), "+f"((c)[3]) \
                 : "r"((a)[0]), "r"((a)[1]), "r"((a)[2]), "r"((a)[3]), \
                   "r"((b)[0]), "r"((b)[1]))

__device__ __forceinline__ uint32_t sw128(uint32_t off) { return off ^ ((off >> 3) & 0x70); }

// split (x, y) fp32 -> packed half2 hi + lo (residual)
__device__ __forceinline__ void split2h(float x, float y, uint32_t& hi, uint32_t& lo) {
    __half hx = __float2half(x), hy = __float2half(y);
    __half2 h2 = __halves2half2(hx, hy);
    __half2 l2 = __halves2half2(__float2half(x - __half2float(hx)),
                                __float2half(y - __half2float(hy)));
    hi = *reinterpret_cast<uint32_t*>(&h2);
    lo = *reinterpret_cast<uint32_t*>(&l2);
}

// ---------------------------------------------------------------------------
// Scratch (device globals) — all fp16 now
// ---------------------------------------------------------------------------
__device__ __half g_Ahi[3][(size_t)M_ * DM_];    // A operands (0 reused for attn out)
__device__ __half g_Alo[3][(size_t)M_ * DM_];
__device__ __half g_Whi[4][(size_t)DM_ * DM_];   // W^T [N,K] K-contig
__device__ __half g_Wlo[4][(size_t)DM_ * DM_];
__device__ __half g_Q16[B_ * H_ * S_ * DK_];     // [B,H,S,64]
__device__ __half g_K16[B_ * H_ * S_ * DK_];
__device__ __half g_V16[B_ * H_ * S_ * DK_];
__device__ __half g_Vt16[B_ * H_ * DK_ * S_];    // [B,H,64,S]

// ---------------------------------------------------------------------------
// fp32 -> (hi, lo) fp16 split for all 3 inputs in one launch
// ---------------------------------------------------------------------------
__global__ void __launch_bounds__(256) conv_inputs(const float4* __restrict__ s0,
                                                   const float4* __restrict__ s1,
                                                   const float4* __restrict__ s2)
{
    const int which = blockIdx.y;
    const float4* src = (which == 0) ? s0 : (which == 1) ? s1 : s2;
    uint32_t* hi = reinterpret_cast<uint32_t*>(g_Ahi[which]);
    uint32_t* lo = reinterpret_cast<uint32_t*>(g_Alo[which]);
    int i = blockIdx.x * 256 + threadIdx.x;
    float4 v = src[i];
    uint32_t h0, l0, h1, l1;
    split2h(v.x, v.y, h0, l0);
    split2h(v.z, v.w, h1, l1);
    hi[2 * i + 0] = h0;
    hi[2 * i + 1] = h1;
    lo[2 * i + 0] = l0;
    lo[2 * i + 1] = l1;
}

// ---------------------------------------------------------------------------
// All 4 weights: W [K,N] fp32 -> transposed split fp16 Wt[N,K]
// ---------------------------------------------------------------------------
__global__ void __launch_bounds__(256) conv_weights(const float* __restrict__ W0,
                                                    const float* __restrict__ W1,
                                                    const float* __restrict__ W2,
                                                    const float* __restrict__ W3)
{
    __shared__ float tile[32][33];
    const int which = blockIdx.z;
    const float* W = (which == 0) ? W0 : (which == 1) ? W1 : (which == 2) ? W2 : W3;
    __half* hi = g_Whi[which];
    __half* lo = g_Wlo[which];
    const int bx = blockIdx.x, by = blockIdx.y;
    const int tx = threadIdx.x, ty = threadIdx.y;     // 32 x 8
    #pragma unroll
    for (int j = 0; j < 32; j += 8)
        tile[ty + j][tx] = W[(size_t)(by * 32 + ty + j) * DM_ + bx * 32 + tx];
    __syncthreads();
    #pragma unroll
    for (int j = 0; j < 32; j += 8) {
        float v = tile[tx][ty + j];
        __half h = __float2half(v);
        size_t o = (size_t)(bx * 32 + ty + j) * DM_ + by * 32 + tx;
        hi[o] = h;
        lo[o] = __float2half(v - __half2float(h));
    }
}

// ---------------------------------------------------------------------------
// V [B,H,S,64] fp16 -> V^T [B,H,64,S] fp16
// ---------------------------------------------------------------------------
__global__ void __launch_bounds__(256) transpV()
{
    __shared__ __half th[64][65];
    const int s0 = blockIdx.x * 64, bh = blockIdx.y;
    const int t = threadIdx.x;
    const __half* src = g_V16 + (size_t)bh * S_ * DK_;
    #pragma unroll
    for (int it = 0; it < 2; it++) {
        int r = (t >> 3) + it * 32, c = (t & 7) * 8;
        #pragma unroll
        for (int q = 0; q < 8; q++)
            th[r][c + q] = src[(size_t)(s0 + r) * DK_ + c + q];
    }
    __syncthreads();
    __half* dst = g_Vt16 + (size_t)bh * DK_ * S_;
    #pragma unroll
    for (int it = 0; it < 2; it++) {
        int d = (t >> 3) + it * 32, sc = (t & 7) * 8;
        #pragma unroll
        for (int q = 0; q < 8; q++)
            dst[(size_t)d * S_ + s0 + sc + q] = th[sc + q][d];
    }
}

// ---------------------------------------------------------------------------
// HMMA GEMM (R4 geometry: 128x128 CTA, BK=64, 2-stage, 2 CTA/SM), fp16,
// variable pass count npass in {1,2,3}:
//   pass0: Ahi*Whi, pass1: Alo*Whi, pass2: Ahi*Wlo
// modes 0/1/2 -> single fp16 head-split Q/K/V buffers; mode 3 -> fp32 Cext.
// ---------------------------------------------------------------------------
#define GM 128
#define GN 128
#define GEMM_SMEM (4 * 16384)

__global__ void __launch_bounds__(256) gemm_mma(const __half* __restrict__ Ahi,
                                                const __half* __restrict__ Alo,
                                                const __half* __restrict__ Whi,
                                                const __half* __restrict__ Wlo,
                                                const float* __restrict__ bias,
                                                float* __restrict__ Cext,
                                                int mode, int npass)
{
    extern __shared__ __align__(1024) char smem[];
    const uint32_t sb = smem_u32(smem);
    const int t = threadIdx.x, lane = t & 31, wid = t >> 5;
    const int warpM = wid >> 1, warpN = wid & 1;
    const int row0 = blockIdx.y * GM, col0 = blockIdx.x * GN;
    const int nch = npass * 16;

    float c[2][8][4] = {};

    int lr[4], lc[4];
    #pragma unroll
    for (int j = 0; j < 4; j++) {
        int g = t + j * 256;
        lr[j] = g >> 3;
        lc[j] = (g & 7) * 8;
    }

    auto issue = [&](int i) {
        const int seg = i >> 4, kc = (i & 15) * 64;
        const __half* aseg = (seg == 1) ? Alo : Ahi;
        const __half* wseg = (seg == 2) ? Wlo : Whi;
        const uint32_t ab = sb + (uint32_t)(i & 1) * 32768u;
        const uint32_t bb = ab + 16384u;
        #pragma unroll
        for (int j = 0; j < 4; j++) {
            uint32_t so = sw128((uint32_t)(lr[j] * 128 + lc[j] * 2));
            CP_ASYNC16(ab + so, aseg + (size_t)(row0 + lr[j]) * DM_ + kc + lc[j]);
            CP_ASYNC16(bb + so, wseg + (size_t)(col0 + lr[j]) * DM_ + kc + lc[j]);
        }
    };

    issue(0);
    CP_COMMIT();

    for (int i = 0; i < nch; i++) {
        if (i + 1 < nch) { issue(i + 1); CP_COMMIT(); CP_WAIT(1); }
        else             { CP_WAIT(0); }
        __syncthreads();

        const uint32_t ab = sb + (uint32_t)(i & 1) * 32768u;
        const uint32_t bb = ab + 16384u;

        #pragma unroll
        for (int kst = 0; kst < 4; kst++) {
            const int kk = kst * 16;
            uint32_t a[2][4], b[8][2];
            #pragma unroll
            for (int mt = 0; mt < 2; mt++) {
                int r = warpM * 32 + mt * 16 + (lane & 7) + ((lane >> 3) & 1) * 8;
                int kcol = kk + (lane >> 4) * 8;
                LDSM_X4(a[mt][0], a[mt][1], a[mt][2], a[mt][3],
                        ab + sw128((uint32_t)(r * 128 + kcol * 2)));
            }
            #pragma unroll
            for (int np = 0; np < 4; np++) {
                int r = warpN * 64 + np * 16 + (lane & 7) + (lane >> 4) * 8;
                int kcol = kk + ((lane >> 3) & 1) * 8;
                LDSM_X4(b[2 * np][0], b[2 * np][1], b[2 * np + 1][0], b[2 * np + 1][1],
                        bb + sw128((uint32_t)(r * 128 + kcol * 2)));
            }
            #pragma unroll
            for (int mt = 0; mt < 2; mt++)
                #pragma unroll
                for (int nt = 0; nt < 8; nt++)
                    MMA_F16(c[mt][nt], a[mt], b[nt]);
        }
        __syncthreads();
    }

    __half* D16 = (mode == 0) ? g_Q16 : (mode == 1) ? g_K16 : g_V16;
    #pragma unroll
    for (int mt = 0; mt < 2; mt++) {
        #pragma unroll
        for (int half = 0; half < 2; half++) {
            const int rowg = row0 + warpM * 32 + mt * 16 + (lane >> 2) + half * 8;
            const int bb_ = rowg >> 11, ss = rowg & (S_ - 1);
            #pragma unroll
            for (int nt = 0; nt < 8; nt++) {
                const int colg = col0 + warpN * 64 + nt * 8 + (lane & 3) * 2;
                const float v0 = c[mt][nt][half * 2 + 0] + bias[colg];
                const float v1 = c[mt][nt][half * 2 + 1] + bias[colg + 1];
                if (mode < 3) {
                    const int h = colg >> 6;
                    size_t off = ((size_t)((bb_ * H_ + h) * S_ + ss)) * DK_ + (colg & 63);
                    __half2 hv = __halves2half2(__float2half(v0), __float2half(v1));
                    *reinterpret_cast<__half2*>(D16 + off) = hv;
                } else {
                    *reinterpret_cast<float2*>(Cext + (size_t)rowg * DM_ + colg) =
                        make_float2(v0, v1);
                }
            }
        }
    }
}

// ---------------------------------------------------------------------------
// HMMA flash attention, causal, fp16.
// S = Q16·K16 (1 pass); O += Phi·V + Plo·V (2 passes, P split in-register).
// CTA = 128 queries of one (b,h); 8 warps x 16 rows; 64 keys/iter; LPT order.
// Output: fp16 hi/lo into g_Ahi[0]/g_Alo[0] at [B,S,1024].
// ---------------------------------------------------------------------------
#define ATT_SMEM 49152

__global__ void __launch_bounds__(256, 1) attn_mma()
{
    extern __shared__ __align__(1024) char smem[];
    const uint32_t sb = smem_u32(smem);
    const int t = threadIdx.x, lane = t & 31, w = t >> 5;
    const int qb = (int)gridDim.x - 1 - (int)blockIdx.x;   // heavy-first (LPT)
    const int bh = blockIdx.y;
    const int qs = qb * 128;
    const int ntiles = qb * 2 + 2;

    const size_t bo = (size_t)bh * S_ * DK_;
    const __half* Qg = g_Q16 + bo;
    const __half* Kg = g_K16 + bo;
    const __half* Vg = g_Vt16 + (size_t)bh * DK_ * S_;

    const uint32_t QB = sb;                 // 16KB Q tile

    #pragma unroll
    for (int j = 0; j < 4; j++) {
        int g = t + j * 256, r = g >> 3, c = (g & 7) * 8;
        uint32_t so = sw128((uint32_t)(r * 128 + c * 2));
        CP_ASYNC16(QB + so, Qg + (size_t)(qs + r) * DK_ + c);
    }
    auto issueKV = [&](int i) {
        const int kt = i * 64;
        const uint32_t bB = sb + 16384u + (uint32_t)(i & 1) * 16384u;
        #pragma unroll
        for (int j = 0; j < 2; j++) {
            int g = t + j * 256, r = g >> 3, c = (g & 7) * 8;
            uint32_t so = sw128((uint32_t)(r * 128 + c * 2));
            CP_ASYNC16(bB + so,        Kg + (size_t)(kt + r) * DK_ + c);
            CP_ASYNC16(bB + 8192 + so, Vg + (size_t)r * S_ + kt + c);
        }
    };
    issueKV(0);
    CP_COMMIT();
    if (ntiles > 1) { issueKV(1); CP_COMMIT(); }

    uint32_t qf[4][4];
    float o[8][4] = {};
    float mrow0 = -INFINITY, mrow1 = -INFINITY, lrow0 = 0.f, lrow1 = 0.f;

    for (int i = 0; i < ntiles; i++) {
        if (i + 1 < ntiles) CP_WAIT(1); else CP_WAIT(0);
        __syncthreads();

        if (i == 0) {
            #pragma unroll
            for (int kc = 0; kc < 4; kc++) {
                int r = w * 16 + (lane & 7) + ((lane >> 3) & 1) * 8;
                int kcol = kc * 16 + (lane >> 4) * 8;
                LDSM_X4(qf[kc][0], qf[kc][1], qf[kc][2], qf[kc][3],
                        QB + sw128((uint32_t)(r * 128 + kcol * 2)));
            }
        }

        const int kt = i * 64;
        const uint32_t bB = sb + 16384u + (uint32_t)(i & 1) * 16384u;

        // ---- S = Q K^T (single fp16 pass)
        float s[8][4] = {};
        #pragma unroll
        for (int kc = 0; kc < 4; kc++) {
            const int kk = kc * 16;
            uint32_t bf[8][2];
            #pragma unroll
            for (int np = 0; np < 4; np++) {
                int r = np * 16 + (lane & 7) + (lane >> 4) * 8;
                int kcol = kk + ((lane >> 3) & 1) * 8;
                LDSM_X4(bf[2 * np][0], bf[2 * np][1], bf[2 * np + 1][0], bf[2 * np + 1][1],
                        bB + sw128((uint32_t)(r * 128 + kcol * 2)));
            }
            #pragma unroll
            for (int j = 0; j < 8; j++)
                MMA_F16(s[j], qf[kc], bf[j]);
        }

        // ---- scale + causal mask + online softmax
        const int r0g = qs + w * 16 + (lane >> 2);
        const bool needmask = (kt + 63 > qs + w * 16);
        float mx0 = -INFINITY, mx1 = -INFINITY;
        #pragma unroll
        for (int j = 0; j < 8; j++) {
            const int cg = kt + j * 8 + (lane & 3) * 2;
            float v0 = s[j][0] * 0.125f, v1 = s[j][1] * 0.125f;
            float v2 = s[j][2] * 0.125f, v3 = s[j][3] * 0.125f;
            if (needmask) {
                if (cg     > r0g)     v0 = -INFINITY;
                if (cg + 1 > r0g)     v1 = -INFINITY;
                if (cg     > r0g + 8) v2 = -INFINITY;
                if (cg + 1 > r0g + 8) v3 = -INFINITY;
            }
            s[j][0] = v0; s[j][1] = v1; s[j][2] = v2; s[j][3] = v3;
            mx0 = fmaxf(mx0, fmaxf(v0, v1));
            mx1 = fmaxf(mx1, fmaxf(v2, v3));
        }
        mx0 = fmaxf(mx0, __shfl_xor_sync(0xffffffffu, mx0, 1));
        mx0 = fmaxf(mx0, __shfl_xor_sync(0xffffffffu, mx0, 2));
        mx1 = fmaxf(mx1, __shfl_xor_sync(0xffffffffu, mx1, 1));
        mx1 = fmaxf(mx1, __shfl_xor_sync(0xffffffffu, mx1, 2));
        const float mn0 = fmaxf(mrow0, mx0), mn1 = fmaxf(mrow1, mx1);
        const float al0 = __expf(mrow0 - mn0), al1 = __expf(mrow1 - mn1);
        float sum0 = 0.f, sum1 = 0.f;
        #pragma unroll
        for (int j = 0; j < 8; j++) {
            float p0 = __expf(s[j][0] - mn0); s[j][0] = p0; sum0 += p0;
            float p1 = __expf(s[j][1] - mn0); s[j][1] = p1; sum0 += p1;
            float p2 = __expf(s[j][2] - mn1); s[j][2] = p2; sum1 += p2;
            float p3 = __expf(s[j][3] - mn1); s[j][3] = p3; sum1 += p3;
        }
        sum0 += __shfl_xor_sync(0xffffffffu, sum0, 1);
        sum0 += __shfl_xor_sync(0xffffffffu, sum0, 2);
        sum1 += __shfl_xor_sync(0xffffffffu, sum1, 1);
        sum1 += __shfl_xor_sync(0xffffffffu, sum1, 2);
        lrow0 = lrow0 * al0 + sum0;
        lrow1 = lrow1 * al1 + sum1;
        mrow0 = mn0; mrow1 = mn1;
        #pragma unroll
        for (int j = 0; j < 8; j++) {
            o[j][0] *= al0; o[j][1] *= al0;
            o[j][2] *= al1; o[j][3] *= al1;
        }

        // ---- P -> fp16 hi/lo A-fragments (in-register)
        uint32_t phi[4][4], plo[4][4];
        #pragma unroll
        for (int kc = 0; kc < 4; kc++) {
            split2h(s[2 * kc][0],     s[2 * kc][1],     phi[kc][0], plo[kc][0]);
            split2h(s[2 * kc][2],     s[2 * kc][3],     phi[kc][1], plo[kc][1]);
            split2h(s[2 * kc + 1][0], s[2 * kc + 1][1], phi[kc][2], plo[kc][2]);
            split2h(s[2 * kc + 1][2], s[2 * kc + 1][3], phi[kc][3], plo[kc][3]);
        }

        // ---- O += Phi*V + Plo*V (2 passes)
        #pragma unroll
        for (int kc = 0; kc < 4; kc++) {
            const int kk = kc * 16;
            uint32_t vf[8][2];
            #pragma unroll
            for (int np = 0; np < 4; np++) {
                int r = np * 16 + (lane & 7) + (lane >> 4) * 8;
                int kcol = kk + ((lane >> 3) & 1) * 8;
                LDSM_X4(vf[2 * np][0], vf[2 * np][1], vf[2 * np + 1][0], vf[2 * np + 1][1],
                        bB + 8192 + sw128((uint32_t)(r * 128 + kcol * 2)));
            }
            #pragma unroll
            for (int j = 0; j < 8; j++) {
                MMA_F16(o[j], phi[kc], vf[j]);
                MMA_F16(o[j], plo[kc], vf[j]);
            }
        }

        __syncthreads();
        if (i + 2 < ntiles) { issueKV(i + 2); CP_COMMIT(); }
    }

    // ---- epilogue: normalize and write fp16 hi/lo to [B,S,1024]
    const float inv0 = 1.0f / lrow0, inv1 = 1.0f / lrow1;
    const int b = bh >> 4, h = bh & 15;
    const int row0g = qs + w * 16 + (lane >> 2);
    #pragma unroll
    for (int j = 0; j < 8; j++) {
        const int d = j * 8 + (lane & 3) * 2;
        size_t off0 = (size_t)(b * S_ + row0g) * DM_ + h * DK_ + d;
        size_t off1 = off0 + (size_t)8 * DM_;
        uint32_t hiw, low;
        split2h(o[j][0] * inv0, o[j][1] * inv0, hiw, low);
        *reinterpret_cast<uint32_t*>(g_Ahi[0] + off0) = hiw;
        *reinterpret_cast<uint32_t*>(g_Alo[0] + off0) = low;
        split2h(o[j][2] * inv1, o[j][3] * inv1, hiw, low);
        *reinterpret_cast<uint32_t*>(g_Ahi[0] + off1) = hiw;
        *reinterpret_cast<uint32_t*>(g_Alo[0] + off1) = low;
    }
}

// ----------------------------------------------------------------------------
extern "C" void kernel_launch(void* const* d_in, const int* in_sizes, int n_in,
                              void* d_out, int out_size)
{
    const float* query = (const float*)d_in[0];
    const float* key   = (const float*)d_in[1];
    const float* value = (const float*)d_in[2];
    const float* Wq = (const float*)d_in[4];
    const float* bq = (const float*)d_in[5];
    const float* Wk = (const float*)d_in[6];
    const float* bk = (const float*)d_in[7];
    const float* Wv = (const float*)d_in[8];
    const float* bv = (const float*)d_in[9];
    const float* Wo = (const float*)d_in[10];
    const float* bo = (const float*)d_in[11];
    float* out = (float*)d_out;

    cudaFuncSetAttribute(gemm_mma, cudaFuncAttributeMaxDynamicSharedMemorySize, GEMM_SMEM);
    cudaFuncSetAttribute(attn_mma, cudaFuncAttributeMaxDynamicSharedMemorySize, ATT_SMEM);

    const int n4 = M_ * DM_ / 4;
    const dim3 gg(DM_ / GN, M_ / GM);   // (8, 32) = 256 CTAs

    __half *Ahi, *Alo, *Whi, *Wlo;
    cudaGetSymbolAddress((void**)&Ahi, g_Ahi);
    cudaGetSymbolAddress((void**)&Alo, g_Alo);
    cudaGetSymbolAddress((void**)&Whi, g_Whi);
    cudaGetSymbolAddress((void**)&Wlo, g_Wlo);
    const size_t AS = (size_t)M_ * DM_;
    const size_t WS = (size_t)DM_ * DM_;

    conv_inputs<<<dim3(n4 / 256, 3), 256>>>((const float4*)query, (const float4*)key,
                                            (const float4*)value);
    conv_weights<<<dim3(32, 32, 4), dim3(32, 8)>>>(Wq, Wk, Wv, Wo);

    // Q, K projections: 1 pass; V: 2 passes
    gemm_mma<<<gg, 256, GEMM_SMEM>>>(Ahi + 0 * AS, Alo + 0 * AS, Whi + 0 * WS, Wlo + 0 * WS, bq, nullptr, 0, 1);
    gemm_mma<<<gg, 256, GEMM_SMEM>>>(Ahi + 1 * AS, Alo + 1 * AS, Whi + 1 * WS, Wlo + 1 * WS, bk, nullptr, 1, 1);
    gemm_mma<<<gg, 256, GEMM_SMEM>>>(Ahi + 2 * AS, Alo + 2 * AS, Whi + 2 * WS, Wlo + 2 * WS, bv, nullptr, 2, 2);
    transpV<<<dim3(S_ / 64, B_ * H_), 256>>>();
    attn_mma<<<dim3(S_ / 128, B_ * H_), 256, ATT_SMEM>>>();
    // Output projection: 3 passes (direct output path)
    gemm_mma<<<gg, 256, GEMM_SMEM>>>(Ahi + 0 * AS, Alo + 0 * AS, Whi + 3 * WS, Wlo + 3 * WS, bo, out, 3, 3);
}

// round 8
// speedup vs baseline: 1.8230x; 1.2296x over previous
#include <cuda_runtime.h>
#include <cuda_fp16.h>
#include <math.h>
#include <cstdint>

#define B_   2
#define S_   2048
#define H_   16
#define DK_  64
#define DM_  1024
#define M_   (B_ * S_)   // 4096

// ---------------------------------------------------------------------------
// PTX helpers — sm_80+ portable (harness PTX target is sm_103 WITHOUT 'a';
// tcgen05/TMEM unavailable; mma.sync/ldmatrix/cp.async are the path).
// ---------------------------------------------------------------------------
__device__ __forceinline__ uint32_t smem_u32(const void* p) {
    uint32_t a;
    asm("{ .reg .u64 t; cvta.to.shared.u64 t, %1; cvt.u32.u64 %0, t; }" : "=r"(a) : "l"(p));
    return a;
}
#define CP_ASYNC16(dst, src) \
    asm volatile("cp.async.cg.shared.global [%0], [%1], 16;" :: "r"(dst), "l"(src))
#define CP_COMMIT() asm volatile("cp.async.commit_group;" ::: "memory")
#define CP_WAIT(n)  asm volatile("cp.async.wait_group %0;" :: "n"(n) : "memory")

#define LDSM_X4(r0, r1, r2, r3, addr) \
    asm volatile("ldmatrix.sync.aligned.m8n8.x4.shared.b16 {%0,%1,%2,%3}, [%4];" \
                 : "=r"(r0), "=r"(r1), "=r"(r2), "=r"(r3) : "r"(addr))

#define MMA_F16(c, a, b) \
    asm volatile("mma.sync.aligned.m16n8k16.row.col.f32.f16.f16.f32 " \
                 "{%0,%1,%2,%3}, {%4,%5,%6,%7}, {%8,%9}, {%0,%1,%2,%3};" \
                 : "+f"((c)[0]), "+f"((c)[1]), "+f"((c)[2]), "+f"((c)[3]) \
                 : "r"((a)[0]), "r"((a)[1]), "r"((a)[2]), "r"((a)[3]), \
                   "r"((b)[0]), "r"((b)[1]))

__device__ __forceinline__ uint32_t sw128(uint32_t off) { return off ^ ((off >> 3) & 0x70); }

// split (x, y) fp32 -> packed half2 hi + lo (residual)
__device__ __forceinline__ void split2h(float x, float y, uint32_t& hi, uint32_t& lo) {
    __half hx = __float2half(x), hy = __float2half(y);
    __half2 h2 = __halves2half2(hx, hy);
    __half2 l2 = __halves2half2(__float2half(x - __half2float(hx)),
                                __float2half(y - __half2float(hy)));
    hi = *reinterpret_cast<uint32_t*>(&h2);
    lo = *reinterpret_cast<uint32_t*>(&l2);
}

// ---------------------------------------------------------------------------
// Scratch (device globals)
// ---------------------------------------------------------------------------
__device__ __half g_Ahi[3][(size_t)M_ * DM_];    // A operands (0 reused for attn out)
__device__ __half g_Alo[(size_t)M_ * DM_];       // lo only needed for attn out
__device__ __half g_Whi[4][(size_t)DM_ * DM_];   // W^T [N,K] K-contig
__device__ __half g_Wlo[4][(size_t)DM_ * DM_];
__device__ __half g_Q16[B_ * H_ * S_ * DK_];     // [B,H,S,64]
__device__ __half g_K16[B_ * H_ * S_ * DK_];
__device__ __half g_V16[B_ * H_ * S_ * DK_];
__device__ __half g_Vt16[B_ * H_ * DK_ * S_];    // [B,H,64,S]

// ---------------------------------------------------------------------------
// fp32 -> fp16 (hi only — all projection GEMMs are A-hi single input now)
// ---------------------------------------------------------------------------
__global__ void __launch_bounds__(256) conv_inputs(const float4* __restrict__ s0,
                                                   const float4* __restrict__ s1,
                                                   const float4* __restrict__ s2)
{
    const int which = blockIdx.y;
    const float4* src = (which == 0) ? s0 : (which == 1) ? s1 : s2;
    uint32_t* hi = reinterpret_cast<uint32_t*>(g_Ahi[which]);
    int i = blockIdx.x * 256 + threadIdx.x;
    float4 v = src[i];
    __half2 h0 = __halves2half2(__float2half(v.x), __float2half(v.y));
    __half2 h1 = __halves2half2(__float2half(v.z), __float2half(v.w));
    hi[2 * i + 0] = *reinterpret_cast<uint32_t*>(&h0);
    hi[2 * i + 1] = *reinterpret_cast<uint32_t*>(&h1);
}

// ---------------------------------------------------------------------------
// All 4 weights: W [K,N] fp32 -> transposed split fp16 Wt[N,K]
// ---------------------------------------------------------------------------
__global__ void __launch_bounds__(256) conv_weights(const float* __restrict__ W0,
                                                    const float* __restrict__ W1,
                                                    const float* __restrict__ W2,
                                                    const float* __restrict__ W3)
{
    __shared__ float tile[32][33];
    const int which = blockIdx.z;
    const float* W = (which == 0) ? W0 : (which == 1) ? W1 : (which == 2) ? W2 : W3;
    __half* hi = g_Whi[which];
    __half* lo = g_Wlo[which];
    const int bx = blockIdx.x, by = blockIdx.y;
    const int tx = threadIdx.x, ty = threadIdx.y;     // 32 x 8
    #pragma unroll
    for (int j = 0; j < 32; j += 8)
        tile[ty + j][tx] = W[(size_t)(by * 32 + ty + j) * DM_ + bx * 32 + tx];
    __syncthreads();
    #pragma unroll
    for (int j = 0; j < 32; j += 8) {
        float v = tile[tx][ty + j];
        __half h = __float2half(v);
        size_t o = (size_t)(bx * 32 + ty + j) * DM_ + by * 32 + tx;
        hi[o] = h;
        lo[o] = __float2half(v - __half2float(h));
    }
}

// ---------------------------------------------------------------------------
// V [B,H,S,64] fp16 -> V^T [B,H,64,S] fp16
// ---------------------------------------------------------------------------
__global__ void __launch_bounds__(256) transpV()
{
    __shared__ __half th[64][65];
    const int s0 = blockIdx.x * 64, bh = blockIdx.y;
    const int t = threadIdx.x;
    const __half* src = g_V16 + (size_t)bh * S_ * DK_;
    #pragma unroll
    for (int it = 0; it < 2; it++) {
        int r = (t >> 3) + it * 32, c = (t & 7) * 8;
        #pragma unroll
        for (int q = 0; q < 8; q++)
            th[r][c + q] = src[(size_t)(s0 + r) * DK_ + c + q];
    }
    __syncthreads();
    __half* dst = g_Vt16 + (size_t)bh * DK_ * S_;
    #pragma unroll
    for (int it = 0; it < 2; it++) {
        int d = (t >> 3) + it * 32, sc = (t & 7) * 8;
        #pragma unroll
        for (int q = 0; q < 8; q++)
            dst[(size_t)d * S_ + s0 + sc + q] = th[sc + q][d];
    }
}

// ---------------------------------------------------------------------------
// HMMA GEMM (128x128 CTA, BK=64, 2-stage, FORCED 2 CTA/SM), fp16.
// Pass schedule: pass0 Ahi*Whi, pass1 Alo*Whi, pass2 Ahi*Wlo (npass selects).
// modes 0/1/2 -> fp16 head-split Q/K/V buffers; mode 3 -> fp32 Cext.
// ---------------------------------------------------------------------------
#define GM 128
#define GN 128
#define GEMM_SMEM (4 * 16384)

__global__ void __launch_bounds__(256, 2) gemm_mma(const __half* __restrict__ Ahi,
                                                   const __half* __restrict__ Alo,
                                                   const __half* __restrict__ Whi,
                                                   const __half* __restrict__ Wlo,
                                                   const float* __restrict__ bias,
                                                   float* __restrict__ Cext,
                                                   int mode, int npass)
{
    extern __shared__ __align__(1024) char smem[];
    const uint32_t sb = smem_u32(smem);
    const int t = threadIdx.x, lane = t & 31, wid = t >> 5;
    const int warpM = wid >> 1, warpN = wid & 1;
    const int row0 = blockIdx.y * GM, col0 = blockIdx.x * GN;
    const int nch = npass * 16;

    float c[2][8][4] = {};

    int lr[4], lc[4];
    #pragma unroll
    for (int j = 0; j < 4; j++) {
        int g = t + j * 256;
        lr[j] = g >> 3;
        lc[j] = (g & 7) * 8;
    }

    auto issue = [&](int i) {
        const int seg = i >> 4, kc = (i & 15) * 64;
        const __half* aseg = (seg == 1) ? Alo : Ahi;
        const __half* wseg = (seg == 2) ? Wlo : Whi;
        const uint32_t ab = sb + (uint32_t)(i & 1) * 32768u;
        const uint32_t bb = ab + 16384u;
        #pragma unroll
        for (int j = 0; j < 4; j++) {
            uint32_t so = sw128((uint32_t)(lr[j] * 128 + lc[j] * 2));
            CP_ASYNC16(ab + so, aseg + (size_t)(row0 + lr[j]) * DM_ + kc + lc[j]);
            CP_ASYNC16(bb + so, wseg + (size_t)(col0 + lr[j]) * DM_ + kc + lc[j]);
        }
    };

    issue(0);
    CP_COMMIT();

    for (int i = 0; i < nch; i++) {
        if (i + 1 < nch) { issue(i + 1); CP_COMMIT(); CP_WAIT(1); }
        else             { CP_WAIT(0); }
        __syncthreads();

        const uint32_t ab = sb + (uint32_t)(i & 1) * 32768u;
        const uint32_t bb = ab + 16384u;

        #pragma unroll
        for (int kst = 0; kst < 4; kst++) {
            const int kk = kst * 16;
            uint32_t a[2][4], b[8][2];
            #pragma unroll
            for (int mt = 0; mt < 2; mt++) {
                int r = warpM * 32 + mt * 16 + (lane & 7) + ((lane >> 3) & 1) * 8;
                int kcol = kk + (lane >> 4) * 8;
                LDSM_X4(a[mt][0], a[mt][1], a[mt][2], a[mt][3],
                        ab + sw128((uint32_t)(r * 128 + kcol * 2)));
            }
            #pragma unroll
            for (int np = 0; np < 4; np++) {
                int r = warpN * 64 + np * 16 + (lane & 7) + (lane >> 4) * 8;
                int kcol = kk + ((lane >> 3) & 1) * 8;
                LDSM_X4(b[2 * np][0], b[2 * np][1], b[2 * np + 1][0], b[2 * np + 1][1],
                        bb + sw128((uint32_t)(r * 128 + kcol * 2)));
            }
            #pragma unroll
            for (int mt = 0; mt < 2; mt++)
                #pragma unroll
                for (int nt = 0; nt < 8; nt++)
                    MMA_F16(c[mt][nt], a[mt], b[nt]);
        }
        __syncthreads();
    }

    __half* D16 = (mode == 0) ? g_Q16 : (mode == 1) ? g_K16 : g_V16;
    #pragma unroll
    for (int mt = 0; mt < 2; mt++) {
        #pragma unroll
        for (int half = 0; half < 2; half++) {
            const int rowg = row0 + warpM * 32 + mt * 16 + (lane >> 2) + half * 8;
            const int bb_ = rowg >> 11, ss = rowg & (S_ - 1);
            #pragma unroll
            for (int nt = 0; nt < 8; nt++) {
                const int colg = col0 + warpN * 64 + nt * 8 + (lane & 3) * 2;
                const float v0 = c[mt][nt][half * 2 + 0] + bias[colg];
                const float v1 = c[mt][nt][half * 2 + 1] + bias[colg + 1];
                if (mode < 3) {
                    const int h = colg >> 6;
                    size_t off = ((size_t)((bb_ * H_ + h) * S_ + ss)) * DK_ + (colg & 63);
                    __half2 hv = __halves2half2(__float2half(v0), __float2half(v1));
                    *reinterpret_cast<__half2*>(D16 + off) = hv;
                } else {
                    *reinterpret_cast<float2*>(Cext + (size_t)rowg * DM_ + colg) =
                        make_float2(v0, v1);
                }
            }
        }
    }
}

// ---------------------------------------------------------------------------
// HMMA flash attention, causal, fp16 (unchanged from R7).
// S = Q16·K16 (1 pass); O += Phi·V + Plo·V (2 passes).
// Output: fp16 hi/lo into g_Ahi[0]/g_Alo at [B,S,1024].
// ---------------------------------------------------------------------------
#define ATT_SMEM 49152

__global__ void __launch_bounds__(256, 1) attn_mma()
{
    extern __shared__ __align__(1024) char smem[];
    const uint32_t sb = smem_u32(smem);
    const int t = threadIdx.x, lane = t & 31, w = t >> 5;
    const int qb = (int)gridDim.x - 1 - (int)blockIdx.x;   // heavy-first (LPT)
    const int bh = blockIdx.y;
    const int qs = qb * 128;
    const int ntiles = qb * 2 + 2;

    const size_t bo = (size_t)bh * S_ * DK_;
    const __half* Qg = g_Q16 + bo;
    const __half* Kg = g_K16 + bo;
    const __half* Vg = g_Vt16 + (size_t)bh * DK_ * S_;

    const uint32_t QB = sb;

    #pragma unroll
    for (int j = 0; j < 4; j++) {
        int g = t + j * 256, r = g >> 3, c = (g & 7) * 8;
        uint32_t so = sw128((uint32_t)(r * 128 + c * 2));
        CP_ASYNC16(QB + so, Qg + (size_t)(qs + r) * DK_ + c);
    }
    auto issueKV = [&](int i) {
        const int kt = i * 64;
        const uint32_t bB = sb + 16384u + (uint32_t)(i & 1) * 16384u;
        #pragma unroll
        for (int j = 0; j < 2; j++) {
            int g = t + j * 256, r = g >> 3, c = (g & 7) * 8;
            uint32_t so = sw128((uint32_t)(r * 128 + c * 2));
            CP_ASYNC16(bB + so,        Kg + (size_t)(kt + r) * DK_ + c);
            CP_ASYNC16(bB + 8192 + so, Vg + (size_t)r * S_ + kt + c);
        }
    };
    issueKV(0);
    CP_COMMIT();
    if (ntiles > 1) { issueKV(1); CP_COMMIT(); }

    uint32_t qf[4][4];
    float o[8][4] = {};
    float mrow0 = -INFINITY, mrow1 = -INFINITY, lrow0 = 0.f, lrow1 = 0.f;

    for (int i = 0; i < ntiles; i++) {
        if (i + 1 < ntiles) CP_WAIT(1); else CP_WAIT(0);
        __syncthreads();

        if (i == 0) {
            #pragma unroll
            for (int kc = 0; kc < 4; kc++) {
                int r = w * 16 + (lane & 7) + ((lane >> 3) & 1) * 8;
                int kcol = kc * 16 + (lane >> 4) * 8;
                LDSM_X4(qf[kc][0], qf[kc][1], qf[kc][2], qf[kc][3],
                        QB + sw128((uint32_t)(r * 128 + kcol * 2)));
            }
        }

        const int kt = i * 64;
        const uint32_t bB = sb + 16384u + (uint32_t)(i & 1) * 16384u;

        float s[8][4] = {};
        #pragma unroll
        for (int kc = 0; kc < 4; kc++) {
            const int kk = kc * 16;
            uint32_t bf[8][2];
            #pragma unroll
            for (int np = 0; np < 4; np++) {
                int r = np * 16 + (lane & 7) + (lane >> 4) * 8;
                int kcol = kk + ((lane >> 3) & 1) * 8;
                LDSM_X4(bf[2 * np][0], bf[2 * np][1], bf[2 * np + 1][0], bf[2 * np + 1][1],
                        bB + sw128((uint32_t)(r * 128 + kcol * 2)));
            }
            #pragma unroll
            for (int j = 0; j < 8; j++)
                MMA_F16(s[j], qf[kc], bf[j]);
        }

        const int r0g = qs + w * 16 + (lane >> 2);
        const bool needmask = (kt + 63 > qs + w * 16);
        float mx0 = -INFINITY, mx1 = -INFINITY;
        #pragma unroll
        for (int j = 0; j < 8; j++) {
            const int cg = kt + j * 8 + (lane & 3) * 2;
            float v0 = s[j][0] * 0.125f, v1 = s[j][1] * 0.125f;
            float v2 = s[j][2] * 0.125f, v3 = s[j][3] * 0.125f;
            if (needmask) {
                if (cg     > r0g)     v0 = -INFINITY;
                if (cg + 1 > r0g)     v1 = -INFINITY;
                if (cg     > r0g + 8) v2 = -INFINITY;
                if (cg + 1 > r0g + 8) v3 = -INFINITY;
            }
            s[j][0] = v0; s[j][1] = v1; s[j][2] = v2; s[j][3] = v3;
            mx0 = fmaxf(mx0, fmaxf(v0, v1));
            mx1 = fmaxf(mx1, fmaxf(v2, v3));
        }
        mx0 = fmaxf(mx0, __shfl_xor_sync(0xffffffffu, mx0, 1));
        mx0 = fmaxf(mx0, __shfl_xor_sync(0xffffffffu, mx0, 2));
        mx1 = fmaxf(mx1, __shfl_xor_sync(0xffffffffu, mx1, 1));
        mx1 = fmaxf(mx1, __shfl_xor_sync(0xffffffffu, mx1, 2));
        const float mn0 = fmaxf(mrow0, mx0), mn1 = fmaxf(mrow1, mx1);
        const float al0 = __expf(mrow0 - mn0), al1 = __expf(mrow1 - mn1);
        float sum0 = 0.f, sum1 = 0.f;
        #pragma unroll
        for (int j = 0; j < 8; j++) {
            float p0 = __expf(s[j][0] - mn0); s[j][0] = p0; sum0 += p0;
            float p1 = __expf(s[j][1] - mn0); s[j][1] = p1; sum0 += p1;
            float p2 = __expf(s[j][2] - mn1); s[j][2] = p2; sum1 += p2;
            float p3 = __expf(s[j][3] - mn1); s[j][3] = p3; sum1 += p3;
        }
        sum0 += __shfl_xor_sync(0xffffffffu, sum0, 1);
        sum0 += __shfl_xor_sync(0xffffffffu, sum0, 2);
        sum1 += __shfl_xor_sync(0xffffffffu, sum1, 1);
        sum1 += __shfl_xor_sync(0xffffffffu, sum1, 2);
        lrow0 = lrow0 * al0 + sum0;
        lrow1 = lrow1 * al1 + sum1;
        mrow0 = mn0; mrow1 = mn1;
        #pragma unroll
        for (int j = 0; j < 8; j++) {
            o[j][0] *= al0; o[j][1] *= al0;
            o[j][2] *= al1; o[j][3] *= al1;
        }

        uint32_t phi[4][4], plo[4][4];
        #pragma unroll
        for (int kc = 0; kc < 4; kc++) {
            split2h(s[2 * kc][0],     s[2 * kc][1],     phi[kc][0], plo[kc][0]);
            split2h(s[2 * kc][2],     s[2 * kc][3],     phi[kc][1], plo[kc][1]);
            split2h(s[2 * kc + 1][0], s[2 * kc + 1][1], phi[kc][2], plo[kc][2]);
            split2h(s[2 * kc + 1][2], s[2 * kc + 1][3], phi[kc][3], plo[kc][3]);
        }

        #pragma unroll
        for (int kc = 0; kc < 4; kc++) {
            const int kk = kc * 16;
            uint32_t vf[8][2];
            #pragma unroll
            for (int np = 0; np < 4; np++) {
                int r = np * 16 + (lane & 7) + (lane >> 4) * 8;
                int kcol = kk + ((lane >> 3) & 1) * 8;
                LDSM_X4(vf[2 * np][0], vf[2 * np][1], vf[2 * np + 1][0], vf[2 * np + 1][1],
                        bB + 8192 + sw128((uint32_t)(r * 128 + kcol * 2)));
            }
            #pragma unroll
            for (int j = 0; j < 8; j++) {
                MMA_F16(o[j], phi[kc], vf[j]);
                MMA_F16(o[j], plo[kc], vf[j]);
            }
        }

        __syncthreads();
        if (i + 2 < ntiles) { issueKV(i + 2); CP_COMMIT(); }
    }

    const float inv0 = 1.0f / lrow0, inv1 = 1.0f / lrow1;
    const int b = bh >> 4, h = bh & 15;
    const int row0g = qs + w * 16 + (lane >> 2);
    #pragma unroll
    for (int j = 0; j < 8; j++) {
        const int d = j * 8 + (lane & 3) * 2;
        size_t off0 = (size_t)(b * S_ + row0g) * DM_ + h * DK_ + d;
        size_t off1 = off0 + (size_t)8 * DM_;
        uint32_t hiw, low;
        split2h(o[j][0] * inv0, o[j][1] * inv0, hiw, low);
        *reinterpret_cast<uint32_t*>(g_Ahi[0] + off0) = hiw;
        *reinterpret_cast<uint32_t*>(g_Alo + off0) = low;
        split2h(o[j][2] * inv1, o[j][3] * inv1, hiw, low);
        *reinterpret_cast<uint32_t*>(g_Ahi[0] + off1) = hiw;
        *reinterpret_cast<uint32_t*>(g_Alo + off1) = low;
    }
}

// ----------------------------------------------------------------------------
extern "C" void kernel_launch(void* const* d_in, const int* in_sizes, int n_in,
                              void* d_out, int out_size)
{
    const float* query = (const float*)d_in[0];
    const float* key   = (const float*)d_in[1];
    const float* value = (const float*)d_in[2];
    const float* Wq = (const float*)d_in[4];
    const float* bq = (const float*)d_in[5];
    const float* Wk = (const float*)d_in[6];
    const float* bk = (const float*)d_in[7];
    const float* Wv = (const float*)d_in[8];
    const float* bv = (const float*)d_in[9];
    const float* Wo = (const float*)d_in[10];
    const float* bo = (const float*)d_in[11];
    float* out = (float*)d_out;

    cudaFuncSetAttribute(gemm_mma, cudaFuncAttributeMaxDynamicSharedMemorySize, GEMM_SMEM);
    cudaFuncSetAttribute(attn_mma, cudaFuncAttributeMaxDynamicSharedMemorySize, ATT_SMEM);

    const int n4 = M_ * DM_ / 4;
    const dim3 gg(DM_ / GN, M_ / GM);   // (8, 32) = 256 CTAs

    __half *Ahi, *Alo, *Whi, *Wlo;
    cudaGetSymbolAddress((void**)&Ahi, g_Ahi);
    cudaGetSymbolAddress((void**)&Alo, g_Alo);
    cudaGetSymbolAddress((void**)&Whi, g_Whi);
    cudaGetSymbolAddress((void**)&Wlo, g_Wlo);
    const size_t AS = (size_t)M_ * DM_;
    const size_t WS = (size_t)DM_ * DM_;

    conv_inputs<<<dim3(n4 / 256, 3), 256>>>((const float4*)query, (const float4*)key,
                                            (const float4*)value);
    conv_weights<<<dim3(32, 32, 4), dim3(32, 8)>>>(Wq, Wk, Wv, Wo);

    // Q, K, V projections: 1 pass each
    gemm_mma<<<gg, 256, GEMM_SMEM>>>(Ahi + 0 * AS, Alo, Whi + 0 * WS, Wlo + 0 * WS, bq, nullptr, 0, 1);
    gemm_mma<<<gg, 256, GEMM_SMEM>>>(Ahi + 1 * AS, Alo, Whi + 1 * WS, Wlo + 1 * WS, bk, nullptr, 1, 1);
    gemm_mma<<<gg, 256, GEMM_SMEM>>>(Ahi + 2 * AS, Alo, Whi + 2 * WS, Wlo + 2 * WS, bv, nullptr, 2, 1);
    transpV<<<dim3(S_ / 64, B_ * H_), 256>>>();
    attn_mma<<<dim3(S_ / 128, B_ * H_), 256, ATT_SMEM>>>();
    // Output projection: 2 passes (Ahi*Whi + Alo*Whi)
    gemm_mma<<<gg, 256, GEMM_SMEM>>>(Ahi + 0 * AS, Alo, Whi + 3 * WS, Wlo + 3 * WS, bo, out, 3, 2);
}

// round 9
// speedup vs baseline: 2.0503x; 1.1247x over previous
#include <cuda_runtime.h>
#include <cuda_fp16.h>
#include <math.h>
#include <cstdint>

#define B_   2
#define S_   2048
#define H_   16
#define DK_  64
#define DM_  1024
#define M_   (B_ * S_)   // 4096

// ---------------------------------------------------------------------------
// PTX helpers — sm_80+ portable (harness PTX target is sm_103 WITHOUT 'a';
// tcgen05/TMEM unavailable; mma.sync/ldmatrix/cp.async are the path).
// ---------------------------------------------------------------------------
__device__ __forceinline__ uint32_t smem_u32(const void* p) {
    uint32_t a;
    asm("{ .reg .u64 t; cvta.to.shared.u64 t, %1; cvt.u32.u64 %0, t; }" : "=r"(a) : "l"(p));
    return a;
}
#define CP_ASYNC16(dst, src) \
    asm volatile("cp.async.cg.shared.global [%0], [%1], 16;" :: "r"(dst), "l"(src))
#define CP_COMMIT() asm volatile("cp.async.commit_group;" ::: "memory")
#define CP_WAIT(n)  asm volatile("cp.async.wait_group %0;" :: "n"(n) : "memory")

#define LDSM_X4(r0, r1, r2, r3, addr) \
    asm volatile("ldmatrix.sync.aligned.m8n8.x4.shared.b16 {%0,%1,%2,%3}, [%4];" \
                 : "=r"(r0), "=r"(r1), "=r"(r2), "=r"(r3) : "r"(addr))

#define MMA_F16(c, a, b) \
    asm volatile("mma.sync.aligned.m16n8k16.row.col.f32.f16.f16.f32 " \
                 "{%0,%1,%2,%3}, {%4,%5,%6,%7}, {%8,%9}, {%0,%1,%2,%3};" \
                 : "+f"((c)[0]), "+f"((c)[1]), "+f"((c)[2]), "+f"((c)[3]) \
                 : "r"((a)[0]), "r"((a)[1]), "r"((a)[2]), "r"((a)[3]), \
                   "r"((b)[0]), "r"((b)[1]))

__device__ __forceinline__ uint32_t sw128(uint32_t off) { return off ^ ((off >> 3) & 0x70); }

// split (x, y) fp32 -> packed half2 hi + lo (residual)
__device__ __forceinline__ void split2h(float x, float y, uint32_t& hi, uint32_t& lo) {
    __half hx = __float2half(x), hy = __float2half(y);
    __half2 h2 = __halves2half2(hx, hy);
    __half2 l2 = __halves2half2(__float2half(x - __half2float(hx)),
                                __float2half(y - __half2float(hy)));
    hi = *reinterpret_cast<uint32_t*>(&h2);
    lo = *reinterpret_cast<uint32_t*>(&l2);
}
__device__ __forceinline__ uint32_t pack2h(float x, float y) {
    __half2 h2 = __halves2half2(__float2half(x), __float2half(y));
    return *reinterpret_cast<uint32_t*>(&h2);
}

// ---------------------------------------------------------------------------
// Scratch (device globals)
// ---------------------------------------------------------------------------
__device__ __half g_Ahi[3][(size_t)M_ * DM_];    // A operands (0 reused for attn out)
__device__ __half g_Alo[(size_t)M_ * DM_];       // lo only needed for attn out
__device__ __half g_Whi[4][(size_t)DM_ * DM_];   // W^T [N,K] K-contig
__device__ __half g_Wlo[4][(size_t)DM_ * DM_];
__device__ __half g_Q16[B_ * H_ * S_ * DK_];     // [B,H,S,64], pre-scaled by 1/8
__device__ __half g_K16[B_ * H_ * S_ * DK_];
__device__ __half g_V16[B_ * H_ * S_ * DK_];
__device__ __half g_Vt16[B_ * H_ * DK_ * S_];    // [B,H,64,S]

// ---------------------------------------------------------------------------
// fp32 -> fp16 (hi only)
// ---------------------------------------------------------------------------
__global__ void __launch_bounds__(256) conv_inputs(const float4* __restrict__ s0,
                                                   const float4* __restrict__ s1,
                                                   const float4* __restrict__ s2)
{
    const int which = blockIdx.y;
    const float4* src = (which == 0) ? s0 : (which == 1) ? s1 : s2;
    uint32_t* hi = reinterpret_cast<uint32_t*>(g_Ahi[which]);
    int i = blockIdx.x * 256 + threadIdx.x;
    float4 v = src[i];
    hi[2 * i + 0] = pack2h(v.x, v.y);
    hi[2 * i + 1] = pack2h(v.z, v.w);
}

// ---------------------------------------------------------------------------
// All 4 weights: W [K,N] fp32 -> transposed split fp16 Wt[N,K]
// ---------------------------------------------------------------------------
__global__ void __launch_bounds__(256) conv_weights(const float* __restrict__ W0,
                                                    const float* __restrict__ W1,
                                                    const float* __restrict__ W2,
                                                    const float* __restrict__ W3)
{
    __shared__ float tile[32][33];
    const int which = blockIdx.z;
    const float* W = (which == 0) ? W0 : (which == 1) ? W1 : (which == 2) ? W2 : W3;
    __half* hi = g_Whi[which];
    __half* lo = g_Wlo[which];
    const int bx = blockIdx.x, by = blockIdx.y;
    const int tx = threadIdx.x, ty = threadIdx.y;     // 32 x 8
    #pragma unroll
    for (int j = 0; j < 32; j += 8)
        tile[ty + j][tx] = W[(size_t)(by * 32 + ty + j) * DM_ + bx * 32 + tx];
    __syncthreads();
    #pragma unroll
    for (int j = 0; j < 32; j += 8) {
        float v = tile[tx][ty + j];
        __half h = __float2half(v);
        size_t o = (size_t)(bx * 32 + ty + j) * DM_ + by * 32 + tx;
        hi[o] = h;
        lo[o] = __float2half(v - __half2float(h));
    }
}

// ---------------------------------------------------------------------------
// V [B,H,S,64] fp16 -> V^T [B,H,64,S] fp16
// ---------------------------------------------------------------------------
__global__ void __launch_bounds__(256) transpV()
{
    __shared__ __half th[64][65];
    const int s0 = blockIdx.x * 64, bh = blockIdx.y;
    const int t = threadIdx.x;
    const __half* src = g_V16 + (size_t)bh * S_ * DK_;
    #pragma unroll
    for (int it = 0; it < 2; it++) {
        int r = (t >> 3) + it * 32, c = (t & 7) * 8;
        #pragma unroll
        for (int q = 0; q < 8; q++)
            th[r][c + q] = src[(size_t)(s0 + r) * DK_ + c + q];
    }
    __syncthreads();
    __half* dst = g_Vt16 + (size_t)bh * DK_ * S_;
    #pragma unroll
    for (int it = 0; it < 2; it++) {
        int d = (t >> 3) + it * 32, sc = (t & 7) * 8;
        #pragma unroll
        for (int q = 0; q < 8; q++)
            dst[(size_t)d * S_ + s0 + sc + q] = th[sc + q][d];
    }
}

// ---------------------------------------------------------------------------
// HMMA GEMM (128x128 CTA, BK=64, 2-stage, 2 CTA/SM), fp16.
// Pass schedule: pass0 Ahi*Whi, pass1 Alo*Whi (npass selects).
// mode 0 output pre-scaled by 1/8 (softmax scale folded into Q).
// ---------------------------------------------------------------------------
#define GM 128
#define GN 128
#define GEMM_SMEM (4 * 16384)

__global__ void __launch_bounds__(256, 2) gemm_mma(const __half* __restrict__ Ahi,
                                                   const __half* __restrict__ Alo,
                                                   const __half* __restrict__ Whi,
                                                   const __half* __restrict__ Wlo,
                                                   const float* __restrict__ bias,
                                                   float* __restrict__ Cext,
                                                   int mode, int npass)
{
    extern __shared__ __align__(1024) char smem[];
    const uint32_t sb = smem_u32(smem);
    const int t = threadIdx.x, lane = t & 31, wid = t >> 5;
    const int warpM = wid >> 1, warpN = wid & 1;
    const int row0 = blockIdx.y * GM, col0 = blockIdx.x * GN;
    const int nch = npass * 16;

    float c[2][8][4] = {};

    int lr[4], lc[4];
    #pragma unroll
    for (int j = 0; j < 4; j++) {
        int g = t + j * 256;
        lr[j] = g >> 3;
        lc[j] = (g & 7) * 8;
    }

    auto issue = [&](int i) {
        const int seg = i >> 4, kc = (i & 15) * 64;
        const __half* aseg = (seg == 1) ? Alo : Ahi;
        const __half* wseg = (seg == 2) ? Wlo : Whi;
        const uint32_t ab = sb + (uint32_t)(i & 1) * 32768u;
        const uint32_t bb = ab + 16384u;
        #pragma unroll
        for (int j = 0; j < 4; j++) {
            uint32_t so = sw128((uint32_t)(lr[j] * 128 + lc[j] * 2));
            CP_ASYNC16(ab + so, aseg + (size_t)(row0 + lr[j]) * DM_ + kc + lc[j]);
            CP_ASYNC16(bb + so, wseg + (size_t)(col0 + lr[j]) * DM_ + kc + lc[j]);
        }
    };

    issue(0);
    CP_COMMIT();

    for (int i = 0; i < nch; i++) {
        if (i + 1 < nch) { issue(i + 1); CP_COMMIT(); CP_WAIT(1); }
        else             { CP_WAIT(0); }
        __syncthreads();

        const uint32_t ab = sb + (uint32_t)(i & 1) * 32768u;
        const uint32_t bb = ab + 16384u;

        #pragma unroll
        for (int kst = 0; kst < 4; kst++) {
            const int kk = kst * 16;
            uint32_t a[2][4], b[8][2];
            #pragma unroll
            for (int mt = 0; mt < 2; mt++) {
                int r = warpM * 32 + mt * 16 + (lane & 7) + ((lane >> 3) & 1) * 8;
                int kcol = kk + (lane >> 4) * 8;
                LDSM_X4(a[mt][0], a[mt][1], a[mt][2], a[mt][3],
                        ab + sw128((uint32_t)(r * 128 + kcol * 2)));
            }
            #pragma unroll
            for (int np = 0; np < 4; np++) {
                int r = warpN * 64 + np * 16 + (lane & 7) + (lane >> 4) * 8;
                int kcol = kk + ((lane >> 3) & 1) * 8;
                LDSM_X4(b[2 * np][0], b[2 * np][1], b[2 * np + 1][0], b[2 * np + 1][1],
                        bb + sw128((uint32_t)(r * 128 + kcol * 2)));
            }
            #pragma unroll
            for (int mt = 0; mt < 2; mt++)
                #pragma unroll
                for (int nt = 0; nt < 8; nt++)
                    MMA_F16(c[mt][nt], a[mt], b[nt]);
        }
        __syncthreads();
    }

    __half* D16 = (mode == 0) ? g_Q16 : (mode == 1) ? g_K16 : g_V16;
    const float oscale = (mode == 0) ? 0.125f : 1.0f;   // fold 1/sqrt(dk) into Q
    #pragma unroll
    for (int mt = 0; mt < 2; mt++) {
        #pragma unroll
        for (int half = 0; half < 2; half++) {
            const int rowg = row0 + warpM * 32 + mt * 16 + (lane >> 2) + half * 8;
            const int bb_ = rowg >> 11, ss = rowg & (S_ - 1);
            #pragma unroll
            for (int nt = 0; nt < 8; nt++) {
                const int colg = col0 + warpN * 64 + nt * 8 + (lane & 3) * 2;
                const float v0 = (c[mt][nt][half * 2 + 0] + bias[colg]) * oscale;
                const float v1 = (c[mt][nt][half * 2 + 1] + bias[colg + 1]) * oscale;
                if (mode < 3) {
                    const int h = colg >> 6;
                    size_t off = ((size_t)((bb_ * H_ + h) * S_ + ss)) * DK_ + (colg & 63);
                    *reinterpret_cast<uint32_t*>(D16 + off) = pack2h(v0, v1);
                } else {
                    *reinterpret_cast<float2*>(Cext + (size_t)rowg * DM_ + colg) =
                        make_float2(v0, v1);
                }
            }
        }
    }
}

// ---------------------------------------------------------------------------
// HMMA flash attention, causal, fp16.
// S = Q16·K16 (Q pre-scaled); O += P16·V (single pass). 2 CTAs/SM target.
// Output: fp16 hi/lo into g_Ahi[0]/g_Alo at [B,S,1024].
// ---------------------------------------------------------------------------
#define ATT_SMEM 49152

__global__ void __launch_bounds__(256, 2) attn_mma()
{
    extern __shared__ __align__(1024) char smem[];
    const uint32_t sb = smem_u32(smem);
    const int t = threadIdx.x, lane = t & 31, w = t >> 5;
    const int qb = (int)gridDim.x - 1 - (int)blockIdx.x;   // heavy-first (LPT)
    const int bh = blockIdx.y;
    const int qs = qb * 128;
    const int ntiles = qb * 2 + 2;

    const size_t bo = (size_t)bh * S_ * DK_;
    const __half* Qg = g_Q16 + bo;
    const __half* Kg = g_K16 + bo;
    const __half* Vg = g_Vt16 + (size_t)bh * DK_ * S_;

    const uint32_t QB = sb;

    #pragma unroll
    for (int j = 0; j < 4; j++) {
        int g = t + j * 256, r = g >> 3, c = (g & 7) * 8;
        uint32_t so = sw128((uint32_t)(r * 128 + c * 2));
        CP_ASYNC16(QB + so, Qg + (size_t)(qs + r) * DK_ + c);
    }
    auto issueKV = [&](int i) {
        const int kt = i * 64;
        const uint32_t bB = sb + 16384u + (uint32_t)(i & 1) * 16384u;
        #pragma unroll
        for (int j = 0; j < 2; j++) {
            int g = t + j * 256, r = g >> 3, c = (g & 7) * 8;
            uint32_t so = sw128((uint32_t)(r * 128 + c * 2));
            CP_ASYNC16(bB + so,        Kg + (size_t)(kt + r) * DK_ + c);
            CP_ASYNC16(bB + 8192 + so, Vg + (size_t)r * S_ + kt + c);
        }
    };
    issueKV(0);
    CP_COMMIT();
    if (ntiles > 1) { issueKV(1); CP_COMMIT(); }

    uint32_t qf[4][4];
    float o[8][4] = {};
    float mrow0 = -INFINITY, mrow1 = -INFINITY, lrow0 = 0.f, lrow1 = 0.f;

    for (int i = 0; i < ntiles; i++) {
        if (i + 1 < ntiles) CP_WAIT(1); else CP_WAIT(0);
        __syncthreads();

        if (i == 0) {
            #pragma unroll
            for (int kc = 0; kc < 4; kc++) {
                int r = w * 16 + (lane & 7) + ((lane >> 3) & 1) * 8;
                int kcol = kc * 16 + (lane >> 4) * 8;
                LDSM_X4(qf[kc][0], qf[kc][1], qf[kc][2], qf[kc][3],
                        QB + sw128((uint32_t)(r * 128 + kcol * 2)));
            }
        }

        const int kt = i * 64;
        const uint32_t bB = sb + 16384u + (uint32_t)(i & 1) * 16384u;

        // ---- S = Q K^T (Q pre-scaled by 1/8)
        float s[8][4] = {};
        #pragma unroll
        for (int kc = 0; kc < 4; kc++) {
            const int kk = kc * 16;
            uint32_t bf[8][2];
            #pragma unroll
            for (int np = 0; np < 4; np++) {
                int r = np * 16 + (lane & 7) + (lane >> 4) * 8;
                int kcol = kk + ((lane >> 3) & 1) * 8;
                LDSM_X4(bf[2 * np][0], bf[2 * np][1], bf[2 * np + 1][0], bf[2 * np + 1][1],
                        bB + sw128((uint32_t)(r * 128 + kcol * 2)));
            }
            #pragma unroll
            for (int j = 0; j < 8; j++)
                MMA_F16(s[j], qf[kc], bf[j]);
        }

        // ---- causal mask + online softmax (no scale mul — folded into Q)
        const int r0g = qs + w * 16 + (lane >> 2);
        const bool needmask = (kt + 63 > qs + w * 16);
        float mx0 = -INFINITY, mx1 = -INFINITY;
        if (needmask) {
            #pragma unroll
            for (int j = 0; j < 8; j++) {
                const int cg = kt + j * 8 + (lane & 3) * 2;
                if (cg     > r0g)     s[j][0] = -INFINITY;
                if (cg + 1 > r0g)     s[j][1] = -INFINITY;
                if (cg     > r0g + 8) s[j][2] = -INFINITY;
                if (cg + 1 > r0g + 8) s[j][3] = -INFINITY;
            }
        }
        #pragma unroll
        for (int j = 0; j < 8; j++) {
            mx0 = fmaxf(mx0, fmaxf(s[j][0], s[j][1]));
            mx1 = fmaxf(mx1, fmaxf(s[j][2], s[j][3]));
        }
        mx0 = fmaxf(mx0, __shfl_xor_sync(0xffffffffu, mx0, 1));
        mx0 = fmaxf(mx0, __shfl_xor_sync(0xffffffffu, mx0, 2));
        mx1 = fmaxf(mx1, __shfl_xor_sync(0xffffffffu, mx1, 1));
        mx1 = fmaxf(mx1, __shfl_xor_sync(0xffffffffu, mx1, 2));
        const float mn0 = fmaxf(mrow0, mx0), mn1 = fmaxf(mrow1, mx1);
        const float al0 = __expf(mrow0 - mn0), al1 = __expf(mrow1 - mn1);
        float sum0 = 0.f, sum1 = 0.f;
        #pragma unroll
        for (int j = 0; j < 8; j++) {
            float p0 = __expf(s[j][0] - mn0); s[j][0] = p0; sum0 += p0;
            float p1 = __expf(s[j][1] - mn0); s[j][1] = p1; sum0 += p1;
            float p2 = __expf(s[j][2] - mn1); s[j][2] = p2; sum1 += p2;
            float p3 = __expf(s[j][3] - mn1); s[j][3] = p3; sum1 += p3;
        }
        sum0 += __shfl_xor_sync(0xffffffffu, sum0, 1);
        sum0 += __shfl_xor_sync(0xffffffffu, sum0, 2);
        sum1 += __shfl_xor_sync(0xffffffffu, sum1, 1);
        sum1 += __shfl_xor_sync(0xffffffffu, sum1, 2);
        lrow0 = lrow0 * al0 + sum0;
        lrow1 = lrow1 * al1 + sum1;
        mrow0 = mn0; mrow1 = mn1;
        #pragma unroll
        for (int j = 0; j < 8; j++) {
            o[j][0] *= al0; o[j][1] *= al0;
            o[j][2] *= al1; o[j][3] *= al1;
        }

        // ---- P -> fp16 A-fragments (single precision pass)
        uint32_t pf[4][4];
        #pragma unroll
        for (int kc = 0; kc < 4; kc++) {
            pf[kc][0] = pack2h(s[2 * kc][0],     s[2 * kc][1]);
            pf[kc][1] = pack2h(s[2 * kc][2],     s[2 * kc][3]);
            pf[kc][2] = pack2h(s[2 * kc + 1][0], s[2 * kc + 1][1]);
            pf[kc][3] = pack2h(s[2 * kc + 1][2], s[2 * kc + 1][3]);
        }

        // ---- O += P V (1 pass)
        #pragma unroll
        for (int kc = 0; kc < 4; kc++) {
            const int kk = kc * 16;
            uint32_t vf[8][2];
            #pragma unroll
            for (int np = 0; np < 4; np++) {
                int r = np * 16 + (lane & 7) + (lane >> 4) * 8;
                int kcol = kk + ((lane >> 3) & 1) * 8;
                LDSM_X4(vf[2 * np][0], vf[2 * np][1], vf[2 * np + 1][0], vf[2 * np + 1][1],
                        bB + 8192 + sw128((uint32_t)(r * 128 + kcol * 2)));
            }
            #pragma unroll
            for (int j = 0; j < 8; j++)
                MMA_F16(o[j], pf[kc], vf[j]);
        }

        __syncthreads();
        if (i + 2 < ntiles) { issueKV(i + 2); CP_COMMIT(); }
    }

    const float inv0 = 1.0f / lrow0, inv1 = 1.0f / lrow1;
    const int b = bh >> 4, h = bh & 15;
    const int row0g = qs + w * 16 + (lane >> 2);
    #pragma unroll
    for (int j = 0; j < 8; j++) {
        const int d = j * 8 + (lane & 3) * 2;
        size_t off0 = (size_t)(b * S_ + row0g) * DM_ + h * DK_ + d;
        size_t off1 = off0 + (size_t)8 * DM_;
        uint32_t hiw, low;
        split2h(o[j][0] * inv0, o[j][1] * inv0, hiw, low);
        *reinterpret_cast<uint32_t*>(g_Ahi[0] + off0) = hiw;
        *reinterpret_cast<uint32_t*>(g_Alo + off0) = low;
        split2h(o[j][2] * inv1, o[j][3] * inv1, hiw, low);
        *reinterpret_cast<uint32_t*>(g_Ahi[0] + off1) = hiw;
        *reinterpret_cast<uint32_t*>(g_Alo + off1) = low;
    }
}

// ----------------------------------------------------------------------------
extern "C" void kernel_launch(void* const* d_in, const int* in_sizes, int n_in,
                              void* d_out, int out_size)
{
    const float* query = (const float*)d_in[0];
    const float* key   = (const float*)d_in[1];
    const float* value = (const float*)d_in[2];
    const float* Wq = (const float*)d_in[4];
    const float* bq = (const float*)d_in[5];
    const float* Wk = (const float*)d_in[6];
    const float* bk = (const float*)d_in[7];
    const float* Wv = (const float*)d_in[8];
    const float* bv = (const float*)d_in[9];
    const float* Wo = (const float*)d_in[10];
    const float* bo = (const float*)d_in[11];
    float* out = (float*)d_out;

    cudaFuncSetAttribute(gemm_mma, cudaFuncAttributeMaxDynamicSharedMemorySize, GEMM_SMEM);
    cudaFuncSetAttribute(attn_mma, cudaFuncAttributeMaxDynamicSharedMemorySize, ATT_SMEM);

    const int n4 = M_ * DM_ / 4;
    const dim3 gg(DM_ / GN, M_ / GM);   // (8, 32) = 256 CTAs

    __half *Ahi, *Alo, *Whi, *Wlo;
    cudaGetSymbolAddress((void**)&Ahi, g_Ahi);
    cudaGetSymbolAddress((void**)&Alo, g_Alo);
    cudaGetSymbolAddress((void**)&Whi, g_Whi);
    cudaGetSymbolAddress((void**)&Wlo, g_Wlo);
    const size_t AS = (size_t)M_ * DM_;
    const size_t WS = (size_t)DM_ * DM_;

    conv_inputs<<<dim3(n4 / 256, 3), 256>>>((const float4*)query, (const float4*)key,
                                            (const float4*)value);
    conv_weights<<<dim3(32, 32, 4), dim3(32, 8)>>>(Wq, Wk, Wv, Wo);

    // Q (pre-scaled 1/8), K, V projections: 1 pass each
    gemm_mma<<<gg, 256, GEMM_SMEM>>>(Ahi + 0 * AS, Alo, Whi + 0 * WS, Wlo + 0 * WS, bq, nullptr, 0, 1);
    gemm_mma<<<gg, 256, GEMM_SMEM>>>(Ahi + 1 * AS, Alo, Whi + 1 * WS, Wlo + 1 * WS, bk, nullptr, 1, 1);
    gemm_mma<<<gg, 256, GEMM_SMEM>>>(Ahi + 2 * AS, Alo, Whi + 2 * WS, Wlo + 2 * WS, bv, nullptr, 2, 1);
    transpV<<<dim3(S_ / 64, B_ * H_), 256>>>();
    attn_mma<<<dim3(S_ / 128, B_ * H_), 256, ATT_SMEM>>>();
    // Output projection: 2 passes (Ahi*Whi + Alo*Whi)
    gemm_mma<<<gg, 256, GEMM_SMEM>>>(Ahi + 0 * AS, Alo, Whi + 3 * WS, Wlo + 3 * WS, bo, out, 3, 2);
}

// round 10
// speedup vs baseline: 2.2838x; 1.1139x over previous
#include <cuda_runtime.h>
#include <cuda_fp16.h>
#include <math.h>
#include <cstdint>

#define B_   2
#define S_   2048
#define H_   16
#define DK_  64
#define DM_  1024
#define M_   (B_ * S_)   // 4096

// ---------------------------------------------------------------------------
// PTX helpers — sm_80+ portable (harness PTX target is sm_103 WITHOUT 'a';
// tcgen05/TMEM unavailable; mma.sync/ldmatrix/cp.async are the path).
// ---------------------------------------------------------------------------
__device__ __forceinline__ uint32_t smem_u32(const void* p) {
    uint32_t a;
    asm("{ .reg .u64 t; cvta.to.shared.u64 t, %1; cvt.u32.u64 %0, t; }" : "=r"(a) : "l"(p));
    return a;
}
#define CP_ASYNC16(dst, src) \
    asm volatile("cp.async.cg.shared.global [%0], [%1], 16;" :: "r"(dst), "l"(src))
#define CP_COMMIT() asm volatile("cp.async.commit_group;" ::: "memory")
#define CP_WAIT(n)  asm volatile("cp.async.wait_group %0;" :: "n"(n) : "memory")

#define LDSM_X4(r0, r1, r2, r3, addr) \
    asm volatile("ldmatrix.sync.aligned.m8n8.x4.shared.b16 {%0,%1,%2,%3}, [%4];" \
                 : "=r"(r0), "=r"(r1), "=r"(r2), "=r"(r3) : "r"(addr))

#define MMA_F16(c, a, b) \
    asm volatile("mma.sync.aligned.m16n8k16.row.col.f32.f16.f16.f32 " \
                 "{%0,%1,%2,%3}, {%4,%5,%6,%7}, {%8,%9}, {%0,%1,%2,%3};" \
                 : "+f"((c)[0]), "+f"((c)[1]), "+f"((c)[2]), "+f"((c)[3]) \
                 : "r"((a)[0]), "r"((a)[1]), "r"((a)[2]), "r"((a)[3]), \
                   "r"((b)[0]), "r"((b)[1]))

__device__ __forceinline__ uint32_t sw128(uint32_t off) { return off ^ ((off >> 3) & 0x70); }

__device__ __forceinline__ uint32_t pack2h(float x, float y) {
    __half2 h2 = __halves2half2(__float2half(x), __float2half(y));
    return *reinterpret_cast<uint32_t*>(&h2);
}
__device__ __forceinline__ float ex2f(float x) {           // 2^x, MUFU.EX2
    float r;
    asm("ex2.approx.f32 %0, %1;" : "=f"(r) : "f"(x));
    return r;
}

// Q prescale: 1/sqrt(64) * log2(e)  (softmax runs in log2 domain)
#define QSCALE 0.18033688011112042f

// ---------------------------------------------------------------------------
// Scratch (device globals)
// ---------------------------------------------------------------------------
__device__ __half g_Ahi[3][(size_t)M_ * DM_];    // A operands (0 reused for attn out)
__device__ __half g_Whi[4][(size_t)DM_ * DM_];   // W^T [N,K] K-contig
__device__ __half g_Q16[B_ * H_ * S_ * DK_];     // [B,H,S,64], pre-scaled by QSCALE
__device__ __half g_K16[B_ * H_ * S_ * DK_];
__device__ __half g_V16[B_ * H_ * S_ * DK_];
__device__ __half g_Vt16[B_ * H_ * DK_ * S_];    // [B,H,64,S]

// ---------------------------------------------------------------------------
// fp32 -> fp16
// ---------------------------------------------------------------------------
__global__ void __launch_bounds__(256) conv_inputs(const float4* __restrict__ s0,
                                                   const float4* __restrict__ s1,
                                                   const float4* __restrict__ s2)
{
    const int which = blockIdx.y;
    const float4* src = (which == 0) ? s0 : (which == 1) ? s1 : s2;
    uint32_t* hi = reinterpret_cast<uint32_t*>(g_Ahi[which]);
    int i = blockIdx.x * 256 + threadIdx.x;
    float4 v = src[i];
    hi[2 * i + 0] = pack2h(v.x, v.y);
    hi[2 * i + 1] = pack2h(v.z, v.w);
}

// ---------------------------------------------------------------------------
// All 4 weights: W [K,N] fp32 -> transposed fp16 Wt[N,K]
// ---------------------------------------------------------------------------
__global__ void __launch_bounds__(256) conv_weights(const float* __restrict__ W0,
                                                    const float* __restrict__ W1,
                                                    const float* __restrict__ W2,
                                                    const float* __restrict__ W3)
{
    __shared__ float tile[32][33];
    const int which = blockIdx.z;
    const float* W = (which == 0) ? W0 : (which == 1) ? W1 : (which == 2) ? W2 : W3;
    __half* hi = g_Whi[which];
    const int bx = blockIdx.x, by = blockIdx.y;
    const int tx = threadIdx.x, ty = threadIdx.y;     // 32 x 8
    #pragma unroll
    for (int j = 0; j < 32; j += 8)
        tile[ty + j][tx] = W[(size_t)(by * 32 + ty + j) * DM_ + bx * 32 + tx];
    __syncthreads();
    #pragma unroll
    for (int j = 0; j < 32; j += 8)
        hi[(size_t)(bx * 32 + ty + j) * DM_ + by * 32 + tx] = __float2half(tile[tx][ty + j]);
}

// ---------------------------------------------------------------------------
// V [B,H,S,64] fp16 -> V^T [B,H,64,S] fp16
// ---------------------------------------------------------------------------
__global__ void __launch_bounds__(256) transpV()
{
    __shared__ __half th[64][65];
    const int s0 = blockIdx.x * 64, bh = blockIdx.y;
    const int t = threadIdx.x;
    const __half* src = g_V16 + (size_t)bh * S_ * DK_;
    #pragma unroll
    for (int it = 0; it < 2; it++) {
        int r = (t >> 3) + it * 32, c = (t & 7) * 8;
        #pragma unroll
        for (int q = 0; q < 8; q++)
            th[r][c + q] = src[(size_t)(s0 + r) * DK_ + c + q];
    }
    __syncthreads();
    __half* dst = g_Vt16 + (size_t)bh * DK_ * S_;
    #pragma unroll
    for (int it = 0; it < 2; it++) {
        int d = (t >> 3) + it * 32, sc = (t & 7) * 8;
        #pragma unroll
        for (int q = 0; q < 8; q++)
            dst[(size_t)d * S_ + s0 + sc + q] = th[sc + q][d];
    }
}

// ---------------------------------------------------------------------------
// Single-pass HMMA GEMM core (128x128 CTA, BK=64, 2-stage, 2 CTA/SM), fp16.
// mode 0/1/2 -> fp16 head-split Q/K/V buffers (mode 0 pre-scaled); 3 -> fp32.
// ---------------------------------------------------------------------------
#define GM 128
#define GN 128
#define GEMM_SMEM (4 * 16384)

__device__ __forceinline__ void gemm_core(const __half* __restrict__ A,
                                          const __half* __restrict__ W,
                                          const float* __restrict__ bias,
                                          float* __restrict__ Cext,
                                          __half* __restrict__ D16,
                                          float oscale, int mode, char* smem)
{
    const uint32_t sb = smem_u32(smem);
    const int t = threadIdx.x, lane = t & 31, wid = t >> 5;
    const int warpM = wid >> 1, warpN = wid & 1;
    const int row0 = blockIdx.y * GM, col0 = blockIdx.x * GN;

    float c[2][8][4] = {};

    int lr[4], lc[4];
    #pragma unroll
    for (int j = 0; j < 4; j++) {
        int g = t + j * 256;
        lr[j] = g >> 3;
        lc[j] = (g & 7) * 8;
    }

    auto issue = [&](int i) {
        const int kc = i * 64;
        const uint32_t ab = sb + (uint32_t)(i & 1) * 32768u;
        const uint32_t bb = ab + 16384u;
        #pragma unroll
        for (int j = 0; j < 4; j++) {
            uint32_t so = sw128((uint32_t)(lr[j] * 128 + lc[j] * 2));
            CP_ASYNC16(ab + so, A + (size_t)(row0 + lr[j]) * DM_ + kc + lc[j]);
            CP_ASYNC16(bb + so, W + (size_t)(col0 + lr[j]) * DM_ + kc + lc[j]);
        }
    };

    issue(0);
    CP_COMMIT();

    for (int i = 0; i < 16; i++) {
        if (i + 1 < 16) { issue(i + 1); CP_COMMIT(); CP_WAIT(1); }
        else            { CP_WAIT(0); }
        __syncthreads();

        const uint32_t ab = sb + (uint32_t)(i & 1) * 32768u;
        const uint32_t bb = ab + 16384u;

        #pragma unroll
        for (int kst = 0; kst < 4; kst++) {
            const int kk = kst * 16;
            uint32_t a[2][4], b[8][2];
            #pragma unroll
            for (int mt = 0; mt < 2; mt++) {
                int r = warpM * 32 + mt * 16 + (lane & 7) + ((lane >> 3) & 1) * 8;
                int kcol = kk + (lane >> 4) * 8;
                LDSM_X4(a[mt][0], a[mt][1], a[mt][2], a[mt][3],
                        ab + sw128((uint32_t)(r * 128 + kcol * 2)));
            }
            #pragma unroll
            for (int np = 0; np < 4; np++) {
                int r = warpN * 64 + np * 16 + (lane & 7) + (lane >> 4) * 8;
                int kcol = kk + ((lane >> 3) & 1) * 8;
                LDSM_X4(b[2 * np][0], b[2 * np][1], b[2 * np + 1][0], b[2 * np + 1][1],
                        bb + sw128((uint32_t)(r * 128 + kcol * 2)));
            }
            #pragma unroll
            for (int mt = 0; mt < 2; mt++)
                #pragma unroll
                for (int nt = 0; nt < 8; nt++)
                    MMA_F16(c[mt][nt], a[mt], b[nt]);
        }
        __syncthreads();
    }

    #pragma unroll
    for (int mt = 0; mt < 2; mt++) {
        #pragma unroll
        for (int half = 0; half < 2; half++) {
            const int rowg = row0 + warpM * 32 + mt * 16 + (lane >> 2) + half * 8;
            const int bb_ = rowg >> 11, ss = rowg & (S_ - 1);
            #pragma unroll
            for (int nt = 0; nt < 8; nt++) {
                const int colg = col0 + warpN * 64 + nt * 8 + (lane & 3) * 2;
                const float v0 = (c[mt][nt][half * 2 + 0] + bias[colg]) * oscale;
                const float v1 = (c[mt][nt][half * 2 + 1] + bias[colg + 1]) * oscale;
                if (mode < 3) {
                    const int h = colg >> 6;
                    size_t off = ((size_t)((bb_ * H_ + h) * S_ + ss)) * DK_ + (colg & 63);
                    *reinterpret_cast<uint32_t*>(D16 + off) = pack2h(v0, v1);
                } else {
                    *reinterpret_cast<float2*>(Cext + (size_t)rowg * DM_ + colg) =
                        make_float2(v0, v1);
                }
            }
        }
    }
}

// Merged Q/K/V projections: blockIdx.z selects the projection.
__global__ void __launch_bounds__(256, 2) gemm_qkv(const float* __restrict__ bq,
                                                   const float* __restrict__ bk,
                                                   const float* __restrict__ bv)
{
    extern __shared__ __align__(1024) char smem[];
    const int z = blockIdx.z;
    const float* bias = (z == 0) ? bq : (z == 1) ? bk : bv;
    __half* D16 = (z == 0) ? g_Q16 : (z == 1) ? g_K16 : g_V16;
    const float oscale = (z == 0) ? QSCALE : 1.0f;
    gemm_core(g_Ahi[z], g_Whi[z], bias, nullptr, D16, oscale, z, smem);
}

// Output projection (single pass, fp32 out).
__global__ void __launch_bounds__(256, 2) gemm_out(const float* __restrict__ bo,
                                                   float* __restrict__ out)
{
    extern __shared__ __align__(1024) char smem[];
    gemm_core(g_Ahi[0], g_Whi[3], bo, out, nullptr, 1.0f, 3, smem);
}

// ---------------------------------------------------------------------------
// HMMA flash attention, causal, fp16, log2-domain softmax.
// S = Q16·K16 (Q pre-scaled by QSCALE); P = ex2(S - m); O += P16·V.
// Output: fp16 into g_Ahi[0] at [B,S,1024].
// ---------------------------------------------------------------------------
#define ATT_SMEM 49152

__global__ void __launch_bounds__(256, 2) attn_mma()
{
    extern __shared__ __align__(1024) char smem[];
    const uint32_t sb = smem_u32(smem);
    const int t = threadIdx.x, lane = t & 31, w = t >> 5;
    const int qb = (int)gridDim.x - 1 - (int)blockIdx.x;   // heavy-first (LPT)
    const int bh = blockIdx.y;
    const int qs = qb * 128;
    const int ntiles = qb * 2 + 2;

    const size_t bo = (size_t)bh * S_ * DK_;
    const __half* Qg = g_Q16 + bo;
    const __half* Kg = g_K16 + bo;
    const __half* Vg = g_Vt16 + (size_t)bh * DK_ * S_;

    const uint32_t QB = sb;

    #pragma unroll
    for (int j = 0; j < 4; j++) {
        int g = t + j * 256, r = g >> 3, c = (g & 7) * 8;
        uint32_t so = sw128((uint32_t)(r * 128 + c * 2));
        CP_ASYNC16(QB + so, Qg + (size_t)(qs + r) * DK_ + c);
    }
    auto issueKV = [&](int i) {
        const int kt = i * 64;
        const uint32_t bB = sb + 16384u + (uint32_t)(i & 1) * 16384u;
        #pragma unroll
        for (int j = 0; j < 2; j++) {
            int g = t + j * 256, r = g >> 3, c = (g & 7) * 8;
            uint32_t so = sw128((uint32_t)(r * 128 + c * 2));
            CP_ASYNC16(bB + so,        Kg + (size_t)(kt + r) * DK_ + c);
            CP_ASYNC16(bB + 8192 + so, Vg + (size_t)r * S_ + kt + c);
        }
    };
    issueKV(0);
    CP_COMMIT();
    if (ntiles > 1) { issueKV(1); CP_COMMIT(); }

    uint32_t qf[4][4];
    float o[8][4] = {};
    float mrow0 = -INFINITY, mrow1 = -INFINITY, lrow0 = 0.f, lrow1 = 0.f;

    for (int i = 0; i < ntiles; i++) {
        if (i + 1 < ntiles) CP_WAIT(1); else CP_WAIT(0);
        __syncthreads();

        if (i == 0) {
            #pragma unroll
            for (int kc = 0; kc < 4; kc++) {
                int r = w * 16 + (lane & 7) + ((lane >> 3) & 1) * 8;
                int kcol = kc * 16 + (lane >> 4) * 8;
                LDSM_X4(qf[kc][0], qf[kc][1], qf[kc][2], qf[kc][3],
                        QB + sw128((uint32_t)(r * 128 + kcol * 2)));
            }
        }

        const int kt = i * 64;
        const uint32_t bB = sb + 16384u + (uint32_t)(i & 1) * 16384u;

        // ---- S = Q K^T (already in log2 domain)
        float s[8][4] = {};
        #pragma unroll
        for (int kc = 0; kc < 4; kc++) {
            const int kk = kc * 16;
            uint32_t bf[8][2];
            #pragma unroll
            for (int np = 0; np < 4; np++) {
                int r = np * 16 + (lane & 7) + (lane >> 4) * 8;
                int kcol = kk + ((lane >> 3) & 1) * 8;
                LDSM_X4(bf[2 * np][0], bf[2 * np][1], bf[2 * np + 1][0], bf[2 * np + 1][1],
                        bB + sw128((uint32_t)(r * 128 + kcol * 2)));
            }
            #pragma unroll
            for (int j = 0; j < 8; j++)
                MMA_F16(s[j], qf[kc], bf[j]);
        }

        // ---- causal mask + online softmax (ex2 domain)
        const int r0g = qs + w * 16 + (lane >> 2);
        const bool needmask = (kt + 63 > qs + w * 16);
        float mx0 = -INFINITY, mx1 = -INFINITY;
        if (needmask) {
            #pragma unroll
            for (int j = 0; j < 8; j++) {
                const int cg = kt + j * 8 + (lane & 3) * 2;
                if (cg     > r0g)     s[j][0] = -INFINITY;
                if (cg + 1 > r0g)     s[j][1] = -INFINITY;
                if (cg     > r0g + 8) s[j][2] = -INFINITY;
                if (cg + 1 > r0g + 8) s[j][3] = -INFINITY;
            }
        }
        #pragma unroll
        for (int j = 0; j < 8; j++) {
            mx0 = fmaxf(mx0, fmaxf(s[j][0], s[j][1]));
            mx1 = fmaxf(mx1, fmaxf(s[j][2], s[j][3]));
        }
        mx0 = fmaxf(mx0, __shfl_xor_sync(0xffffffffu, mx0, 1));
        mx0 = fmaxf(mx0, __shfl_xor_sync(0xffffffffu, mx0, 2));
        mx1 = fmaxf(mx1, __shfl_xor_sync(0xffffffffu, mx1, 1));
        mx1 = fmaxf(mx1, __shfl_xor_sync(0xffffffffu, mx1, 2));
        const float mn0 = fmaxf(mrow0, mx0), mn1 = fmaxf(mrow1, mx1);
        const float al0 = ex2f(mrow0 - mn0), al1 = ex2f(mrow1 - mn1);
        float sum0 = 0.f, sum1 = 0.f;
        #pragma unroll
        for (int j = 0; j < 8; j++) {
            float p0 = ex2f(s[j][0] - mn0); s[j][0] = p0; sum0 += p0;
            float p1 = ex2f(s[j][1] - mn0); s[j][1] = p1; sum0 += p1;
            float p2 = ex2f(s[j][2] - mn1); s[j][2] = p2; sum1 += p2;
            float p3 = ex2f(s[j][3] - mn1); s[j][3] = p3; sum1 += p3;
        }
        sum0 += __shfl_xor_sync(0xffffffffu, sum0, 1);
        sum0 += __shfl_xor_sync(0xffffffffu, sum0, 2);
        sum1 += __shfl_xor_sync(0xffffffffu, sum1, 1);
        sum1 += __shfl_xor_sync(0xffffffffu, sum1, 2);
        lrow0 = lrow0 * al0 + sum0;
        lrow1 = lrow1 * al1 + sum1;
        mrow0 = mn0; mrow1 = mn1;
        if (!(al0 == 1.0f && al1 == 1.0f)) {        // skip when maxes stable
            #pragma unroll
            for (int j = 0; j < 8; j++) {
                o[j][0] *= al0; o[j][1] *= al0;
                o[j][2] *= al1; o[j][3] *= al1;
            }
        }

        // ---- P -> fp16 A-fragments
        uint32_t pf[4][4];
        #pragma unroll
        for (int kc = 0; kc < 4; kc++) {
            pf[kc][0] = pack2h(s[2 * kc][0],     s[2 * kc][1]);
            pf[kc][1] = pack2h(s[2 * kc][2],     s[2 * kc][3]);
            pf[kc][2] = pack2h(s[2 * kc + 1][0], s[2 * kc + 1][1]);
            pf[kc][3] = pack2h(s[2 * kc + 1][2], s[2 * kc + 1][3]);
        }

        // ---- O += P V
        #pragma unroll
        for (int kc = 0; kc < 4; kc++) {
            const int kk = kc * 16;
            uint32_t vf[8][2];
            #pragma unroll
            for (int np = 0; np < 4; np++) {
                int r = np * 16 + (lane & 7) + (lane >> 4) * 8;
                int kcol = kk + ((lane >> 3) & 1) * 8;
                LDSM_X4(vf[2 * np][0], vf[2 * np][1], vf[2 * np + 1][0], vf[2 * np + 1][1],
                        bB + 8192 + sw128((uint32_t)(r * 128 + kcol * 2)));
            }
            #pragma unroll
            for (int j = 0; j < 8; j++)
                MMA_F16(o[j], pf[kc], vf[j]);
        }

        __syncthreads();
        if (i + 2 < ntiles) { issueKV(i + 2); CP_COMMIT(); }
    }

    // ---- epilogue: normalize, write fp16 to [B,S,1024]
    const float inv0 = 1.0f / lrow0, inv1 = 1.0f / lrow1;
    const int b = bh >> 4, h = bh & 15;
    const int row0g = qs + w * 16 + (lane >> 2);
    #pragma unroll
    for (int j = 0; j < 8; j++) {
        const int d = j * 8 + (lane & 3) * 2;
        size_t off0 = (size_t)(b * S_ + row0g) * DM_ + h * DK_ + d;
        size_t off1 = off0 + (size_t)8 * DM_;
        *reinterpret_cast<uint32_t*>(g_Ahi[0] + off0) = pack2h(o[j][0] * inv0, o[j][1] * inv0);
        *reinterpret_cast<uint32_t*>(g_Ahi[0] + off1) = pack2h(o[j][2] * inv1, o[j][3] * inv1);
    }
}

// ----------------------------------------------------------------------------
extern "C" void kernel_launch(void* const* d_in, const int* in_sizes, int n_in,
                              void* d_out, int out_size)
{
    const float* query = (const float*)d_in[0];
    const float* key   = (const float*)d_in[1];
    const float* value = (const float*)d_in[2];
    const float* Wq = (const float*)d_in[4];
    const float* bq = (const float*)d_in[5];
    const float* Wk = (const float*)d_in[6];
    const float* bk = (const float*)d_in[7];
    const float* Wv = (const float*)d_in[8];
    const float* bv = (const float*)d_in[9];
    const float* Wo = (const float*)d_in[10];
    const float* bo = (const float*)d_in[11];
    float* out = (float*)d_out;

    cudaFuncSetAttribute(gemm_qkv, cudaFuncAttributeMaxDynamicSharedMemorySize, GEMM_SMEM);
    cudaFuncSetAttribute(gemm_out, cudaFuncAttributeMaxDynamicSharedMemorySize, GEMM_SMEM);
    cudaFuncSetAttribute(attn_mma, cudaFuncAttributeMaxDynamicSharedMemorySize, ATT_SMEM);

    const int n4 = M_ * DM_ / 4;

    conv_inputs<<<dim3(n4 / 256, 3), 256>>>((const float4*)query, (const float4*)key,
                                            (const float4*)value);
    conv_weights<<<dim3(32, 32, 4), dim3(32, 8)>>>(Wq, Wk, Wv, Wo);

    gemm_qkv<<<dim3(DM_ / GN, M_ / GM, 3), 256, GEMM_SMEM>>>(bq, bk, bv);
    transpV<<<dim3(S_ / 64, B_ * H_), 256>>>();
    attn_mma<<<dim3(S_ / 128, B_ * H_), 256, ATT_SMEM>>>();
    gemm_out<<<dim3(DM_ / GN, M_ / GM), 256, GEMM_SMEM>>>(bo, out);
}

// round 11
// speedup vs baseline: 2.5462x; 1.1149x over previous
#include <cuda_runtime.h>
#include <cuda_fp16.h>
#include <math.h>
#include <cstdint>

#define B_   2
#define S_   2048
#define H_   16
#define DK_  64
#define DM_  1024
#define M_   (B_ * S_)   // 4096

// ---------------------------------------------------------------------------
// PTX helpers — sm_80+ portable (harness PTX target is sm_103 WITHOUT 'a';
// tcgen05/TMEM unavailable; mma.sync/ldmatrix/cp.async are the path).
// ---------------------------------------------------------------------------
__device__ __forceinline__ uint32_t smem_u32(const void* p) {
    uint32_t a;
    asm("{ .reg .u64 t; cvta.to.shared.u64 t, %1; cvt.u32.u64 %0, t; }" : "=r"(a) : "l"(p));
    return a;
}
#define CP_ASYNC16(dst, src) \
    asm volatile("cp.async.cg.shared.global [%0], [%1], 16;" :: "r"(dst), "l"(src))
#define CP_COMMIT() asm volatile("cp.async.commit_group;" ::: "memory")
#define CP_WAIT(n)  asm volatile("cp.async.wait_group %0;" :: "n"(n) : "memory")

#define LDSM_X4(r0, r1, r2, r3, addr) \
    asm volatile("ldmatrix.sync.aligned.m8n8.x4.shared.b16 {%0,%1,%2,%3}, [%4];" \
                 : "=r"(r0), "=r"(r1), "=r"(r2), "=r"(r3) : "r"(addr))

#define MMA_F16(c, a, b) \
    asm volatile("mma.sync.aligned.m16n8k16.row.col.f32.f16.f16.f32 " \
                 "{%0,%1,%2,%3}, {%4,%5,%6,%7}, {%8,%9}, {%0,%1,%2,%3};" \
                 : "+f"((c)[0]), "+f"((c)[1]), "+f"((c)[2]), "+f"((c)[3]) \
                 : "r"((a)[0]), "r"((a)[1]), "r"((a)[2]), "r"((a)[3]), \
                   "r"((b)[0]), "r"((b)[1]))

__device__ __forceinline__ uint32_t sw128(uint32_t off) { return off ^ ((off >> 3) & 0x70); }

__device__ __forceinline__ uint32_t pack2h(float x, float y) {
    __half2 h2 = __halves2half2(__float2half(x), __float2half(y));
    return *reinterpret_cast<uint32_t*>(&h2);
}
__device__ __forceinline__ float ex2f(float x) {           // 2^x, MUFU.EX2
    float r;
    asm("ex2.approx.f32 %0, %1;" : "=f"(r) : "f"(x));
    return r;
}
__device__ __forceinline__ uint32_t ex2h2(__half2 x) {     // 2^x on fp16x2
    uint32_t xi = *reinterpret_cast<uint32_t*>(&x), r;
    asm("ex2.approx.f16x2 %0, %1;" : "=r"(r) : "r"(xi));
    return r;
}

// Q prescale: 1/sqrt(64) * log2(e)  (softmax runs in log2 domain)
#define QSCALE 0.18033688011112042f

// ---------------------------------------------------------------------------
// Scratch (device globals)
// ---------------------------------------------------------------------------
__device__ __half g_Ahi[3][(size_t)M_ * DM_];    // A operands (0 reused for attn out)
__device__ __half g_Whi[4][(size_t)DM_ * DM_];   // W^T [N,K] K-contig
__device__ __half g_Q16[B_ * H_ * S_ * DK_];     // [B,H,S,64], pre-scaled by QSCALE
__device__ __half g_K16[B_ * H_ * S_ * DK_];
__device__ __half g_V16[B_ * H_ * S_ * DK_];
__device__ __half g_Vt16[B_ * H_ * DK_ * S_];    // [B,H,64,S]

// ---------------------------------------------------------------------------
// fp32 -> fp16
// ---------------------------------------------------------------------------
__global__ void __launch_bounds__(256) conv_inputs(const float4* __restrict__ s0,
                                                   const float4* __restrict__ s1,
                                                   const float4* __restrict__ s2)
{
    const int which = blockIdx.y;
    const float4* src = (which == 0) ? s0 : (which == 1) ? s1 : s2;
    uint32_t* hi = reinterpret_cast<uint32_t*>(g_Ahi[which]);
    int i = blockIdx.x * 256 + threadIdx.x;
    float4 v = src[i];
    hi[2 * i + 0] = pack2h(v.x, v.y);
    hi[2 * i + 1] = pack2h(v.z, v.w);
}

// ---------------------------------------------------------------------------
// All 4 weights: W [K,N] fp32 -> transposed fp16 Wt[N,K]
// ---------------------------------------------------------------------------
__global__ void __launch_bounds__(256) conv_weights(const float* __restrict__ W0,
                                                    const float* __restrict__ W1,
                                                    const float* __restrict__ W2,
                                                    const float* __restrict__ W3)
{
    __shared__ float tile[32][33];
    const int which = blockIdx.z;
    const float* W = (which == 0) ? W0 : (which == 1) ? W1 : (which == 2) ? W2 : W3;
    __half* hi = g_Whi[which];
    const int bx = blockIdx.x, by = blockIdx.y;
    const int tx = threadIdx.x, ty = threadIdx.y;     // 32 x 8
    #pragma unroll
    for (int j = 0; j < 32; j += 8)
        tile[ty + j][tx] = W[(size_t)(by * 32 + ty + j) * DM_ + bx * 32 + tx];
    __syncthreads();
    #pragma unroll
    for (int j = 0; j < 32; j += 8)
        hi[(size_t)(bx * 32 + ty + j) * DM_ + by * 32 + tx] = __float2half(tile[tx][ty + j]);
}

// ---------------------------------------------------------------------------
// V [B,H,S,64] fp16 -> V^T [B,H,64,S] fp16  (vectorized gmem)
// ---------------------------------------------------------------------------
__global__ void __launch_bounds__(256) transpV()
{
    __shared__ __half th[64][65];
    const int s0 = blockIdx.x * 64, bh = blockIdx.y;
    const int t = threadIdx.x;
    const __half* src = g_V16 + (size_t)bh * S_ * DK_;
    #pragma unroll
    for (int it = 0; it < 2; it++) {
        int r = (t >> 3) + it * 32, c = (t & 7) * 8;
        uint4 v = *reinterpret_cast<const uint4*>(src + (size_t)(s0 + r) * DK_ + c);
        const __half* hv = reinterpret_cast<const __half*>(&v);
        #pragma unroll
        for (int q = 0; q < 8; q++) th[r][c + q] = hv[q];
    }
    __syncthreads();
    __half* dst = g_Vt16 + (size_t)bh * DK_ * S_;
    #pragma unroll
    for (int it = 0; it < 2; it++) {
        int d = (t >> 3) + it * 32, sc = (t & 7) * 8;
        uint4 v;
        uint32_t* vw = reinterpret_cast<uint32_t*>(&v);
        #pragma unroll
        for (int q = 0; q < 4; q++) {
            __half2 h2 = __halves2half2(th[sc + 2 * q][d], th[sc + 2 * q + 1][d]);
            vw[q] = *reinterpret_cast<uint32_t*>(&h2);
        }
        *reinterpret_cast<uint4*>(dst + (size_t)d * S_ + s0 + sc) = v;
    }
}

// ---------------------------------------------------------------------------
// Single-pass HMMA GEMM core (128x128 CTA, BK=64, 2-stage, 2 CTA/SM), fp16.
// ---------------------------------------------------------------------------
#define GM 128
#define GN 128
#define GEMM_SMEM (4 * 16384)

__device__ __forceinline__ void gemm_core(const __half* __restrict__ A,
                                          const __half* __restrict__ W,
                                          const float* __restrict__ bias,
                                          float* __restrict__ Cext,
                                          __half* __restrict__ D16,
                                          float oscale, int mode, char* smem)
{
    const uint32_t sb = smem_u32(smem);
    const int t = threadIdx.x, lane = t & 31, wid = t >> 5;
    const int warpM = wid >> 1, warpN = wid & 1;
    const int row0 = blockIdx.y * GM, col0 = blockIdx.x * GN;

    float c[2][8][4] = {};

    int lr[4], lc[4];
    #pragma unroll
    for (int j = 0; j < 4; j++) {
        int g = t + j * 256;
        lr[j] = g >> 3;
        lc[j] = (g & 7) * 8;
    }

    auto issue = [&](int i) {
        const int kc = i * 64;
        const uint32_t ab = sb + (uint32_t)(i & 1) * 32768u;
        const uint32_t bb = ab + 16384u;
        #pragma unroll
        for (int j = 0; j < 4; j++) {
            uint32_t so = sw128((uint32_t)(lr[j] * 128 + lc[j] * 2));
            CP_ASYNC16(ab + so, A + (size_t)(row0 + lr[j]) * DM_ + kc + lc[j]);
            CP_ASYNC16(bb + so, W + (size_t)(col0 + lr[j]) * DM_ + kc + lc[j]);
        }
    };

    issue(0);
    CP_COMMIT();

    for (int i = 0; i < 16; i++) {
        if (i + 1 < 16) { issue(i + 1); CP_COMMIT(); CP_WAIT(1); }
        else            { CP_WAIT(0); }
        __syncthreads();

        const uint32_t ab = sb + (uint32_t)(i & 1) * 32768u;
        const uint32_t bb = ab + 16384u;

        #pragma unroll
        for (int kst = 0; kst < 4; kst++) {
            const int kk = kst * 16;
            uint32_t a[2][4], b[8][2];
            #pragma unroll
            for (int mt = 0; mt < 2; mt++) {
                int r = warpM * 32 + mt * 16 + (lane & 7) + ((lane >> 3) & 1) * 8;
                int kcol = kk + (lane >> 4) * 8;
                LDSM_X4(a[mt][0], a[mt][1], a[mt][2], a[mt][3],
                        ab + sw128((uint32_t)(r * 128 + kcol * 2)));
            }
            #pragma unroll
            for (int np = 0; np < 4; np++) {
                int r = warpN * 64 + np * 16 + (lane & 7) + (lane >> 4) * 8;
                int kcol = kk + ((lane >> 3) & 1) * 8;
                LDSM_X4(b[2 * np][0], b[2 * np][1], b[2 * np + 1][0], b[2 * np + 1][1],
                        bb + sw128((uint32_t)(r * 128 + kcol * 2)));
            }
            #pragma unroll
            for (int mt = 0; mt < 2; mt++)
                #pragma unroll
                for (int nt = 0; nt < 8; nt++)
                    MMA_F16(c[mt][nt], a[mt], b[nt]);
        }
        __syncthreads();
    }

    #pragma unroll
    for (int mt = 0; mt < 2; mt++) {
        #pragma unroll
        for (int half = 0; half < 2; half++) {
            const int rowg = row0 + warpM * 32 + mt * 16 + (lane >> 2) + half * 8;
            const int bb_ = rowg >> 11, ss = rowg & (S_ - 1);
            #pragma unroll
            for (int nt = 0; nt < 8; nt++) {
                const int colg = col0 + warpN * 64 + nt * 8 + (lane & 3) * 2;
                const float v0 = (c[mt][nt][half * 2 + 0] + bias[colg]) * oscale;
                const float v1 = (c[mt][nt][half * 2 + 1] + bias[colg + 1]) * oscale;
                if (mode < 3) {
                    const int h = colg >> 6;
                    size_t off = ((size_t)((bb_ * H_ + h) * S_ + ss)) * DK_ + (colg & 63);
                    *reinterpret_cast<uint32_t*>(D16 + off) = pack2h(v0, v1);
                } else {
                    *reinterpret_cast<float2*>(Cext + (size_t)rowg * DM_ + colg) =
                        make_float2(v0, v1);
                }
            }
        }
    }
}

__global__ void __launch_bounds__(256, 2) gemm_qkv(const float* __restrict__ bq,
                                                   const float* __restrict__ bk,
                                                   const float* __restrict__ bv)
{
    extern __shared__ __align__(1024) char smem[];
    const int z = blockIdx.z;
    const float* bias = (z == 0) ? bq : (z == 1) ? bk : bv;
    __half* D16 = (z == 0) ? g_Q16 : (z == 1) ? g_K16 : g_V16;
    const float oscale = (z == 0) ? QSCALE : 1.0f;
    gemm_core(g_Ahi[z], g_Whi[z], bias, nullptr, D16, oscale, z, smem);
}

__global__ void __launch_bounds__(256, 2) gemm_out(const float* __restrict__ bo,
                                                   float* __restrict__ out)
{
    extern __shared__ __align__(1024) char smem[];
    gemm_core(g_Ahi[0], g_Whi[3], bo, out, nullptr, 1.0f, 3, smem);
}

// ---------------------------------------------------------------------------
// HMMA flash attention, causal, fp16, log2-domain half2 softmax.
// S = Q16·K16; P = ex2.f16x2(S - m); O += P·V; l = P·ones via MMA.
// Output: fp16 into g_Ahi[0] at [B,S,1024].
// ---------------------------------------------------------------------------
#define ATT_SMEM 49152

__global__ void __launch_bounds__(256, 2) attn_mma()
{
    extern __shared__ __align__(1024) char smem[];
    const uint32_t sb = smem_u32(smem);
    const int t = threadIdx.x, lane = t & 31, w = t >> 5;
    const int qb = (int)gridDim.x - 1 - (int)blockIdx.x;   // heavy-first (LPT)
    const int bh = blockIdx.y;
    const int qs = qb * 128;
    const int ntiles = qb * 2 + 2;

    const size_t bo = (size_t)bh * S_ * DK_;
    const __half* Qg = g_Q16 + bo;
    const __half* Kg = g_K16 + bo;
    const __half* Vg = g_Vt16 + (size_t)bh * DK_ * S_;

    const uint32_t QB = sb;

    #pragma unroll
    for (int j = 0; j < 4; j++) {
        int g = t + j * 256, r = g >> 3, c = (g & 7) * 8;
        uint32_t so = sw128((uint32_t)(r * 128 + c * 2));
        CP_ASYNC16(QB + so, Qg + (size_t)(qs + r) * DK_ + c);
    }
    auto issueKV = [&](int i) {
        const int kt = i * 64;
        const uint32_t bB = sb + 16384u + (uint32_t)(i & 1) * 16384u;
        #pragma unroll
        for (int j = 0; j < 2; j++) {
            int g = t + j * 256, r = g >> 3, c = (g & 7) * 8;
            uint32_t so = sw128((uint32_t)(r * 128 + c * 2));
            CP_ASYNC16(bB + so,        Kg + (size_t)(kt + r) * DK_ + c);
            CP_ASYNC16(bB + 8192 + so, Vg + (size_t)r * S_ + kt + c);
        }
    };
    issueKV(0);
    CP_COMMIT();
    if (ntiles > 1) { issueKV(1); CP_COMMIT(); }

    uint32_t qf[4][4];
    float o[8][4] = {};
    float ol[4] = {};                            // l accumulator (ones-MMA)
    float mrow0 = -INFINITY, mrow1 = -INFINITY;
    const uint32_t onesf[2] = {0x3C003C00u, 0x3C003C00u};   // all-ones b-fragment

    for (int i = 0; i < ntiles; i++) {
        if (i + 1 < ntiles) CP_WAIT(1); else CP_WAIT(0);
        __syncthreads();

        if (i == 0) {
            #pragma unroll
            for (int kc = 0; kc < 4; kc++) {
                int r = w * 16 + (lane & 7) + ((lane >> 3) & 1) * 8;
                int kcol = kc * 16 + (lane >> 4) * 8;
                LDSM_X4(qf[kc][0], qf[kc][1], qf[kc][2], qf[kc][3],
                        QB + sw128((uint32_t)(r * 128 + kcol * 2)));
            }
        }

        const int kt = i * 64;
        const uint32_t bB = sb + 16384u + (uint32_t)(i & 1) * 16384u;

        // ---- S = Q K^T (log2 domain)
        float s[8][4] = {};
        #pragma unroll
        for (int kc = 0; kc < 4; kc++) {
            const int kk = kc * 16;
            uint32_t bf[8][2];
            #pragma unroll
            for (int np = 0; np < 4; np++) {
                int r = np * 16 + (lane & 7) + (lane >> 4) * 8;
                int kcol = kk + ((lane >> 3) & 1) * 8;
                LDSM_X4(bf[2 * np][0], bf[2 * np][1], bf[2 * np + 1][0], bf[2 * np + 1][1],
                        bB + sw128((uint32_t)(r * 128 + kcol * 2)));
            }
            #pragma unroll
            for (int j = 0; j < 8; j++)
                MMA_F16(s[j], qf[kc], bf[j]);
        }

        // ---- causal mask (f32)
        const int r0g = qs + w * 16 + (lane >> 2);
        if (kt + 63 > qs + w * 16) {
            #pragma unroll
            for (int j = 0; j < 8; j++) {
                const int cg = kt + j * 8 + (lane & 3) * 2;
                if (cg     > r0g)     s[j][0] = -INFINITY;
                if (cg + 1 > r0g)     s[j][1] = -INFINITY;
                if (cg     > r0g + 8) s[j][2] = -INFINITY;
                if (cg + 1 > r0g + 8) s[j][3] = -INFINITY;
            }
        }

        // ---- pack to half2 (row0 pairs / row1 pairs)
        __half2 hp0[8], hp1[8];
        #pragma unroll
        for (int j = 0; j < 8; j++) {
            hp0[j] = __floats2half2_rn(s[j][0], s[j][1]);
            hp1[j] = __floats2half2_rn(s[j][2], s[j][3]);
        }

        // ---- row max (fp16 tree + f32 quad shuffles)
        __half2 hm0 = hp0[0], hm1 = hp1[0];
        #pragma unroll
        for (int j = 1; j < 8; j++) {
            hm0 = __hmax2(hm0, hp0[j]);
            hm1 = __hmax2(hm1, hp1[j]);
        }
        float mx0 = fmaxf(__low2float(hm0), __high2float(hm0));
        float mx1 = fmaxf(__low2float(hm1), __high2float(hm1));
        mx0 = fmaxf(mx0, __shfl_xor_sync(0xffffffffu, mx0, 1));
        mx0 = fmaxf(mx0, __shfl_xor_sync(0xffffffffu, mx0, 2));
        mx1 = fmaxf(mx1, __shfl_xor_sync(0xffffffffu, mx1, 1));
        mx1 = fmaxf(mx1, __shfl_xor_sync(0xffffffffu, mx1, 2));
        const float mn0 = fmaxf(mrow0, mx0), mn1 = fmaxf(mrow1, mx1);
        const float al0 = ex2f(mrow0 - mn0), al1 = ex2f(mrow1 - mn1);
        mrow0 = mn0; mrow1 = mn1;

        // ---- P = ex2(S - m) directly into fp16 fragments
        const __half2 mn0h = __float2half2_rn(mn0);
        const __half2 mn1h = __float2half2_rn(mn1);
        uint32_t pf[4][4];
        #pragma unroll
        for (int kc = 0; kc < 4; kc++) {
            pf[kc][0] = ex2h2(__hsub2(hp0[2 * kc],     mn0h));
            pf[kc][1] = ex2h2(__hsub2(hp1[2 * kc],     mn1h));
            pf[kc][2] = ex2h2(__hsub2(hp0[2 * kc + 1], mn0h));
            pf[kc][3] = ex2h2(__hsub2(hp1[2 * kc + 1], mn1h));
        }

        // ---- rescale O and l (skip when maxes unchanged)
        if (!(al0 == 1.0f && al1 == 1.0f)) {
            #pragma unroll
            for (int j = 0; j < 8; j++) {
                o[j][0] *= al0; o[j][1] *= al0;
                o[j][2] *= al1; o[j][3] *= al1;
            }
            ol[0] *= al0; ol[1] *= al0;
            ol[2] *= al1; ol[3] *= al1;
        }

        // ---- O += P V ; l += P · 1
        #pragma unroll
        for (int kc = 0; kc < 4; kc++) {
            const int kk = kc * 16;
            uint32_t vf[8][2];
            #pragma unroll
            for (int np = 0; np < 4; np++) {
                int r = np * 16 + (lane & 7) + (lane >> 4) * 8;
                int kcol = kk + ((lane >> 3) & 1) * 8;
                LDSM_X4(vf[2 * np][0], vf[2 * np][1], vf[2 * np + 1][0], vf[2 * np + 1][1],
                        bB + 8192 + sw128((uint32_t)(r * 128 + kcol * 2)));
            }
            #pragma unroll
            for (int j = 0; j < 8; j++)
                MMA_F16(o[j], pf[kc], vf[j]);
            MMA_F16(ol, pf[kc], onesf);
        }

        __syncthreads();
        if (i + 2 < ntiles) { issueKV(i + 2); CP_COMMIT(); }
    }

    // ---- epilogue: normalize, write fp16 to [B,S,1024]
    const float inv0 = 1.0f / ol[0], inv1 = 1.0f / ol[2];
    const int b = bh >> 4, h = bh & 15;
    const int row0g = qs + w * 16 + (lane >> 2);
    #pragma unroll
    for (int j = 0; j < 8; j++) {
        const int d = j * 8 + (lane & 3) * 2;
        size_t off0 = (size_t)(b * S_ + row0g) * DM_ + h * DK_ + d;
        size_t off1 = off0 + (size_t)8 * DM_;
        *reinterpret_cast<uint32_t*>(g_Ahi[0] + off0) = pack2h(o[j][0] * inv0, o[j][1] * inv0);
        *reinterpret_cast<uint32_t*>(g_Ahi[0] + off1) = pack2h(o[j][2] * inv1, o[j][3] * inv1);
    }
}

// ----------------------------------------------------------------------------
extern "C" void kernel_launch(void* const* d_in, const int* in_sizes, int n_in,
                              void* d_out, int out_size)
{
    const float* query = (const float*)d_in[0];
    const float* key   = (const float*)d_in[1];
    const float* value = (const float*)d_in[2];
    const float* Wq = (const float*)d_in[4];
    const float* bq = (const float*)d_in[5];
    const float* Wk = (const float*)d_in[6];
    const float* bk = (const float*)d_in[7];
    const float* Wv = (const float*)d_in[8];
    const float* bv = (const float*)d_in[9];
    const float* Wo = (const float*)d_in[10];
    const float* bo = (const float*)d_in[11];
    float* out = (float*)d_out;

    cudaFuncSetAttribute(gemm_qkv, cudaFuncAttributeMaxDynamicSharedMemorySize, GEMM_SMEM);
    cudaFuncSetAttribute(gemm_out, cudaFuncAttributeMaxDynamicSharedMemorySize, GEMM_SMEM);
    cudaFuncSetAttribute(attn_mma, cudaFuncAttributeMaxDynamicSharedMemorySize, ATT_SMEM);

    const int n4 = M_ * DM_ / 4;

    conv_inputs<<<dim3(n4 / 256, 3), 256>>>((const float4*)query, (const float4*)key,
                                            (const float4*)value);
    conv_weights<<<dim3(32, 32, 4), dim3(32, 8)>>>(Wq, Wk, Wv, Wo);

    gemm_qkv<<<dim3(DM_ / GN, M_ / GM, 3), 256, GEMM_SMEM>>>(bq, bk, bv);
    transpV<<<dim3(S_ / 64, B_ * H_), 256>>>();
    attn_mma<<<dim3(S_ / 128, B_ * H_), 256, ATT_SMEM>>>();
    gemm_out<<<dim3(DM_ / GN, M_ / GM), 256, GEMM_SMEM>>>(bo, out);
}

// round 12
// speedup vs baseline: 2.7303x; 1.0723x over previous
#include <cuda_runtime.h>
#include <cuda_fp16.h>
#include <math.h>
#include <cstdint>

#define B_   2
#define S_   2048
#define H_   16
#define DK_  64
#define DM_  1024
#define M_   (B_ * S_)   // 4096

// ---------------------------------------------------------------------------
// PTX helpers — sm_80+ portable (harness PTX target is sm_103 WITHOUT 'a';
// tcgen05/TMEM unavailable; mma.sync/ldmatrix/cp.async are the path).
// ---------------------------------------------------------------------------
__device__ __forceinline__ uint32_t smem_u32(const void* p) {
    uint32_t a;
    asm("{ .reg .u64 t; cvta.to.shared.u64 t, %1; cvt.u32.u64 %0, t; }" : "=r"(a) : "l"(p));
    return a;
}
#define CP_ASYNC16(dst, src) \
    asm volatile("cp.async.cg.shared.global [%0], [%1], 16;" :: "r"(dst), "l"(src))
#define CP_COMMIT() asm volatile("cp.async.commit_group;" ::: "memory")
#define CP_WAIT(n)  asm volatile("cp.async.wait_group %0;" :: "n"(n) : "memory")

#define LDSM_X4(r0, r1, r2, r3, addr) \
    asm volatile("ldmatrix.sync.aligned.m8n8.x4.shared.b16 {%0,%1,%2,%3}, [%4];" \
                 : "=r"(r0), "=r"(r1), "=r"(r2), "=r"(r3) : "r"(addr))

#define LDSM_X4_T(r0, r1, r2, r3, addr) \
    asm volatile("ldmatrix.sync.aligned.m8n8.x4.trans.shared.b16 {%0,%1,%2,%3}, [%4];" \
                 : "=r"(r0), "=r"(r1), "=r"(r2), "=r"(r3) : "r"(addr))

#define MMA_F16(c, a, b) \
    asm volatile("mma.sync.aligned.m16n8k16.row.col.f32.f16.f16.f32 " \
                 "{%0,%1,%2,%3}, {%4,%5,%6,%7}, {%8,%9}, {%0,%1,%2,%3};" \
                 : "+f"((c)[0]), "+f"((c)[1]), "+f"((c)[2]), "+f"((c)[3]) \
                 : "r"((a)[0]), "r"((a)[1]), "r"((a)[2]), "r"((a)[3]), \
                   "r"((b)[0]), "r"((b)[1]))

__device__ __forceinline__ uint32_t sw128(uint32_t off) { return off ^ ((off >> 3) & 0x70); }

__device__ __forceinline__ uint32_t pack2h(float x, float y) {
    __half2 h2 = __halves2half2(__float2half(x), __float2half(y));
    return *reinterpret_cast<uint32_t*>(&h2);
}
__device__ __forceinline__ float ex2f(float x) {
    float r;
    asm("ex2.approx.f32 %0, %1;" : "=f"(r) : "f"(x));
    return r;
}
__device__ __forceinline__ uint32_t ex2h2(__half2 x) {
    uint32_t xi = *reinterpret_cast<uint32_t*>(&x), r;
    asm("ex2.approx.f16x2 %0, %1;" : "=r"(r) : "r"(xi));
    return r;
}

// Q prescale: 1/sqrt(64) * log2(e)  (softmax runs in log2 domain)
#define QSCALE 0.18033688011112042f

// ---------------------------------------------------------------------------
// Scratch (device globals)
// ---------------------------------------------------------------------------
__device__ __half g_Ahi[3][(size_t)M_ * DM_];    // A operands (0 reused for attn out)
__device__ __half g_Whi[4][(size_t)DM_ * DM_];   // W^T [N,K] K-contig
__device__ __half g_Q16[B_ * H_ * S_ * DK_];     // [B,H,S,64], pre-scaled by QSCALE
__device__ __half g_K16[B_ * H_ * S_ * DK_];
__device__ __half g_V16[B_ * H_ * S_ * DK_];

// ---------------------------------------------------------------------------
// fp32 -> fp16
// ---------------------------------------------------------------------------
__global__ void __launch_bounds__(256) conv_inputs(const float4* __restrict__ s0,
                                                   const float4* __restrict__ s1,
                                                   const float4* __restrict__ s2)
{
    const int which = blockIdx.y;
    const float4* src = (which == 0) ? s0 : (which == 1) ? s1 : s2;
    uint32_t* hi = reinterpret_cast<uint32_t*>(g_Ahi[which]);
    int i = blockIdx.x * 256 + threadIdx.x;
    float4 v = src[i];
    hi[2 * i + 0] = pack2h(v.x, v.y);
    hi[2 * i + 1] = pack2h(v.z, v.w);
}

// ---------------------------------------------------------------------------
// All 4 weights: W [K,N] fp32 -> transposed fp16 Wt[N,K]
// ---------------------------------------------------------------------------
__global__ void __launch_bounds__(256) conv_weights(const float* __restrict__ W0,
                                                    const float* __restrict__ W1,
                                                    const float* __restrict__ W2,
                                                    const float* __restrict__ W3)
{
    __shared__ float tile[32][33];
    const int which = blockIdx.z;
    const float* W = (which == 0) ? W0 : (which == 1) ? W1 : (which == 2) ? W2 : W3;
    __half* hi = g_Whi[which];
    const int bx = blockIdx.x, by = blockIdx.y;
    const int tx = threadIdx.x, ty = threadIdx.y;     // 32 x 8
    #pragma unroll
    for (int j = 0; j < 32; j += 8)
        tile[ty + j][tx] = W[(size_t)(by * 32 + ty + j) * DM_ + bx * 32 + tx];
    __syncthreads();
    #pragma unroll
    for (int j = 0; j < 32; j += 8)
        hi[(size_t)(bx * 32 + ty + j) * DM_ + by * 32 + tx] = __float2half(tile[tx][ty + j]);
}

// ---------------------------------------------------------------------------
// Single-pass HMMA GEMM core (128x128 CTA, BK=64, 2-stage, 2 CTA/SM), fp16.
// ---------------------------------------------------------------------------
#define GM 128
#define GN 128
#define GEMM_SMEM (4 * 16384)

__device__ __forceinline__ void gemm_core(const __half* __restrict__ A,
                                          const __half* __restrict__ W,
                                          const float* __restrict__ bias,
                                          float* __restrict__ Cext,
                                          __half* __restrict__ D16,
                                          float oscale, int mode, char* smem)
{
    const uint32_t sb = smem_u32(smem);
    const int t = threadIdx.x, lane = t & 31, wid = t >> 5;
    const int warpM = wid >> 1, warpN = wid & 1;
    const int row0 = blockIdx.y * GM, col0 = blockIdx.x * GN;

    float c[2][8][4] = {};

    int lr[4], lc[4];
    #pragma unroll
    for (int j = 0; j < 4; j++) {
        int g = t + j * 256;
        lr[j] = g >> 3;
        lc[j] = (g & 7) * 8;
    }

    auto issue = [&](int i) {
        const int kc = i * 64;
        const uint32_t ab = sb + (uint32_t)(i & 1) * 32768u;
        const uint32_t bb = ab + 16384u;
        #pragma unroll
        for (int j = 0; j < 4; j++) {
            uint32_t so = sw128((uint32_t)(lr[j] * 128 + lc[j] * 2));
            CP_ASYNC16(ab + so, A + (size_t)(row0 + lr[j]) * DM_ + kc + lc[j]);
            CP_ASYNC16(bb + so, W + (size_t)(col0 + lr[j]) * DM_ + kc + lc[j]);
        }
    };

    issue(0);
    CP_COMMIT();

    for (int i = 0; i < 16; i++) {
        if (i + 1 < 16) { issue(i + 1); CP_COMMIT(); CP_WAIT(1); }
        else            { CP_WAIT(0); }
        __syncthreads();

        const uint32_t ab = sb + (uint32_t)(i & 1) * 32768u;
        const uint32_t bb = ab + 16384u;

        #pragma unroll
        for (int kst = 0; kst < 4; kst++) {
            const int kk = kst * 16;
            uint32_t a[2][4], b[8][2];
            #pragma unroll
            for (int mt = 0; mt < 2; mt++) {
                int r = warpM * 32 + mt * 16 + (lane & 7) + ((lane >> 3) & 1) * 8;
                int kcol = kk + (lane >> 4) * 8;
                LDSM_X4(a[mt][0], a[mt][1], a[mt][2], a[mt][3],
                        ab + sw128((uint32_t)(r * 128 + kcol * 2)));
            }
            #pragma unroll
            for (int np = 0; np < 4; np++) {
                int r = warpN * 64 + np * 16 + (lane & 7) + (lane >> 4) * 8;
                int kcol = kk + ((lane >> 3) & 1) * 8;
                LDSM_X4(b[2 * np][0], b[2 * np][1], b[2 * np + 1][0], b[2 * np + 1][1],
                        bb + sw128((uint32_t)(r * 128 + kcol * 2)));
            }
            #pragma unroll
            for (int mt = 0; mt < 2; mt++)
                #pragma unroll
                for (int nt = 0; nt < 8; nt++)
                    MMA_F16(c[mt][nt], a[mt], b[nt]);
        }
        __syncthreads();
    }

    #pragma unroll
    for (int mt = 0; mt < 2; mt++) {
        #pragma unroll
        for (int half = 0; half < 2; half++) {
            const int rowg = row0 + warpM * 32 + mt * 16 + (lane >> 2) + half * 8;
            const int bb_ = rowg >> 11, ss = rowg & (S_ - 1);
            #pragma unroll
            for (int nt = 0; nt < 8; nt++) {
                const int colg = col0 + warpN * 64 + nt * 8 + (lane & 3) * 2;
                const float v0 = (c[mt][nt][half * 2 + 0] + bias[colg]) * oscale;
                const float v1 = (c[mt][nt][half * 2 + 1] + bias[colg + 1]) * oscale;
                if (mode < 3) {
                    const int h = colg >> 6;
                    size_t off = ((size_t)((bb_ * H_ + h) * S_ + ss)) * DK_ + (colg & 63);
                    *reinterpret_cast<uint32_t*>(D16 + off) = pack2h(v0, v1);
                } else {
                    *reinterpret_cast<float2*>(Cext + (size_t)rowg * DM_ + colg) =
                        make_float2(v0, v1);
                }
            }
        }
    }
}

__global__ void __launch_bounds__(256, 2) gemm_qkv(const float* __restrict__ bq,
                                                   const float* __restrict__ bk,
                                                   const float* __restrict__ bv)
{
    extern __shared__ __align__(1024) char smem[];
    const int z = blockIdx.z;
    const float* bias = (z == 0) ? bq : (z == 1) ? bk : bv;
    __half* D16 = (z == 0) ? g_Q16 : (z == 1) ? g_K16 : g_V16;
    const float oscale = (z == 0) ? QSCALE : 1.0f;
    gemm_core(g_Ahi[z], g_Whi[z], bias, nullptr, D16, oscale, z, smem);
}

__global__ void __launch_bounds__(256, 2) gemm_out(const float* __restrict__ bo,
                                                   float* __restrict__ out)
{
    extern __shared__ __align__(1024) char smem[];
    gemm_core(g_Ahi[0], g_Whi[3], bo, out, nullptr, 1.0f, 3, smem);
}

// ---------------------------------------------------------------------------
// HMMA flash attention, causal, fp16, log2-domain half2 softmax.
// Bq=64, 128 threads (4 warps x 16 rows), 64-key tiles, 4 CTAs/SM.
// V consumed via ldmatrix.trans directly from K-layout tiles (no V^T pass).
// S = Q16·K16; P = ex2.f16x2(S - m); O += P·V; l = P·ones via MMA.
// Output: fp16 into g_Ahi[0] at [B,S,1024].
// ---------------------------------------------------------------------------
#define ATT_SMEM (8192 + 2 * 16384)   // Q tile + 2 KV stages = 40 KB

__global__ void __launch_bounds__(128, 4) attn_mma()
{
    extern __shared__ __align__(1024) char smem[];
    const uint32_t sb = smem_u32(smem);
    const int t = threadIdx.x, lane = t & 31, w = t >> 5;   // 4 warps
    const int qb = (int)gridDim.x - 1 - (int)blockIdx.x;    // heavy-first (LPT)
    const int bh = blockIdx.y;
    const int qs = qb * 64;
    const int ntiles = qb + 1;

    const size_t bo = (size_t)bh * S_ * DK_;
    const __half* Qg = g_Q16 + bo;
    const __half* Kg = g_K16 + bo;
    const __half* Vg = g_V16 + bo;

    const uint32_t QB = sb;

    // Q tile: 64x64 fp16 = 8KB, 512 chunks of 16B, 128 threads x 4
    #pragma unroll
    for (int j = 0; j < 4; j++) {
        int g = t + j * 128, r = g >> 3, c = (g & 7) * 8;
        uint32_t so = sw128((uint32_t)(r * 128 + c * 2));
        CP_ASYNC16(QB + so, Qg + (size_t)(qs + r) * DK_ + c);
    }
    auto issueKV = [&](int i) {
        const int kt = i * 64;
        const uint32_t bB = sb + 8192u + (uint32_t)(i & 1) * 16384u;
        #pragma unroll
        for (int j = 0; j < 4; j++) {
            int g = t + j * 128, r = g >> 3, c = (g & 7) * 8;
            uint32_t so = sw128((uint32_t)(r * 128 + c * 2));
            CP_ASYNC16(bB + so,        Kg + (size_t)(kt + r) * DK_ + c);
            CP_ASYNC16(bB + 8192 + so, Vg + (size_t)(kt + r) * DK_ + c);
        }
    };
    issueKV(0);
    CP_COMMIT();
    if (ntiles > 1) { issueKV(1); CP_COMMIT(); }

    uint32_t qf[4][4];
    float o[8][4] = {};
    float ol[4] = {};                            // l accumulator (ones-MMA)
    float mrow0 = -INFINITY, mrow1 = -INFINITY;
    const uint32_t onesf[2] = {0x3C003C00u, 0x3C003C00u};

    for (int i = 0; i < ntiles; i++) {
        if (i + 1 < ntiles) CP_WAIT(1); else CP_WAIT(0);
        __syncthreads();

        if (i == 0) {
            #pragma unroll
            for (int kc = 0; kc < 4; kc++) {
                int r = w * 16 + (lane & 7) + ((lane >> 3) & 1) * 8;
                int kcol = kc * 16 + (lane >> 4) * 8;
                LDSM_X4(qf[kc][0], qf[kc][1], qf[kc][2], qf[kc][3],
                        QB + sw128((uint32_t)(r * 128 + kcol * 2)));
            }
        }

        const int kt = i * 64;
        const uint32_t bB = sb + 8192u + (uint32_t)(i & 1) * 16384u;

        // ---- S = Q K^T (log2 domain)
        float s[8][4] = {};
        #pragma unroll
        for (int kc = 0; kc < 4; kc++) {
            const int kk = kc * 16;
            uint32_t bf[8][2];
            #pragma unroll
            for (int np = 0; np < 4; np++) {
                int r = np * 16 + (lane & 7) + (lane >> 4) * 8;
                int kcol = kk + ((lane >> 3) & 1) * 8;
                LDSM_X4(bf[2 * np][0], bf[2 * np][1], bf[2 * np + 1][0], bf[2 * np + 1][1],
                        bB + sw128((uint32_t)(r * 128 + kcol * 2)));
            }
            #pragma unroll
            for (int j = 0; j < 8; j++)
                MMA_F16(s[j], qf[kc], bf[j]);
        }

        // ---- causal mask (f32)
        const int r0g = qs + w * 16 + (lane >> 2);
        if (kt + 63 > qs + w * 16) {
            #pragma unroll
            for (int j = 0; j < 8; j++) {
                const int cg = kt + j * 8 + (lane & 3) * 2;
                if (cg     > r0g)     s[j][0] = -INFINITY;
                if (cg + 1 > r0g)     s[j][1] = -INFINITY;
                if (cg     > r0g + 8) s[j][2] = -INFINITY;
                if (cg + 1 > r0g + 8) s[j][3] = -INFINITY;
            }
        }

        // ---- pack to half2
        __half2 hp0[8], hp1[8];
        #pragma unroll
        for (int j = 0; j < 8; j++) {
            hp0[j] = __floats2half2_rn(s[j][0], s[j][1]);
            hp1[j] = __floats2half2_rn(s[j][2], s[j][3]);
        }

        // ---- row max
        __half2 hm0 = hp0[0], hm1 = hp1[0];
        #pragma unroll
        for (int j = 1; j < 8; j++) {
            hm0 = __hmax2(hm0, hp0[j]);
            hm1 = __hmax2(hm1, hp1[j]);
        }
        float mx0 = fmaxf(__low2float(hm0), __high2float(hm0));
        float mx1 = fmaxf(__low2float(hm1), __high2float(hm1));
        mx0 = fmaxf(mx0, __shfl_xor_sync(0xffffffffu, mx0, 1));
        mx0 = fmaxf(mx0, __shfl_xor_sync(0xffffffffu, mx0, 2));
        mx1 = fmaxf(mx1, __shfl_xor_sync(0xffffffffu, mx1, 1));
        mx1 = fmaxf(mx1, __shfl_xor_sync(0xffffffffu, mx1, 2));
        const float mn0 = fmaxf(mrow0, mx0), mn1 = fmaxf(mrow1, mx1);
        const float al0 = ex2f(mrow0 - mn0), al1 = ex2f(mrow1 - mn1);
        mrow0 = mn0; mrow1 = mn1;

        // ---- P = ex2(S - m) into fp16 fragments
        const __half2 mn0h = __float2half2_rn(mn0);
        const __half2 mn1h = __float2half2_rn(mn1);
        uint32_t pf[4][4];
        #pragma unroll
        for (int kc = 0; kc < 4; kc++) {
            pf[kc][0] = ex2h2(__hsub2(hp0[2 * kc],     mn0h));
            pf[kc][1] = ex2h2(__hsub2(hp1[2 * kc],     mn1h));
            pf[kc][2] = ex2h2(__hsub2(hp0[2 * kc + 1], mn0h));
            pf[kc][3] = ex2h2(__hsub2(hp1[2 * kc + 1], mn1h));
        }

        // ---- rescale O and l (skip when maxes unchanged)
        if (!(al0 == 1.0f && al1 == 1.0f)) {
            #pragma unroll
            for (int j = 0; j < 8; j++) {
                o[j][0] *= al0; o[j][1] *= al0;
                o[j][2] *= al1; o[j][3] *= al1;
            }
            ol[0] *= al0; ol[1] *= al0;
            ol[2] *= al1; ol[3] *= al1;
        }

        // ---- O += P V (ldmatrix.trans: B[k=key][n=d] from [key][d] tile); l += P·1
        #pragma unroll
        for (int kc = 0; kc < 4; kc++) {
            const int kk = kc * 16;
            uint32_t vf[8][2];
            #pragma unroll
            for (int np = 0; np < 4; np++) {
                int r = kk + (lane & 7) + ((lane >> 3) & 1) * 8;    // key rows
                int dcol = np * 16 + (lane >> 4) * 8;               // d columns
                LDSM_X4_T(vf[2 * np][0], vf[2 * np][1], vf[2 * np + 1][0], vf[2 * np + 1][1],
                          bB + 8192 + sw128((uint32_t)(r * 128 + dcol * 2)));
            }
            #pragma unroll
            for (int j = 0; j < 8; j++)
                MMA_F16(o[j], pf[kc], vf[j]);
            MMA_F16(ol, pf[kc], onesf);
        }

        __syncthreads();
        if (i + 2 < ntiles) { issueKV(i + 2); CP_COMMIT(); }
    }

    // ---- epilogue: normalize, write fp16 to [B,S,1024]
    const float inv0 = 1.0f / ol[0], inv1 = 1.0f / ol[2];
    const int b = bh >> 4, h = bh & 15;
    const int row0g = qs + w * 16 + (lane >> 2);
    #pragma unroll
    for (int j = 0; j < 8; j++) {
        const int d = j * 8 + (lane & 3) * 2;
        size_t off0 = (size_t)(b * S_ + row0g) * DM_ + h * DK_ + d;
        size_t off1 = off0 + (size_t)8 * DM_;
        *reinterpret_cast<uint32_t*>(g_Ahi[0] + off0) = pack2h(o[j][0] * inv0, o[j][1] * inv0);
        *reinterpret_cast<uint32_t*>(g_Ahi[0] + off1) = pack2h(o[j][2] * inv1, o[j][3] * inv1);
    }
}

// ----------------------------------------------------------------------------
extern "C" void kernel_launch(void* const* d_in, const int* in_sizes, int n_in,
                              void* d_out, int out_size)
{
    const float* query = (const float*)d_in[0];
    const float* key   = (const float*)d_in[1];
    const float* value = (const float*)d_in[2];
    const float* Wq = (const float*)d_in[4];
    const float* bq = (const float*)d_in[5];
    const float* Wk = (const float*)d_in[6];
    const float* bk = (const float*)d_in[7];
    const float* Wv = (const float*)d_in[8];
    const float* bv = (const float*)d_in[9];
    const float* Wo = (const float*)d_in[10];
    const float* bo = (const float*)d_in[11];
    float* out = (float*)d_out;

    cudaFuncSetAttribute(gemm_qkv, cudaFuncAttributeMaxDynamicSharedMemorySize, GEMM_SMEM);
    cudaFuncSetAttribute(gemm_out, cudaFuncAttributeMaxDynamicSharedMemorySize, GEMM_SMEM);
    cudaFuncSetAttribute(attn_mma, cudaFuncAttributeMaxDynamicSharedMemorySize, ATT_SMEM);

    const int n4 = M_ * DM_ / 4;

    conv_inputs<<<dim3(n4 / 256, 3), 256>>>((const float4*)query, (const float4*)key,
                                            (const float4*)value);
    conv_weights<<<dim3(32, 32, 4), dim3(32, 8)>>>(Wq, Wk, Wv, Wo);

    gemm_qkv<<<dim3(DM_ / GN, M_ / GM, 3), 256, GEMM_SMEM>>>(bq, bk, bv);
    attn_mma<<<dim3(S_ / 64, B_ * H_), 128, ATT_SMEM>>>();
    gemm_out<<<dim3(DM_ / GN, M_ / GM), 256, GEMM_SMEM>>>(bo, out);
}

// round 13
// speedup vs baseline: 2.7890x; 1.0215x over previous
#include <cuda_runtime.h>
#include <cuda_fp16.h>
#include <math.h>
#include <cstdint>

#define B_   2
#define S_   2048
#define H_   16
#define DK_  64
#define DM_  1024
#define M_   (B_ * S_)   // 4096

// ---------------------------------------------------------------------------
// PTX helpers — sm_80+ portable (harness PTX target is sm_103 WITHOUT 'a';
// tcgen05/TMEM unavailable; mma.sync/ldmatrix/cp.async are the path).
// ---------------------------------------------------------------------------
__device__ __forceinline__ uint32_t smem_u32(const void* p) {
    uint32_t a;
    asm("{ .reg .u64 t; cvta.to.shared.u64 t, %1; cvt.u32.u64 %0, t; }" : "=r"(a) : "l"(p));
    return a;
}
#define CP_ASYNC16(dst, src) \
    asm volatile("cp.async.cg.shared.global [%0], [%1], 16;" :: "r"(dst), "l"(src))
#define CP_COMMIT() asm volatile("cp.async.commit_group;" ::: "memory")
#define CP_WAIT(n)  asm volatile("cp.async.wait_group %0;" :: "n"(n) : "memory")

#define LDSM_X4(r0, r1, r2, r3, addr) \
    asm volatile("ldmatrix.sync.aligned.m8n8.x4.shared.b16 {%0,%1,%2,%3}, [%4];" \
                 : "=r"(r0), "=r"(r1), "=r"(r2), "=r"(r3) : "r"(addr))

#define LDSM_X4_T(r0, r1, r2, r3, addr) \
    asm volatile("ldmatrix.sync.aligned.m8n8.x4.trans.shared.b16 {%0,%1,%2,%3}, [%4];" \
                 : "=r"(r0), "=r"(r1), "=r"(r2), "=r"(r3) : "r"(addr))

#define MMA_F16(c, a, b) \
    asm volatile("mma.sync.aligned.m16n8k16.row.col.f32.f16.f16.f32 " \
                 "{%0,%1,%2,%3}, {%4,%5,%6,%7}, {%8,%9}, {%0,%1,%2,%3};" \
                 : "+f"((c)[0]), "+f"((c)[1]), "+f"((c)[2]), "+f"((c)[3]) \
                 : "r"((a)[0]), "r"((a)[1]), "r"((a)[2]), "r"((a)[3]), \
                   "r"((b)[0]), "r"((b)[1]))

__device__ __forceinline__ uint32_t sw128(uint32_t off) { return off ^ ((off >> 3) & 0x70); }

__device__ __forceinline__ uint32_t pack2h(float x, float y) {
    __half2 h2 = __halves2half2(__float2half(x), __float2half(y));
    return *reinterpret_cast<uint32_t*>(&h2);
}
__device__ __forceinline__ float ex2f(float x) {
    float r;
    asm("ex2.approx.f32 %0, %1;" : "=f"(r) : "f"(x));
    return r;
}
__device__ __forceinline__ uint32_t ex2h2(__half2 x) {
    uint32_t xi = *reinterpret_cast<uint32_t*>(&x), r;
    asm("ex2.approx.f16x2 %0, %1;" : "=r"(r) : "r"(xi));
    return r;
}

// Q prescale: 1/sqrt(64) * log2(e)  (softmax runs in log2 domain)
#define QSCALE 0.18033688011112042f

// ---------------------------------------------------------------------------
// Scratch (device globals)
// ---------------------------------------------------------------------------
__device__ __half g_Ahi[3][(size_t)M_ * DM_];    // A operands (0 reused for attn out)
__device__ __half g_Whi[4][(size_t)DM_ * DM_];   // W^T [N,K] K-contig
__device__ __half g_Q16[B_ * H_ * S_ * DK_];     // [B,H,S,64], pre-scaled by QSCALE
__device__ __half g_K16[B_ * H_ * S_ * DK_];
__device__ __half g_V16[B_ * H_ * S_ * DK_];

// ---------------------------------------------------------------------------
// fp32 -> fp16
// ---------------------------------------------------------------------------
__global__ void __launch_bounds__(256) conv_inputs(const float4* __restrict__ s0,
                                                   const float4* __restrict__ s1,
                                                   const float4* __restrict__ s2)
{
    const int which = blockIdx.y;
    const float4* src = (which == 0) ? s0 : (which == 1) ? s1 : s2;
    uint32_t* hi = reinterpret_cast<uint32_t*>(g_Ahi[which]);
    int i = blockIdx.x * 256 + threadIdx.x;
    float4 v = src[i];
    hi[2 * i + 0] = pack2h(v.x, v.y);
    hi[2 * i + 1] = pack2h(v.z, v.w);
}

// ---------------------------------------------------------------------------
// All 4 weights: W [K,N] fp32 -> transposed fp16 Wt[N,K]
// ---------------------------------------------------------------------------
__global__ void __launch_bounds__(256) conv_weights(const float* __restrict__ W0,
                                                    const float* __restrict__ W1,
                                                    const float* __restrict__ W2,
                                                    const float* __restrict__ W3)
{
    __shared__ float tile[32][33];
    const int which = blockIdx.z;
    const float* W = (which == 0) ? W0 : (which == 1) ? W1 : (which == 2) ? W2 : W3;
    __half* hi = g_Whi[which];
    const int bx = blockIdx.x, by = blockIdx.y;
    const int tx = threadIdx.x, ty = threadIdx.y;     // 32 x 8
    #pragma unroll
    for (int j = 0; j < 32; j += 8)
        tile[ty + j][tx] = W[(size_t)(by * 32 + ty + j) * DM_ + bx * 32 + tx];
    __syncthreads();
    #pragma unroll
    for (int j = 0; j < 32; j += 8)
        hi[(size_t)(bx * 32 + ty + j) * DM_ + by * 32 + tx] = __float2half(tile[tx][ty + j]);
}

// ---------------------------------------------------------------------------
// Single-pass HMMA GEMM core (128x128 CTA, BK=64, 2-stage, 2 CTA/SM), fp16.
// ---------------------------------------------------------------------------
#define GM 128
#define GN 128
#define GEMM_SMEM (4 * 16384)

__device__ __forceinline__ void gemm_core(const __half* __restrict__ A,
                                          const __half* __restrict__ W,
                                          const float* __restrict__ bias,
                                          float* __restrict__ Cext,
                                          __half* __restrict__ D16,
                                          float oscale, int mode, char* smem)
{
    const uint32_t sb = smem_u32(smem);
    const int t = threadIdx.x, lane = t & 31, wid = t >> 5;
    const int warpM = wid >> 1, warpN = wid & 1;
    const int row0 = blockIdx.y * GM, col0 = blockIdx.x * GN;

    float c[2][8][4] = {};

    int lr[4], lc[4];
    #pragma unroll
    for (int j = 0; j < 4; j++) {
        int g = t + j * 256;
        lr[j] = g >> 3;
        lc[j] = (g & 7) * 8;
    }

    auto issue = [&](int i) {
        const int kc = i * 64;
        const uint32_t ab = sb + (uint32_t)(i & 1) * 32768u;
        const uint32_t bb = ab + 16384u;
        #pragma unroll
        for (int j = 0; j < 4; j++) {
            uint32_t so = sw128((uint32_t)(lr[j] * 128 + lc[j] * 2));
            CP_ASYNC16(ab + so, A + (size_t)(row0 + lr[j]) * DM_ + kc + lc[j]);
            CP_ASYNC16(bb + so, W + (size_t)(col0 + lr[j]) * DM_ + kc + lc[j]);
        }
    };

    issue(0);
    CP_COMMIT();

    for (int i = 0; i < 16; i++) {
        if (i + 1 < 16) { issue(i + 1); CP_COMMIT(); CP_WAIT(1); }
        else            { CP_WAIT(0); }
        __syncthreads();

        const uint32_t ab = sb + (uint32_t)(i & 1) * 32768u;
        const uint32_t bb = ab + 16384u;

        #pragma unroll
        for (int kst = 0; kst < 4; kst++) {
            const int kk = kst * 16;
            uint32_t a[2][4], b[8][2];
            #pragma unroll
            for (int mt = 0; mt < 2; mt++) {
                int r = warpM * 32 + mt * 16 + (lane & 7) + ((lane >> 3) & 1) * 8;
                int kcol = kk + (lane >> 4) * 8;
                LDSM_X4(a[mt][0], a[mt][1], a[mt][2], a[mt][3],
                        ab + sw128((uint32_t)(r * 128 + kcol * 2)));
            }
            #pragma unroll
            for (int np = 0; np < 4; np++) {
                int r = warpN * 64 + np * 16 + (lane & 7) + (lane >> 4) * 8;
                int kcol = kk + ((lane >> 3) & 1) * 8;
                LDSM_X4(b[2 * np][0], b[2 * np][1], b[2 * np + 1][0], b[2 * np + 1][1],
                        bb + sw128((uint32_t)(r * 128 + kcol * 2)));
            }
            #pragma unroll
            for (int mt = 0; mt < 2; mt++)
                #pragma unroll
                for (int nt = 0; nt < 8; nt++)
                    MMA_F16(c[mt][nt], a[mt], b[nt]);
        }
        __syncthreads();
    }

    #pragma unroll
    for (int mt = 0; mt < 2; mt++) {
        #pragma unroll
        for (int half = 0; half < 2; half++) {
            const int rowg = row0 + warpM * 32 + mt * 16 + (lane >> 2) + half * 8;
            const int bb_ = rowg >> 11, ss = rowg & (S_ - 1);
            #pragma unroll
            for (int nt = 0; nt < 8; nt++) {
                const int colg = col0 + warpN * 64 + nt * 8 + (lane & 3) * 2;
                const float v0 = (c[mt][nt][half * 2 + 0] + bias[colg]) * oscale;
                const float v1 = (c[mt][nt][half * 2 + 1] + bias[colg + 1]) * oscale;
                if (mode < 3) {
                    const int h = colg >> 6;
                    size_t off = ((size_t)((bb_ * H_ + h) * S_ + ss)) * DK_ + (colg & 63);
                    *reinterpret_cast<uint32_t*>(D16 + off) = pack2h(v0, v1);
                } else {
                    *reinterpret_cast<float2*>(Cext + (size_t)rowg * DM_ + colg) =
                        make_float2(v0, v1);
                }
            }
        }
    }
}

__global__ void __launch_bounds__(256, 2) gemm_qkv(const float* __restrict__ bq,
                                                   const float* __restrict__ bk,
                                                   const float* __restrict__ bv)
{
    extern __shared__ __align__(1024) char smem[];
    const int z = blockIdx.z;
    const float* bias = (z == 0) ? bq : (z == 1) ? bk : bv;
    __half* D16 = (z == 0) ? g_Q16 : (z == 1) ? g_K16 : g_V16;
    const float oscale = (z == 0) ? QSCALE : 1.0f;
    gemm_core(g_Ahi[z], g_Whi[z], bias, nullptr, D16, oscale, z, smem);
}

__global__ void __launch_bounds__(256, 2) gemm_out(const float* __restrict__ bo,
                                                   float* __restrict__ out)
{
    extern __shared__ __align__(1024) char smem[];
    gemm_core(g_Ahi[0], g_Whi[3], bo, out, nullptr, 1.0f, 3, smem);
}

// ---------------------------------------------------------------------------
// HMMA flash attention, causal, fp16, log2-domain half2 softmax.
// Bq=64, 128 threads (4 warps x 16 rows), 64-key tiles, 4 CTAs/SM.
// Wrap-paired schedule: CTA x handles qb = 31-x then qb = x (33 units each,
// 512 CTAs = one balanced wave). 3-stage KV ring, single barrier per tile.
// V via ldmatrix.trans from K-layout tiles. l = P·ones via MMA.
// Output: fp16 into g_Ahi[0] at [B,S,1024].
// ---------------------------------------------------------------------------
#define ATT_SMEM (8192 + 3 * 16384)   // Q tile + 3 KV stages = 56 KB

__global__ void __launch_bounds__(128, 4) attn_mma()
{
    extern __shared__ __align__(1024) char smem[];
    const uint32_t sb = smem_u32(smem);
    const int t = threadIdx.x, lane = t & 31, w = t >> 5;   // 4 warps
    const int bh = blockIdx.y;
    const int nqb = (int)(S_ / 64);                         // 32

    const size_t bo = (size_t)bh * S_ * DK_;
    const __half* Qg = g_Q16 + bo;
    const __half* Kg = g_K16 + bo;
    const __half* Vg = g_V16 + bo;
    const uint32_t QB = sb;
    const int b = bh >> 4, h = bh & 15;
    const uint32_t onesf[2] = {0x3C003C00u, 0x3C003C00u};

    #pragma unroll 1
    for (int seg = 0; seg < 2; seg++) {
        const int qb = seg ? (int)blockIdx.x : (nqb - 1 - (int)blockIdx.x);
        const int qs = qb * 64;
        const int nt = qb + 1;

        if (seg) __syncthreads();   // all warps done with previous segment's smem

        // prologue: Q tile + KV0 (group 0), KV1 (group 1)
        #pragma unroll
        for (int j = 0; j < 4; j++) {
            int g = t + j * 128, r = g >> 3, c = (g & 7) * 8;
            uint32_t so = sw128((uint32_t)(r * 128 + c * 2));
            CP_ASYNC16(QB + so, Qg + (size_t)(qs + r) * DK_ + c);
        }
        auto issueKV = [&](int i) {
            const int kt = i * 64;
            const uint32_t bB = sb + 8192u + (uint32_t)(i % 3) * 16384u;
            #pragma unroll
            for (int j = 0; j < 4; j++) {
                int g = t + j * 128, r = g >> 3, c = (g & 7) * 8;
                uint32_t so = sw128((uint32_t)(r * 128 + c * 2));
                CP_ASYNC16(bB + so,        Kg + (size_t)(kt + r) * DK_ + c);
                CP_ASYNC16(bB + 8192 + so, Vg + (size_t)(kt + r) * DK_ + c);
            }
        };
        issueKV(0);
        CP_COMMIT();
        if (nt > 1) { issueKV(1); CP_COMMIT(); }

        uint32_t qf[4][4];
        float o[8][4] = {};
        float ol[4] = {};
        float mrow0 = -INFINITY, mrow1 = -INFINITY;

        for (int i = 0; i < nt; i++) {
            if (i + 1 < nt) CP_WAIT(1); else CP_WAIT(0);
            __syncthreads();                              // single barrier / tile
            if (i + 2 < nt) { issueKV(i + 2); CP_COMMIT(); }

            if (i == 0) {
                #pragma unroll
                for (int kc = 0; kc < 4; kc++) {
                    int r = w * 16 + (lane & 7) + ((lane >> 3) & 1) * 8;
                    int kcol = kc * 16 + (lane >> 4) * 8;
                    LDSM_X4(qf[kc][0], qf[kc][1], qf[kc][2], qf[kc][3],
                            QB + sw128((uint32_t)(r * 128 + kcol * 2)));
                }
            }

            const int kt = i * 64;
            const uint32_t bB = sb + 8192u + (uint32_t)(i % 3) * 16384u;

            // ---- S = Q K^T (log2 domain)
            float s[8][4] = {};
            #pragma unroll
            for (int kc = 0; kc < 4; kc++) {
                const int kk = kc * 16;
                uint32_t bf[8][2];
                #pragma unroll
                for (int np = 0; np < 4; np++) {
                    int r = np * 16 + (lane & 7) + (lane >> 4) * 8;
                    int kcol = kk + ((lane >> 3) & 1) * 8;
                    LDSM_X4(bf[2 * np][0], bf[2 * np][1], bf[2 * np + 1][0], bf[2 * np + 1][1],
                            bB + sw128((uint32_t)(r * 128 + kcol * 2)));
                }
                #pragma unroll
                for (int j = 0; j < 8; j++)
                    MMA_F16(s[j], qf[kc], bf[j]);
            }

            // ---- causal mask (f32)
            const int r0g = qs + w * 16 + (lane >> 2);
            if (kt + 63 > qs + w * 16) {
                #pragma unroll
                for (int j = 0; j < 8; j++) {
                    const int cg = kt + j * 8 + (lane & 3) * 2;
                    if (cg     > r0g)     s[j][0] = -INFINITY;
                    if (cg + 1 > r0g)     s[j][1] = -INFINITY;
                    if (cg     > r0g + 8) s[j][2] = -INFINITY;
                    if (cg + 1 > r0g + 8) s[j][3] = -INFINITY;
                }
            }

            // ---- pack to half2
            __half2 hp0[8], hp1[8];
            #pragma unroll
            for (int j = 0; j < 8; j++) {
                hp0[j] = __floats2half2_rn(s[j][0], s[j][1]);
                hp1[j] = __floats2half2_rn(s[j][2], s[j][3]);
            }

            // ---- row max
            __half2 hm0 = hp0[0], hm1 = hp1[0];
            #pragma unroll
            for (int j = 1; j < 8; j++) {
                hm0 = __hmax2(hm0, hp0[j]);
                hm1 = __hmax2(hm1, hp1[j]);
            }
            float mx0 = fmaxf(__low2float(hm0), __high2float(hm0));
            float mx1 = fmaxf(__low2float(hm1), __high2float(hm1));
            mx0 = fmaxf(mx0, __shfl_xor_sync(0xffffffffu, mx0, 1));
            mx0 = fmaxf(mx0, __shfl_xor_sync(0xffffffffu, mx0, 2));
            mx1 = fmaxf(mx1, __shfl_xor_sync(0xffffffffu, mx1, 1));
            mx1 = fmaxf(mx1, __shfl_xor_sync(0xffffffffu, mx1, 2));
            const float mn0 = fmaxf(mrow0, mx0), mn1 = fmaxf(mrow1, mx1);
            const float al0 = ex2f(mrow0 - mn0), al1 = ex2f(mrow1 - mn1);
            mrow0 = mn0; mrow1 = mn1;

            // ---- P = ex2(S - m) into fp16 fragments
            const __half2 mn0h = __float2half2_rn(mn0);
            const __half2 mn1h = __float2half2_rn(mn1);
            uint32_t pf[4][4];
            #pragma unroll
            for (int kc = 0; kc < 4; kc++) {
                pf[kc][0] = ex2h2(__hsub2(hp0[2 * kc],     mn0h));
                pf[kc][1] = ex2h2(__hsub2(hp1[2 * kc],     mn1h));
                pf[kc][2] = ex2h2(__hsub2(hp0[2 * kc + 1], mn0h));
                pf[kc][3] = ex2h2(__hsub2(hp1[2 * kc + 1], mn1h));
            }

            // ---- rescale O and l (skip when maxes unchanged)
            if (!(al0 == 1.0f && al1 == 1.0f)) {
                #pragma unroll
                for (int j = 0; j < 8; j++) {
                    o[j][0] *= al0; o[j][1] *= al0;
                    o[j][2] *= al1; o[j][3] *= al1;
                }
                ol[0] *= al0; ol[1] *= al0;
                ol[2] *= al1; ol[3] *= al1;
            }

            // ---- O += P V (ldmatrix.trans from K-layout tile); l += P·1
            #pragma unroll
            for (int kc = 0; kc < 4; kc++) {
                const int kk = kc * 16;
                uint32_t vf[8][2];
                #pragma unroll
                for (int np = 0; np < 4; np++) {
                    int r = kk + (lane & 7) + ((lane >> 3) & 1) * 8;
                    int dcol = np * 16 + (lane >> 4) * 8;
                    LDSM_X4_T(vf[2 * np][0], vf[2 * np][1], vf[2 * np + 1][0], vf[2 * np + 1][1],
                              bB + 8192 + sw128((uint32_t)(r * 128 + dcol * 2)));
                }
                #pragma unroll
                for (int j = 0; j < 8; j++)
                    MMA_F16(o[j], pf[kc], vf[j]);
                MMA_F16(ol, pf[kc], onesf);
            }
        }

        // ---- epilogue: normalize, write fp16 to [B,S,1024]
        const float inv0 = 1.0f / ol[0], inv1 = 1.0f / ol[2];
        const int row0g = qs + w * 16 + (lane >> 2);
        #pragma unroll
        for (int j = 0; j < 8; j++) {
            const int d = j * 8 + (lane & 3) * 2;
            size_t off0 = (size_t)(b * S_ + row0g) * DM_ + h * DK_ + d;
            size_t off1 = off0 + (size_t)8 * DM_;
            *reinterpret_cast<uint32_t*>(g_Ahi[0] + off0) = pack2h(o[j][0] * inv0, o[j][1] * inv0);
            *reinterpret_cast<uint32_t*>(g_Ahi[0] + off1) = pack2h(o[j][2] * inv1, o[j][3] * inv1);
        }
    }
}

// ----------------------------------------------------------------------------
extern "C" void kernel_launch(void* const* d_in, const int* in_sizes, int n_in,
                              void* d_out, int out_size)
{
    const float* query = (const float*)d_in[0];
    const float* key   = (const float*)d_in[1];
    const float* value = (const float*)d_in[2];
    const float* Wq = (const float*)d_in[4];
    const float* bq = (const float*)d_in[5];
    const float* Wk = (const float*)d_in[6];
    const float* bk = (const float*)d_in[7];
    const float* Wv = (const float*)d_in[8];
    const float* bv = (const float*)d_in[9];
    const float* Wo = (const float*)d_in[10];
    const float* bo = (const float*)d_in[11];
    float* out = (float*)d_out;

    cudaFuncSetAttribute(gemm_qkv, cudaFuncAttributeMaxDynamicSharedMemorySize, GEMM_SMEM);
    cudaFuncSetAttribute(gemm_out, cudaFuncAttributeMaxDynamicSharedMemorySize, GEMM_SMEM);
    cudaFuncSetAttribute(attn_mma, cudaFuncAttributeMaxDynamicSharedMemorySize, ATT_SMEM);

    const int n4 = M_ * DM_ / 4;

    conv_inputs<<<dim3(n4 / 256, 3), 256>>>((const float4*)query, (const float4*)key,
                                            (const float4*)value);
    conv_weights<<<dim3(32, 32, 4), dim3(32, 8)>>>(Wq, Wk, Wv, Wo);

    gemm_qkv<<<dim3(DM_ / GN, M_ / GM, 3), 256, GEMM_SMEM>>>(bq, bk, bv);
    attn_mma<<<dim3(S_ / 128, B_ * H_), 128, ATT_SMEM>>>();   // 16 x 32 paired CTAs
    gemm_out<<<dim3(DM_ / GN, M_ / GM), 256, GEMM_SMEM>>>(bo, out);
}

// round 14
// speedup vs baseline: 2.8528x; 1.0229x over previous
#include <cuda_runtime.h>
#include <cuda_fp16.h>
#include <math.h>
#include <cstdint>

#define B_   2
#define S_   2048
#define H_   16
#define DK_  64
#define DM_  1024
#define M_   (B_ * S_)   // 4096

// ---------------------------------------------------------------------------
// PTX helpers — sm_80+ portable (harness PTX target is sm_103 WITHOUT 'a';
// tcgen05/TMEM unavailable; mma.sync/ldmatrix/cp.async are the path).
// ---------------------------------------------------------------------------
__device__ __forceinline__ uint32_t smem_u32(const void* p) {
    uint32_t a;
    asm("{ .reg .u64 t; cvta.to.shared.u64 t, %1; cvt.u32.u64 %0, t; }" : "=r"(a) : "l"(p));
    return a;
}
#define CP_ASYNC16(dst, src) \
    asm volatile("cp.async.cg.shared.global [%0], [%1], 16;" :: "r"(dst), "l"(src))
#define CP_COMMIT() asm volatile("cp.async.commit_group;" ::: "memory")
#define CP_WAIT(n)  asm volatile("cp.async.wait_group %0;" :: "n"(n) : "memory")

#define LDSM_X4(r0, r1, r2, r3, addr) \
    asm volatile("ldmatrix.sync.aligned.m8n8.x4.shared.b16 {%0,%1,%2,%3}, [%4];" \
                 : "=r"(r0), "=r"(r1), "=r"(r2), "=r"(r3) : "r"(addr))

#define LDSM_X4_T(r0, r1, r2, r3, addr) \
    asm volatile("ldmatrix.sync.aligned.m8n8.x4.trans.shared.b16 {%0,%1,%2,%3}, [%4];" \
                 : "=r"(r0), "=r"(r1), "=r"(r2), "=r"(r3) : "r"(addr))

#define MMA_F16(c, a, b) \
    asm volatile("mma.sync.aligned.m16n8k16.row.col.f32.f16.f16.f32 " \
                 "{%0,%1,%2,%3}, {%4,%5,%6,%7}, {%8,%9}, {%0,%1,%2,%3};" \
                 : "+f"((c)[0]), "+f"((c)[1]), "+f"((c)[2]), "+f"((c)[3]) \
                 : "r"((a)[0]), "r"((a)[1]), "r"((a)[2]), "r"((a)[3]), \
                   "r"((b)[0]), "r"((b)[1]))

__device__ __forceinline__ uint32_t sw128(uint32_t off) { return off ^ ((off >> 3) & 0x70); }

__device__ __forceinline__ uint32_t pack2h(float x, float y) {
    __half2 h2 = __halves2half2(__float2half(x), __float2half(y));
    return *reinterpret_cast<uint32_t*>(&h2);
}
__device__ __forceinline__ float ex2f(float x) {
    float r;
    asm("ex2.approx.f32 %0, %1;" : "=f"(r) : "f"(x));
    return r;
}
__device__ __forceinline__ uint32_t ex2h2(__half2 x) {
    uint32_t xi = *reinterpret_cast<uint32_t*>(&x), r;
    asm("ex2.approx.f16x2 %0, %1;" : "=r"(r) : "r"(xi));
    return r;
}

// Q prescale: 1/sqrt(64) * log2(e)  (softmax runs in log2 domain)
#define QSCALE 0.18033688011112042f

// ---------------------------------------------------------------------------
// Scratch (device globals)
// ---------------------------------------------------------------------------
__device__ __half g_Ahi[3][(size_t)M_ * DM_];    // A operands (0 reused for attn out)
__device__ __half g_Whi[4][(size_t)DM_ * DM_];   // W^T [N,K] K-contig
__device__ __half g_Q16[B_ * H_ * S_ * DK_];     // [B,H,S,64], pre-scaled by QSCALE
__device__ __half g_K16[B_ * H_ * S_ * DK_];
__device__ __half g_V16[B_ * H_ * S_ * DK_];

// ---------------------------------------------------------------------------
// fp32 -> fp16
// ---------------------------------------------------------------------------
__global__ void __launch_bounds__(256) conv_inputs(const float4* __restrict__ s0,
                                                   const float4* __restrict__ s1,
                                                   const float4* __restrict__ s2)
{
    const int which = blockIdx.y;
    const float4* src = (which == 0) ? s0 : (which == 1) ? s1 : s2;
    uint32_t* hi = reinterpret_cast<uint32_t*>(g_Ahi[which]);
    int i = blockIdx.x * 256 + threadIdx.x;
    float4 v = src[i];
    hi[2 * i + 0] = pack2h(v.x, v.y);
    hi[2 * i + 1] = pack2h(v.z, v.w);
}

// ---------------------------------------------------------------------------
// All 4 weights: W [K,N] fp32 -> transposed fp16 Wt[N,K]
// ---------------------------------------------------------------------------
__global__ void __launch_bounds__(256) conv_weights(const float* __restrict__ W0,
                                                    const float* __restrict__ W1,
                                                    const float* __restrict__ W2,
                                                    const float* __restrict__ W3)
{
    __shared__ float tile[32][33];
    const int which = blockIdx.z;
    const float* W = (which == 0) ? W0 : (which == 1) ? W1 : (which == 2) ? W2 : W3;
    __half* hi = g_Whi[which];
    const int bx = blockIdx.x, by = blockIdx.y;
    const int tx = threadIdx.x, ty = threadIdx.y;     // 32 x 8
    #pragma unroll
    for (int j = 0; j < 32; j += 8)
        tile[ty + j][tx] = W[(size_t)(by * 32 + ty + j) * DM_ + bx * 32 + tx];
    __syncthreads();
    #pragma unroll
    for (int j = 0; j < 32; j += 8)
        hi[(size_t)(bx * 32 + ty + j) * DM_ + by * 32 + tx] = __float2half(tile[tx][ty + j]);
}

// ---------------------------------------------------------------------------
// Single-pass HMMA GEMM core: 64x128 CTA tile, 128 threads (2Mx2N warps,
// warp tile 32x64), BK=64, 2-stage cp.async, 4 CTAs/SM.
// Fine granularity minimizes wave-quantization loss (T_cta halves).
// ---------------------------------------------------------------------------
#define GM 64
#define GN 128
#define GSTAGE 24576                   // A 8KB + B 16KB
#define GEMM_SMEM (2 * GSTAGE)         // 48 KB

__device__ __forceinline__ void gemm_core(const __half* __restrict__ A,
                                          const __half* __restrict__ W,
                                          const float* __restrict__ bias,
                                          float* __restrict__ Cext,
                                          __half* __restrict__ D16,
                                          float oscale, int mode, char* smem)
{
    const uint32_t sb = smem_u32(smem);
    const int t = threadIdx.x, lane = t & 31, wid = t >> 5;
    const int warpM = wid >> 1, warpN = wid & 1;
    const int row0 = blockIdx.y * GM, col0 = blockIdx.x * GN;

    float c[2][8][4] = {};

    auto issue = [&](int i) {
        const int kc = i * 64;
        const uint32_t ab = sb + (uint32_t)(i & 1) * GSTAGE;
        const uint32_t bb = ab + 8192u;
        #pragma unroll
        for (int j = 0; j < 4; j++) {          // A: 64x64 = 512 x 16B chunks
            int g = t + j * 128, r = g >> 3, ccol = (g & 7) * 8;
            uint32_t so = sw128((uint32_t)(r * 128 + ccol * 2));
            CP_ASYNC16(ab + so, A + (size_t)(row0 + r) * DM_ + kc + ccol);
        }
        #pragma unroll
        for (int j = 0; j < 8; j++) {          // B: 128x64 = 1024 x 16B chunks
            int g = t + j * 128, r = g >> 3, ccol = (g & 7) * 8;
            uint32_t so = sw128((uint32_t)(r * 128 + ccol * 2));
            CP_ASYNC16(bb + so, W + (size_t)(col0 + r) * DM_ + kc + ccol);
        }
    };

    issue(0);
    CP_COMMIT();

    for (int i = 0; i < 16; i++) {
        if (i + 1 < 16) { issue(i + 1); CP_COMMIT(); CP_WAIT(1); }
        else            { CP_WAIT(0); }
        __syncthreads();

        const uint32_t ab = sb + (uint32_t)(i & 1) * GSTAGE;
        const uint32_t bb = ab + 8192u;

        #pragma unroll
        for (int kst = 0; kst < 4; kst++) {
            const int kk = kst * 16;
            uint32_t a[2][4], b[8][2];
            #pragma unroll
            for (int mt = 0; mt < 2; mt++) {
                int r = warpM * 32 + mt * 16 + (lane & 7) + ((lane >> 3) & 1) * 8;
                int kcol = kk + (lane >> 4) * 8;
                LDSM_X4(a[mt][0], a[mt][1], a[mt][2], a[mt][3],
                        ab + sw128((uint32_t)(r * 128 + kcol * 2)));
            }
            #pragma unroll
            for (int np = 0; np < 4; np++) {
                int r = warpN * 64 + np * 16 + (lane & 7) + (lane >> 4) * 8;
                int kcol = kk + ((lane >> 3) & 1) * 8;
                LDSM_X4(b[2 * np][0], b[2 * np][1], b[2 * np + 1][0], b[2 * np + 1][1],
                        bb + sw128((uint32_t)(r * 128 + kcol * 2)));
            }
            #pragma unroll
            for (int mt = 0; mt < 2; mt++)
                #pragma unroll
                for (int nt = 0; nt < 8; nt++)
                    MMA_F16(c[mt][nt], a[mt], b[nt]);
        }
        __syncthreads();
    }

    #pragma unroll
    for (int mt = 0; mt < 2; mt++) {
        #pragma unroll
        for (int half = 0; half < 2; half++) {
            const int rowg = row0 + warpM * 32 + mt * 16 + (lane >> 2) + half * 8;
            const int bb_ = rowg >> 11, ss = rowg & (S_ - 1);
            #pragma unroll
            for (int nt = 0; nt < 8; nt++) {
                const int colg = col0 + warpN * 64 + nt * 8 + (lane & 3) * 2;
                const float v0 = (c[mt][nt][half * 2 + 0] + bias[colg]) * oscale;
                const float v1 = (c[mt][nt][half * 2 + 1] + bias[colg + 1]) * oscale;
                if (mode < 3) {
                    const int h = colg >> 6;
                    size_t off = ((size_t)((bb_ * H_ + h) * S_ + ss)) * DK_ + (colg & 63);
                    *reinterpret_cast<uint32_t*>(D16 + off) = pack2h(v0, v1);
                } else {
                    *reinterpret_cast<float2*>(Cext + (size_t)rowg * DM_ + colg) =
                        make_float2(v0, v1);
                }
            }
        }
    }
}

__global__ void __launch_bounds__(128, 4) gemm_qkv(const float* __restrict__ bq,
                                                   const float* __restrict__ bk,
                                                   const float* __restrict__ bv)
{
    extern __shared__ __align__(1024) char smem[];
    const int z = blockIdx.z;
    const float* bias = (z == 0) ? bq : (z == 1) ? bk : bv;
    __half* D16 = (z == 0) ? g_Q16 : (z == 1) ? g_K16 : g_V16;
    const float oscale = (z == 0) ? QSCALE : 1.0f;
    gemm_core(g_Ahi[z], g_Whi[z], bias, nullptr, D16, oscale, z, smem);
}

__global__ void __launch_bounds__(128, 4) gemm_out(const float* __restrict__ bo,
                                                   float* __restrict__ out)
{
    extern __shared__ __align__(1024) char smem[];
    gemm_core(g_Ahi[0], g_Whi[3], bo, out, nullptr, 1.0f, 3, smem);
}

// ---------------------------------------------------------------------------
// HMMA flash attention, causal, fp16, log2-domain half2 softmax (as R13).
// Bq=64, 128 threads, wrap-paired schedule, 3-stage KV ring, V via
// ldmatrix.trans, l via ones-MMA. Output fp16 into g_Ahi[0].
// ---------------------------------------------------------------------------
#define ATT_SMEM (8192 + 3 * 16384)   // 56 KB

__global__ void __launch_bounds__(128, 4) attn_mma()
{
    extern __shared__ __align__(1024) char smem[];
    const uint32_t sb = smem_u32(smem);
    const int t = threadIdx.x, lane = t & 31, w = t >> 5;   // 4 warps
    const int bh = blockIdx.y;
    const int nqb = (int)(S_ / 64);                         // 32

    const size_t bo = (size_t)bh * S_ * DK_;
    const __half* Qg = g_Q16 + bo;
    const __half* Kg = g_K16 + bo;
    const __half* Vg = g_V16 + bo;
    const uint32_t QB = sb;
    const int b = bh >> 4, h = bh & 15;
    const uint32_t onesf[2] = {0x3C003C00u, 0x3C003C00u};

    #pragma unroll 1
    for (int seg = 0; seg < 2; seg++) {
        const int qb = seg ? (int)blockIdx.x : (nqb - 1 - (int)blockIdx.x);
        const int qs = qb * 64;
        const int nt = qb + 1;

        if (seg) __syncthreads();

        #pragma unroll
        for (int j = 0; j < 4; j++) {
            int g = t + j * 128, r = g >> 3, c = (g & 7) * 8;
            uint32_t so = sw128((uint32_t)(r * 128 + c * 2));
            CP_ASYNC16(QB + so, Qg + (size_t)(qs + r) * DK_ + c);
        }
        auto issueKV = [&](int i) {
            const int kt = i * 64;
            const uint32_t bB = sb + 8192u + (uint32_t)(i % 3) * 16384u;
            #pragma unroll
            for (int j = 0; j < 4; j++) {
                int g = t + j * 128, r = g >> 3, c = (g & 7) * 8;
                uint32_t so = sw128((uint32_t)(r * 128 + c * 2));
                CP_ASYNC16(bB + so,        Kg + (size_t)(kt + r) * DK_ + c);
                CP_ASYNC16(bB + 8192 + so, Vg + (size_t)(kt + r) * DK_ + c);
            }
        };
        issueKV(0);
        CP_COMMIT();
        if (nt > 1) { issueKV(1); CP_COMMIT(); }

        uint32_t qf[4][4];
        float o[8][4] = {};
        float ol[4] = {};
        float mrow0 = -INFINITY, mrow1 = -INFINITY;

        for (int i = 0; i < nt; i++) {
            if (i + 1 < nt) CP_WAIT(1); else CP_WAIT(0);
            __syncthreads();
            if (i + 2 < nt) { issueKV(i + 2); CP_COMMIT(); }

            if (i == 0) {
                #pragma unroll
                for (int kc = 0; kc < 4; kc++) {
                    int r = w * 16 + (lane & 7) + ((lane >> 3) & 1) * 8;
                    int kcol = kc * 16 + (lane >> 4) * 8;
                    LDSM_X4(qf[kc][0], qf[kc][1], qf[kc][2], qf[kc][3],
                            QB + sw128((uint32_t)(r * 128 + kcol * 2)));
                }
            }

            const int kt = i * 64;
            const uint32_t bB = sb + 8192u + (uint32_t)(i % 3) * 16384u;

            // ---- S = Q K^T (log2 domain)
            float s[8][4] = {};
            #pragma unroll
            for (int kc = 0; kc < 4; kc++) {
                const int kk = kc * 16;
                uint32_t bf[8][2];
                #pragma unroll
                for (int np = 0; np < 4; np++) {
                    int r = np * 16 + (lane & 7) + (lane >> 4) * 8;
                    int kcol = kk + ((lane >> 3) & 1) * 8;
                    LDSM_X4(bf[2 * np][0], bf[2 * np][1], bf[2 * np + 1][0], bf[2 * np + 1][1],
                            bB + sw128((uint32_t)(r * 128 + kcol * 2)));
                }
                #pragma unroll
                for (int j = 0; j < 8; j++)
                    MMA_F16(s[j], qf[kc], bf[j]);
            }

            // ---- causal mask
            const int r0g = qs + w * 16 + (lane >> 2);
            if (kt + 63 > qs + w * 16) {
                #pragma unroll
                for (int j = 0; j < 8; j++) {
                    const int cg = kt + j * 8 + (lane & 3) * 2;
                    if (cg     > r0g)     s[j][0] = -INFINITY;
                    if (cg + 1 > r0g)     s[j][1] = -INFINITY;
                    if (cg     > r0g + 8) s[j][2] = -INFINITY;
                    if (cg + 1 > r0g + 8) s[j][3] = -INFINITY;
                }
            }

            // ---- pack to half2
            __half2 hp0[8], hp1[8];
            #pragma unroll
            for (int j = 0; j < 8; j++) {
                hp0[j] = __floats2half2_rn(s[j][0], s[j][1]);
                hp1[j] = __floats2half2_rn(s[j][2], s[j][3]);
            }

            // ---- row max
            __half2 hm0 = hp0[0], hm1 = hp1[0];
            #pragma unroll
            for (int j = 1; j < 8; j++) {
                hm0 = __hmax2(hm0, hp0[j]);
                hm1 = __hmax2(hm1, hp1[j]);
            }
            float mx0 = fmaxf(__low2float(hm0), __high2float(hm0));
            float mx1 = fmaxf(__low2float(hm1), __high2float(hm1));
            mx0 = fmaxf(mx0, __shfl_xor_sync(0xffffffffu, mx0, 1));
            mx0 = fmaxf(mx0, __shfl_xor_sync(0xffffffffu, mx0, 2));
            mx1 = fmaxf(mx1, __shfl_xor_sync(0xffffffffu, mx1, 1));
            mx1 = fmaxf(mx1, __shfl_xor_sync(0xffffffffu, mx1, 2));
            const float mn0 = fmaxf(mrow0, mx0), mn1 = fmaxf(mrow1, mx1);
            const float al0 = ex2f(mrow0 - mn0), al1 = ex2f(mrow1 - mn1);
            mrow0 = mn0; mrow1 = mn1;

            // ---- P = ex2(S - m) into fp16 fragments
            const __half2 mn0h = __float2half2_rn(mn0);
            const __half2 mn1h = __float2half2_rn(mn1);
            uint32_t pf[4][4];
            #pragma unroll
            for (int kc = 0; kc < 4; kc++) {
                pf[kc][0] = ex2h2(__hsub2(hp0[2 * kc],     mn0h));
                pf[kc][1] = ex2h2(__hsub2(hp1[2 * kc],     mn1h));
                pf[kc][2] = ex2h2(__hsub2(hp0[2 * kc + 1], mn0h));
                pf[kc][3] = ex2h2(__hsub2(hp1[2 * kc + 1], mn1h));
            }

            // ---- rescale O and l (skip when maxes unchanged)
            if (!(al0 == 1.0f && al1 == 1.0f)) {
                #pragma unroll
                for (int j = 0; j < 8; j++) {
                    o[j][0] *= al0; o[j][1] *= al0;
                    o[j][2] *= al1; o[j][3] *= al1;
                }
                ol[0] *= al0; ol[1] *= al0;
                ol[2] *= al1; ol[3] *= al1;
            }

            // ---- O += P V (ldmatrix.trans from K-layout tile); l += P·1
            #pragma unroll
            for (int kc = 0; kc < 4; kc++) {
                const int kk = kc * 16;
                uint32_t vf[8][2];
                #pragma unroll
                for (int np = 0; np < 4; np++) {
                    int r = kk + (lane & 7) + ((lane >> 3) & 1) * 8;
                    int dcol = np * 16 + (lane >> 4) * 8;
                    LDSM_X4_T(vf[2 * np][0], vf[2 * np][1], vf[2 * np + 1][0], vf[2 * np + 1][1],
                              bB + 8192 + sw128((uint32_t)(r * 128 + dcol * 2)));
                }
                #pragma unroll
                for (int j = 0; j < 8; j++)
                    MMA_F16(o[j], pf[kc], vf[j]);
                MMA_F16(ol, pf[kc], onesf);
            }
        }

        // ---- epilogue
        const float inv0 = 1.0f / ol[0], inv1 = 1.0f / ol[2];
        const int row0g = qs + w * 16 + (lane >> 2);
        #pragma unroll
        for (int j = 0; j < 8; j++) {
            const int d = j * 8 + (lane & 3) * 2;
            size_t off0 = (size_t)(b * S_ + row0g) * DM_ + h * DK_ + d;
            size_t off1 = off0 + (size_t)8 * DM_;
            *reinterpret_cast<uint32_t*>(g_Ahi[0] + off0) = pack2h(o[j][0] * inv0, o[j][1] * inv0);
            *reinterpret_cast<uint32_t*>(g_Ahi[0] + off1) = pack2h(o[j][2] * inv1, o[j][3] * inv1);
        }
    }
}

// ----------------------------------------------------------------------------
extern "C" void kernel_launch(void* const* d_in, const int* in_sizes, int n_in,
                              void* d_out, int out_size)
{
    const float* query = (const float*)d_in[0];
    const float* key   = (const float*)d_in[1];
    const float* value = (const float*)d_in[2];
    const float* Wq = (const float*)d_in[4];
    const float* bq = (const float*)d_in[5];
    const float* Wk = (const float*)d_in[6];
    const float* bk = (const float*)d_in[7];
    const float* Wv = (const float*)d_in[8];
    const float* bv = (const float*)d_in[9];
    const float* Wo = (const float*)d_in[10];
    const float* bo = (const float*)d_in[11];
    float* out = (float*)d_out;

    cudaFuncSetAttribute(gemm_qkv, cudaFuncAttributeMaxDynamicSharedMemorySize, GEMM_SMEM);
    cudaFuncSetAttribute(gemm_out, cudaFuncAttributeMaxDynamicSharedMemorySize, GEMM_SMEM);
    cudaFuncSetAttribute(attn_mma, cudaFuncAttributeMaxDynamicSharedMemorySize, ATT_SMEM);

    const int n4 = M_ * DM_ / 4;

    conv_inputs<<<dim3(n4 / 256, 3), 256>>>((const float4*)query, (const float4*)key,
                                            (const float4*)value);
    conv_weights<<<dim3(32, 32, 4), dim3(32, 8)>>>(Wq, Wk, Wv, Wo);

    gemm_qkv<<<dim3(DM_ / GN, M_ / GM, 3), 128, GEMM_SMEM>>>(bq, bk, bv);   // 1536 CTAs
    attn_mma<<<dim3(S_ / 128, B_ * H_), 128, ATT_SMEM>>>();                 // 512 paired CTAs
    gemm_out<<<dim3(DM_ / GN, M_ / GM), 128, GEMM_SMEM>>>(bo, out);         // 512 CTAs
}

// round 15
// speedup vs baseline: 2.9160x; 1.0222x over previous
#include <cuda_runtime.h>
#include <cuda_fp16.h>
#include <math.h>
#include <cstdint>

#define B_   2
#define S_   2048
#define H_   16
#define DK_  64
#define DM_  1024
#define M_   (B_ * S_)   // 4096

// ---------------------------------------------------------------------------
// PTX helpers — sm_80+ portable (harness PTX target is sm_103 WITHOUT 'a';
// tcgen05/TMEM unavailable; mma.sync/ldmatrix/cp.async are the path).
// ---------------------------------------------------------------------------
__device__ __forceinline__ uint32_t smem_u32(const void* p) {
    uint32_t a;
    asm("{ .reg .u64 t; cvta.to.shared.u64 t, %1; cvt.u32.u64 %0, t; }" : "=r"(a) : "l"(p));
    return a;
}
#define CP_ASYNC16(dst, src) \
    asm volatile("cp.async.cg.shared.global [%0], [%1], 16;" :: "r"(dst), "l"(src))
#define CP_COMMIT() asm volatile("cp.async.commit_group;" ::: "memory")
#define CP_WAIT(n)  asm volatile("cp.async.wait_group %0;" :: "n"(n) : "memory")

#define LDSM_X4(r0, r1, r2, r3, addr) \
    asm volatile("ldmatrix.sync.aligned.m8n8.x4.shared.b16 {%0,%1,%2,%3}, [%4];" \
                 : "=r"(r0), "=r"(r1), "=r"(r2), "=r"(r3) : "r"(addr))

#define LDSM_X4_T(r0, r1, r2, r3, addr) \
    asm volatile("ldmatrix.sync.aligned.m8n8.x4.trans.shared.b16 {%0,%1,%2,%3}, [%4];" \
                 : "=r"(r0), "=r"(r1), "=r"(r2), "=r"(r3) : "r"(addr))

#define MMA_F16(c, a, b) \
    asm volatile("mma.sync.aligned.m16n8k16.row.col.f32.f16.f16.f32 " \
                 "{%0,%1,%2,%3}, {%4,%5,%6,%7}, {%8,%9}, {%0,%1,%2,%3};" \
                 : "+f"((c)[0]), "+f"((c)[1]), "+f"((c)[2]), "+f"((c)[3]) \
                 : "r"((a)[0]), "r"((a)[1]), "r"((a)[2]), "r"((a)[3]), \
                   "r"((b)[0]), "r"((b)[1]))

__device__ __forceinline__ uint32_t sw128(uint32_t off) { return off ^ ((off >> 3) & 0x70); }

__device__ __forceinline__ uint32_t pack2h(float x, float y) {
    __half2 h2 = __halves2half2(__float2half(x), __float2half(y));
    return *reinterpret_cast<uint32_t*>(&h2);
}
__device__ __forceinline__ float ex2f(float x) {
    float r;
    asm("ex2.approx.f32 %0, %1;" : "=f"(r) : "f"(x));
    return r;
}
__device__ __forceinline__ uint32_t ex2h2(__half2 x) {
    uint32_t xi = *reinterpret_cast<uint32_t*>(&x), r;
    asm("ex2.approx.f16x2 %0, %1;" : "=r"(r) : "r"(xi));
    return r;
}

// Q prescale: 1/sqrt(64) * log2(e)  (softmax runs in log2 domain)
#define QSCALE 0.18033688011112042f

// ---------------------------------------------------------------------------
// Scratch (device globals)
// ---------------------------------------------------------------------------
__device__ __half g_Ahi[3][(size_t)M_ * DM_];    // A operands (0 reused for attn out)
__device__ __half g_Whi[4][(size_t)DM_ * DM_];   // W^T [N,K] K-contig
__device__ __half g_Q16[B_ * H_ * S_ * DK_];     // [B,H,S,64], pre-scaled by QSCALE
__device__ __half g_K16[B_ * H_ * S_ * DK_];
__device__ __half g_V16[B_ * H_ * S_ * DK_];

// ---------------------------------------------------------------------------
// fp32 -> fp16
// ---------------------------------------------------------------------------
__global__ void __launch_bounds__(256) conv_inputs(const float4* __restrict__ s0,
                                                   const float4* __restrict__ s1,
                                                   const float4* __restrict__ s2)
{
    const int which = blockIdx.y;
    const float4* src = (which == 0) ? s0 : (which == 1) ? s1 : s2;
    uint32_t* hi = reinterpret_cast<uint32_t*>(g_Ahi[which]);
    int i = blockIdx.x * 256 + threadIdx.x;
    float4 v = src[i];
    hi[2 * i + 0] = pack2h(v.x, v.y);
    hi[2 * i + 1] = pack2h(v.z, v.w);
}

// ---------------------------------------------------------------------------
// All 4 weights: W [K,N] fp32 -> transposed fp16 Wt[N,K]
// ---------------------------------------------------------------------------
__global__ void __launch_bounds__(256) conv_weights(const float* __restrict__ W0,
                                                    const float* __restrict__ W1,
                                                    const float* __restrict__ W2,
                                                    const float* __restrict__ W3)
{
    __shared__ float tile[32][33];
    const int which = blockIdx.z;
    const float* W = (which == 0) ? W0 : (which == 1) ? W1 : (which == 2) ? W2 : W3;
    __half* hi = g_Whi[which];
    const int bx = blockIdx.x, by = blockIdx.y;
    const int tx = threadIdx.x, ty = threadIdx.y;     // 32 x 8
    #pragma unroll
    for (int j = 0; j < 32; j += 8)
        tile[ty + j][tx] = W[(size_t)(by * 32 + ty + j) * DM_ + bx * 32 + tx];
    __syncthreads();
    #pragma unroll
    for (int j = 0; j < 32; j += 8)
        hi[(size_t)(bx * 32 + ty + j) * DM_ + by * 32 + tx] = __float2half(tile[tx][ty + j]);
}

// ---------------------------------------------------------------------------
// Single-pass HMMA GEMM core: 64x128 CTA tile, 128 threads (2Mx2N warps,
// warp tile 32x64), BK=64, 2-stage cp.async, 4 CTAs/SM. (unchanged R14)
// ---------------------------------------------------------------------------
#define GM 64
#define GN 128
#define GSTAGE 24576
#define GEMM_SMEM (2 * GSTAGE)

__device__ __forceinline__ void gemm_core(const __half* __restrict__ A,
                                          const __half* __restrict__ W,
                                          const float* __restrict__ bias,
                                          float* __restrict__ Cext,
                                          __half* __restrict__ D16,
                                          float oscale, int mode, char* smem)
{
    const uint32_t sb = smem_u32(smem);
    const int t = threadIdx.x, lane = t & 31, wid = t >> 5;
    const int warpM = wid >> 1, warpN = wid & 1;
    const int row0 = blockIdx.y * GM, col0 = blockIdx.x * GN;

    float c[2][8][4] = {};

    auto issue = [&](int i) {
        const int kc = i * 64;
        const uint32_t ab = sb + (uint32_t)(i & 1) * GSTAGE;
        const uint32_t bb = ab + 8192u;
        #pragma unroll
        for (int j = 0; j < 4; j++) {
            int g = t + j * 128, r = g >> 3, ccol = (g & 7) * 8;
            uint32_t so = sw128((uint32_t)(r * 128 + ccol * 2));
            CP_ASYNC16(ab + so, A + (size_t)(row0 + r) * DM_ + kc + ccol);
        }
        #pragma unroll
        for (int j = 0; j < 8; j++) {
            int g = t + j * 128, r = g >> 3, ccol = (g & 7) * 8;
            uint32_t so = sw128((uint32_t)(r * 128 + ccol * 2));
            CP_ASYNC16(bb + so, W + (size_t)(col0 + r) * DM_ + kc + ccol);
        }
    };

    issue(0);
    CP_COMMIT();

    for (int i = 0; i < 16; i++) {
        if (i + 1 < 16) { issue(i + 1); CP_COMMIT(); CP_WAIT(1); }
        else            { CP_WAIT(0); }
        __syncthreads();

        const uint32_t ab = sb + (uint32_t)(i & 1) * GSTAGE;
        const uint32_t bb = ab + 8192u;

        #pragma unroll
        for (int kst = 0; kst < 4; kst++) {
            const int kk = kst * 16;
            uint32_t a[2][4], b[8][2];
            #pragma unroll
            for (int mt = 0; mt < 2; mt++) {
                int r = warpM * 32 + mt * 16 + (lane & 7) + ((lane >> 3) & 1) * 8;
                int kcol = kk + (lane >> 4) * 8;
                LDSM_X4(a[mt][0], a[mt][1], a[mt][2], a[mt][3],
                        ab + sw128((uint32_t)(r * 128 + kcol * 2)));
            }
            #pragma unroll
            for (int np = 0; np < 4; np++) {
                int r = warpN * 64 + np * 16 + (lane & 7) + (lane >> 4) * 8;
                int kcol = kk + ((lane >> 3) & 1) * 8;
                LDSM_X4(b[2 * np][0], b[2 * np][1], b[2 * np + 1][0], b[2 * np + 1][1],
                        bb + sw128((uint32_t)(r * 128 + kcol * 2)));
            }
            #pragma unroll
            for (int mt = 0; mt < 2; mt++)
                #pragma unroll
                for (int nt = 0; nt < 8; nt++)
                    MMA_F16(c[mt][nt], a[mt], b[nt]);
        }
        __syncthreads();
    }

    #pragma unroll
    for (int mt = 0; mt < 2; mt++) {
        #pragma unroll
        for (int half = 0; half < 2; half++) {
            const int rowg = row0 + warpM * 32 + mt * 16 + (lane >> 2) + half * 8;
            const int bb_ = rowg >> 11, ss = rowg & (S_ - 1);
            #pragma unroll
            for (int nt = 0; nt < 8; nt++) {
                const int colg = col0 + warpN * 64 + nt * 8 + (lane & 3) * 2;
                const float v0 = (c[mt][nt][half * 2 + 0] + bias[colg]) * oscale;
                const float v1 = (c[mt][nt][half * 2 + 1] + bias[colg + 1]) * oscale;
                if (mode < 3) {
                    const int h = colg >> 6;
                    size_t off = ((size_t)((bb_ * H_ + h) * S_ + ss)) * DK_ + (colg & 63);
                    *reinterpret_cast<uint32_t*>(D16 + off) = pack2h(v0, v1);
                } else {
                    *reinterpret_cast<float2*>(Cext + (size_t)rowg * DM_ + colg) =
                        make_float2(v0, v1);
                }
            }
        }
    }
}

__global__ void __launch_bounds__(128, 4) gemm_qkv(const float* __restrict__ bq,
                                                   const float* __restrict__ bk,
                                                   const float* __restrict__ bv)
{
    extern __shared__ __align__(1024) char smem[];
    const int z = blockIdx.z;
    const float* bias = (z == 0) ? bq : (z == 1) ? bk : bv;
    __half* D16 = (z == 0) ? g_Q16 : (z == 1) ? g_K16 : g_V16;
    const float oscale = (z == 0) ? QSCALE : 1.0f;
    gemm_core(g_Ahi[z], g_Whi[z], bias, nullptr, D16, oscale, z, smem);
}

__global__ void __launch_bounds__(128, 4) gemm_out(const float* __restrict__ bo,
                                                   float* __restrict__ out)
{
    extern __shared__ __align__(1024) char smem[];
    gemm_core(g_Ahi[0], g_Whi[3], bo, out, nullptr, 1.0f, 3, smem);
}

// ---------------------------------------------------------------------------
// HMMA flash attention, causal, fp16, log2-domain half2 softmax.
// Bq=64, 64 threads = 2 warps; each warp owns 32 query rows (2 m16 frags)
// sharing one set of K/V fragment loads -> smem bytes/MAC halved.
// Wrap-paired schedule, 3-stage KV ring, V via ldmatrix.trans, l via ones-MMA.
// Output fp16 into g_Ahi[0] at [B,S,1024].
// ---------------------------------------------------------------------------
#define ATT_SMEM (8192 + 3 * 16384)   // 56 KB

__global__ void __launch_bounds__(64, 4) attn_mma()
{
    extern __shared__ __align__(1024) char smem[];
    const uint32_t sb = smem_u32(smem);
    const int t = threadIdx.x, lane = t & 31, w = t >> 5;   // 2 warps
    const int bh = blockIdx.y;
    const int nqb = (int)(S_ / 64);                         // 32

    const size_t bo = (size_t)bh * S_ * DK_;
    const __half* Qg = g_Q16 + bo;
    const __half* Kg = g_K16 + bo;
    const __half* Vg = g_V16 + bo;
    const uint32_t QB = sb;
    const int b = bh >> 4, h = bh & 15;
    const uint32_t onesf[2] = {0x3C003C00u, 0x3C003C00u};

    #pragma unroll 1
    for (int seg = 0; seg < 2; seg++) {
        const int qb = seg ? (int)blockIdx.x : (nqb - 1 - (int)blockIdx.x);
        const int qs = qb * 64;
        const int nt = qb + 1;

        if (seg) __syncthreads();

        #pragma unroll
        for (int j = 0; j < 8; j++) {
            int g = t + j * 64, r = g >> 3, c = (g & 7) * 8;
            uint32_t so = sw128((uint32_t)(r * 128 + c * 2));
            CP_ASYNC16(QB + so, Qg + (size_t)(qs + r) * DK_ + c);
        }
        auto issueKV = [&](int i) {
            const int kt = i * 64;
            const uint32_t bB = sb + 8192u + (uint32_t)(i % 3) * 16384u;
            #pragma unroll
            for (int j = 0; j < 8; j++) {
                int g = t + j * 64, r = g >> 3, c = (g & 7) * 8;
                uint32_t so = sw128((uint32_t)(r * 128 + c * 2));
                CP_ASYNC16(bB + so,        Kg + (size_t)(kt + r) * DK_ + c);
                CP_ASYNC16(bB + 8192 + so, Vg + (size_t)(kt + r) * DK_ + c);
            }
        };
        issueKV(0);
        CP_COMMIT();
        if (nt > 1) { issueKV(1); CP_COMMIT(); }

        uint32_t qf[2][4][4];                  // 2 m16 fragments x 4 kc
        float o[2][8][4] = {};
        float ol[2][4] = {};
        float mrow[2][2] = {{-INFINITY, -INFINITY}, {-INFINITY, -INFINITY}};

        for (int i = 0; i < nt; i++) {
            if (i + 1 < nt) CP_WAIT(1); else CP_WAIT(0);
            __syncthreads();
            if (i + 2 < nt) { issueKV(i + 2); CP_COMMIT(); }

            if (i == 0) {
                #pragma unroll
                for (int f = 0; f < 2; f++)
                    #pragma unroll
                    for (int kc = 0; kc < 4; kc++) {
                        int r = w * 32 + f * 16 + (lane & 7) + ((lane >> 3) & 1) * 8;
                        int kcol = kc * 16 + (lane >> 4) * 8;
                        LDSM_X4(qf[f][kc][0], qf[f][kc][1], qf[f][kc][2], qf[f][kc][3],
                                QB + sw128((uint32_t)(r * 128 + kcol * 2)));
                    }
            }

            const int kt = i * 64;
            const uint32_t bB = sb + 8192u + (uint32_t)(i % 3) * 16384u;

            // ---- S = Q K^T (log2 domain), shared bf across both fragments
            float s[2][8][4] = {};
            #pragma unroll
            for (int kc = 0; kc < 4; kc++) {
                const int kk = kc * 16;
                uint32_t bf[8][2];
                #pragma unroll
                for (int np = 0; np < 4; np++) {
                    int r = np * 16 + (lane & 7) + (lane >> 4) * 8;
                    int kcol = kk + ((lane >> 3) & 1) * 8;
                    LDSM_X4(bf[2 * np][0], bf[2 * np][1], bf[2 * np + 1][0], bf[2 * np + 1][1],
                            bB + sw128((uint32_t)(r * 128 + kcol * 2)));
                }
                #pragma unroll
                for (int f = 0; f < 2; f++)
                    #pragma unroll
                    for (int j = 0; j < 8; j++)
                        MMA_F16(s[f][j], qf[f][kc], bf[j]);
            }

            // ---- per-fragment softmax -> pf
            uint32_t pf[2][4][4];
            #pragma unroll
            for (int f = 0; f < 2; f++) {
                const int rbase = qs + w * 32 + f * 16;
                const int r0g = rbase + (lane >> 2);
                if (kt + 63 > rbase) {
                    #pragma unroll
                    for (int j = 0; j < 8; j++) {
                        const int cg = kt + j * 8 + (lane & 3) * 2;
                        if (cg     > r0g)     s[f][j][0] = -INFINITY;
                        if (cg + 1 > r0g)     s[f][j][1] = -INFINITY;
                        if (cg     > r0g + 8) s[f][j][2] = -INFINITY;
                        if (cg + 1 > r0g + 8) s[f][j][3] = -INFINITY;
                    }
                }
                __half2 hp0[8], hp1[8];
                #pragma unroll
                for (int j = 0; j < 8; j++) {
                    hp0[j] = __floats2half2_rn(s[f][j][0], s[f][j][1]);
                    hp1[j] = __floats2half2_rn(s[f][j][2], s[f][j][3]);
                }
                __half2 hm0 = hp0[0], hm1 = hp1[0];
                #pragma unroll
                for (int j = 1; j < 8; j++) {
                    hm0 = __hmax2(hm0, hp0[j]);
                    hm1 = __hmax2(hm1, hp1[j]);
                }
                float mx0 = fmaxf(__low2float(hm0), __high2float(hm0));
                float mx1 = fmaxf(__low2float(hm1), __high2float(hm1));
                mx0 = fmaxf(mx0, __shfl_xor_sync(0xffffffffu, mx0, 1));
                mx0 = fmaxf(mx0, __shfl_xor_sync(0xffffffffu, mx0, 2));
                mx1 = fmaxf(mx1, __shfl_xor_sync(0xffffffffu, mx1, 1));
                mx1 = fmaxf(mx1, __shfl_xor_sync(0xffffffffu, mx1, 2));
                const float mn0 = fmaxf(mrow[f][0], mx0), mn1 = fmaxf(mrow[f][1], mx1);
                const float al0 = ex2f(mrow[f][0] - mn0), al1 = ex2f(mrow[f][1] - mn1);
                mrow[f][0] = mn0; mrow[f][1] = mn1;

                const __half2 mn0h = __float2half2_rn(mn0);
                const __half2 mn1h = __float2half2_rn(mn1);
                #pragma unroll
                for (int kc = 0; kc < 4; kc++) {
                    pf[f][kc][0] = ex2h2(__hsub2(hp0[2 * kc],     mn0h));
                    pf[f][kc][1] = ex2h2(__hsub2(hp1[2 * kc],     mn1h));
                    pf[f][kc][2] = ex2h2(__hsub2(hp0[2 * kc + 1], mn0h));
                    pf[f][kc][3] = ex2h2(__hsub2(hp1[2 * kc + 1], mn1h));
                }

                if (!(al0 == 1.0f && al1 == 1.0f)) {
                    #pragma unroll
                    for (int j = 0; j < 8; j++) {
                        o[f][j][0] *= al0; o[f][j][1] *= al0;
                        o[f][j][2] *= al1; o[f][j][3] *= al1;
                    }
                    ol[f][0] *= al0; ol[f][1] *= al0;
                    ol[f][2] *= al1; ol[f][3] *= al1;
                }
            }

            // ---- O += P V (shared vf across fragments); l += P·1
            #pragma unroll
            for (int kc = 0; kc < 4; kc++) {
                const int kk = kc * 16;
                uint32_t vf[8][2];
                #pragma unroll
                for (int np = 0; np < 4; np++) {
                    int r = kk + (lane & 7) + ((lane >> 3) & 1) * 8;
                    int dcol = np * 16 + (lane >> 4) * 8;
                    LDSM_X4_T(vf[2 * np][0], vf[2 * np][1], vf[2 * np + 1][0], vf[2 * np + 1][1],
                              bB + 8192 + sw128((uint32_t)(r * 128 + dcol * 2)));
                }
                #pragma unroll
                for (int f = 0; f < 2; f++) {
                    #pragma unroll
                    for (int j = 0; j < 8; j++)
                        MMA_F16(o[f][j], pf[f][kc], vf[j]);
                    MMA_F16(ol[f], pf[f][kc], onesf);
                }
            }
        }

        // ---- epilogue: normalize, write fp16 to [B,S,1024]
        #pragma unroll
        for (int f = 0; f < 2; f++) {
            const float inv0 = 1.0f / ol[f][0], inv1 = 1.0f / ol[f][2];
            const int row0g = qs + w * 32 + f * 16 + (lane >> 2);
            #pragma unroll
            for (int j = 0; j < 8; j++) {
                const int d = j * 8 + (lane & 3) * 2;
                size_t off0 = (size_t)(b * S_ + row0g) * DM_ + h * DK_ + d;
                size_t off1 = off0 + (size_t)8 * DM_;
                *reinterpret_cast<uint32_t*>(g_Ahi[0] + off0) =
                    pack2h(o[f][j][0] * inv0, o[f][j][1] * inv0);
                *reinterpret_cast<uint32_t*>(g_Ahi[0] + off1) =
                    pack2h(o[f][j][2] * inv1, o[f][j][3] * inv1);
            }
        }
    }
}

// ----------------------------------------------------------------------------
extern "C" void kernel_launch(void* const* d_in, const int* in_sizes, int n_in,
                              void* d_out, int out_size)
{
    const float* query = (const float*)d_in[0];
    const float* key   = (const float*)d_in[1];
    const float* value = (const float*)d_in[2];
    const float* Wq = (const float*)d_in[4];
    const float* bq = (const float*)d_in[5];
    const float* Wk = (const float*)d_in[6];
    const float* bk = (const float*)d_in[7];
    const float* Wv = (const float*)d_in[8];
    const float* bv = (const float*)d_in[9];
    const float* Wo = (const float*)d_in[10];
    const float* bo = (const float*)d_in[11];
    float* out = (float*)d_out;

    cudaFuncSetAttribute(gemm_qkv, cudaFuncAttributeMaxDynamicSharedMemorySize, GEMM_SMEM);
    cudaFuncSetAttribute(gemm_out, cudaFuncAttributeMaxDynamicSharedMemorySize, GEMM_SMEM);
    cudaFuncSetAttribute(attn_mma, cudaFuncAttributeMaxDynamicSharedMemorySize, ATT_SMEM);

    const int n4 = M_ * DM_ / 4;

    conv_inputs<<<dim3(n4 / 256, 3), 256>>>((const float4*)query, (const float4*)key,
                                            (const float4*)value);
    conv_weights<<<dim3(32, 32, 4), dim3(32, 8)>>>(Wq, Wk, Wv, Wo);

    gemm_qkv<<<dim3(DM_ / GN, M_ / GM, 3), 128, GEMM_SMEM>>>(bq, bk, bv);
    attn_mma<<<dim3(S_ / 128, B_ * H_), 64, ATT_SMEM>>>();   // 16 x 32 paired CTAs, 2 warps
    gemm_out<<<dim3(DM_ / GN, M_ / GM), 128, GEMM_SMEM>>>(bo, out);
}